// round 3
// baseline (speedup 1.0000x reference)
#include <cuda_runtime.h>
#include <math_constants.h>

// Problem constants (B=2, H=8 -> BH=16; N=16384; D=64; M=266)
#define BH   16
#define NSEQ 16384
#define DDIM 64
#define MDIM 266
#define MP   272      // padded M stride for scratch (16B-aligned rows)
#define MPAD 320      // padded M for context (5 chunks of 64)
#define NT   256      // NSEQ/64 row tiles
#define NSPLIT 16     // deterministic split-K over N for context

__device__ __align__(16) float g_ddk[(size_t)BH * NSEQ * MP];      // dd_k - diag_k
__device__ float g_headmax[BH];
__device__ __align__(16) float g_ctx_part[(size_t)BH * NSPLIT * MPAD * DDIM];
__device__ float g_ksum_part[BH * NSPLIT * MPAD];
__device__ __align__(16) float g_ctx[BH * MPAD * DDIM];
__device__ float g_ksum[BH * MPAD];

__device__ __forceinline__ float dn_const()    { return 0.35355339059327379f; }  // 64^-0.25
__device__ __forceinline__ float ratio_const() { return 0.06131393394849658f; }  // 266^-0.5
#define EPSV 1e-4f

__device__ __forceinline__ void atomicMaxFloat(float* addr, float val) {
    int* ai = (int*)addr;
    int old = *ai;
    while (__int_as_float(old) < val) {
        int prev = atomicCAS(ai, old, __float_as_int(val));
        if (prev == old) return;
        old = prev;
    }
}

__global__ void init_kernel() {
    if (threadIdx.x < BH) g_headmax[threadIdx.x] = -CUDART_INF_F;
}

// ---------------------------------------------------------------------------
// Pass 1: dd_k tile GEMM. Stores (dd - diag) to scratch; per-head max of dd.
// grid = BH * NT blocks of 256 threads. 64x266 output per block, k-dim 64.
// ---------------------------------------------------------------------------
__global__ __launch_bounds__(256) void pass1_k(const float* __restrict__ kin,
                                               const float* __restrict__ proj) {
    __shared__ float sK[64 * 65];
    __shared__ float sP[64 * 65];
    __shared__ float sdiag[64];
    __shared__ float swred[8];
    const int tid = threadIdx.x, tx = tid & 15, ty = tid >> 4;
    const int bh = blockIdx.x >> 8, nt = blockIdx.x & 255;
    const float* kb = kin + ((size_t)(bh * NSEQ + nt * 64)) * DDIM;

    for (int e = tid; e < 4096; e += 256) {
        int n = e >> 6, d = e & 63;
        sK[n * 65 + d] = kb[e] * dn_const();
    }
    __syncthreads();
    if (tid < 64) {
        float s = 0.f;
        #pragma unroll
        for (int d = 0; d < 64; d++) { float vv = sK[tid * 65 + d]; s = fmaf(vv, vv, s); }
        sdiag[tid] = 0.5f * s;   // 0.5 * dn^2 * sum(x^2) via pre-scaled rows
    }

    float tmax = -CUDART_INF_F;
    const size_t rb = ((size_t)(bh * NSEQ + nt * 64)) * MP;

    for (int mc = 0; mc < 5; mc++) {
        const int m0 = mc * 64;
        __syncthreads();
        for (int e = tid; e < 4096; e += 256) {
            int mm = e >> 6, d = e & 63;
            int m = m0 + mm;
            sP[mm * 65 + d] = (m < MDIM) ? proj[m * DDIM + d] : 0.f;
        }
        __syncthreads();

        float acc[4][4] = {};
        #pragma unroll 16
        for (int kk = 0; kk < 64; kk++) {
            float a[4], b[4];
            #pragma unroll
            for (int i = 0; i < 4; i++) a[i] = sK[(ty * 4 + i) * 65 + kk];
            #pragma unroll
            for (int j = 0; j < 4; j++) b[j] = sP[(tx * 4 + j) * 65 + kk];
            #pragma unroll
            for (int i = 0; i < 4; i++)
                #pragma unroll
                for (int j = 0; j < 4; j++)
                    acc[i][j] = fmaf(a[i], b[j], acc[i][j]);
        }

        if (mc < 4) {
            #pragma unroll
            for (int i = 0; i < 4; i++) {
                int row = ty * 4 + i;
                float dg = sdiag[row];
                tmax = fmaxf(tmax, fmaxf(fmaxf(acc[i][0], acc[i][1]),
                                         fmaxf(acc[i][2], acc[i][3])));
                float4 vv = make_float4(acc[i][0] - dg, acc[i][1] - dg,
                                        acc[i][2] - dg, acc[i][3] - dg);
                *reinterpret_cast<float4*>(&g_ddk[rb + (size_t)row * MP + m0 + tx * 4]) = vv;
            }
        } else {
            #pragma unroll
            for (int i = 0; i < 4; i++) {
                int row = ty * 4 + i;
                float dg = sdiag[row];
                #pragma unroll
                for (int j = 0; j < 4; j++) {
                    int m = m0 + tx * 4 + j;
                    if (m < MDIM) {
                        tmax = fmaxf(tmax, acc[i][j]);
                        g_ddk[rb + (size_t)row * MP + m] = acc[i][j] - dg;
                    }
                }
            }
        }
    }

    #pragma unroll
    for (int off = 16; off; off >>= 1)
        tmax = fmaxf(tmax, __shfl_xor_sync(0xffffffffu, tmax, off));
    if ((tid & 31) == 0) swred[tid >> 5] = tmax;
    __syncthreads();
    if (tid == 0) {
        float m = swred[0];
        #pragma unroll
        for (int w = 1; w < 8; w++) m = fmaxf(m, swred[w]);
        atomicMaxFloat(&g_headmax[bh], m);
    }
}

// ---------------------------------------------------------------------------
// Pass 2a: kp = ratio*(exp(scratch - stab)+eps); partial context kp^T v and
// partial ksum over a fixed 1024-row N split. Deterministic (no float atomics).
// grid = BH * 5 * NSPLIT
// ---------------------------------------------------------------------------
__global__ __launch_bounds__(256) void pass2a(const float* __restrict__ vin) {
    __shared__ float sKP[64 * 65];
    __shared__ float sV[64 * 65];
    const int tid = threadIdx.x, tx = tid & 15, ty = tid >> 4;
    const int split = blockIdx.x & 15;
    const int mc = (blockIdx.x >> 4) % 5;
    const int bh = blockIdx.x / 80;
    const float stab = g_headmax[bh];
    const int m0 = mc * 64;

    float acc[4][4] = {};
    float ksl = 0.f;

    for (int t = 0; t < 16; t++) {
        const int nb = split * 1024 + t * 64;
        __syncthreads();
        for (int e = tid; e < 4096; e += 256) {
            int nn = e >> 6, c = e & 63;
            size_t nrow = (size_t)(bh * NSEQ + nb + nn);
            float kp = 0.f;
            int m = m0 + c;
            if (m < MDIM) {
                float x = g_ddk[nrow * MP + m];
                kp = ratio_const() * (__expf(x - stab) + EPSV);
            }
            sKP[nn * 65 + c] = kp;
            sV[nn * 65 + c] = vin[nrow * DDIM + c];
        }
        __syncthreads();
        if (tid < 64) {
            #pragma unroll
            for (int nn = 0; nn < 64; nn++) ksl += sKP[nn * 65 + tid];
        }
        #pragma unroll 8
        for (int nn = 0; nn < 64; nn++) {
            float a[4], b[4];
            #pragma unroll
            for (int i = 0; i < 4; i++) a[i] = sKP[nn * 65 + ty * 4 + i];
            #pragma unroll
            for (int j = 0; j < 4; j++) b[j] = sV[nn * 65 + tx * 4 + j];
            #pragma unroll
            for (int i = 0; i < 4; i++)
                #pragma unroll
                for (int j = 0; j < 4; j++)
                    acc[i][j] = fmaf(a[i], b[j], acc[i][j]);
        }
    }

    const size_t pb = (size_t)(bh * NSPLIT + split) * (MPAD * DDIM);
    #pragma unroll
    for (int i = 0; i < 4; i++) {
        int m = m0 + ty * 4 + i;
        *reinterpret_cast<float4*>(&g_ctx_part[pb + (size_t)m * DDIM + tx * 4]) =
            make_float4(acc[i][0], acc[i][1], acc[i][2], acc[i][3]);
    }
    if (tid < 64)
        g_ksum_part[(bh * NSPLIT + split) * MPAD + m0 + tid] = ksl;
}

// ---------------------------------------------------------------------------
// Pass 2b: reduce split-K partials (fixed order -> deterministic).
// ---------------------------------------------------------------------------
__global__ __launch_bounds__(256) void pass2b() {
    int gid = blockIdx.x * 256 + threadIdx.x;
    if (gid < BH * MPAD * DDIM) {
        int bh = gid / (MPAD * DDIM);
        int rem = gid - bh * (MPAD * DDIM);
        float s = 0.f;
        #pragma unroll
        for (int sp = 0; sp < NSPLIT; sp++)
            s += g_ctx_part[(size_t)(bh * NSPLIT + sp) * (MPAD * DDIM) + rem];
        g_ctx[gid] = s;
    }
    if (gid < BH * MPAD) {
        int bh = gid / MPAD, m = gid - bh * MPAD;
        float s = 0.f;
        #pragma unroll
        for (int sp = 0; sp < NSPLIT; sp++)
            s += g_ksum_part[(bh * NSPLIT + sp) * MPAD + m];
        g_ksum[gid] = s;
    }
}

// ---------------------------------------------------------------------------
// Pass 3: fused q side. dd_q GEMM -> row max -> exp -> qp@context + denom.
// grid = BH * NT, dynamic smem.
// ---------------------------------------------------------------------------
template <int MEND>
__device__ __forceinline__ void gemm2_chunk(const float* sDD, const float* sPC,
                                            int ty, int tx, int m0, float oacc[4][4]) {
    #pragma unroll
    for (int mm = 0; mm < MEND; mm++) {
        float a[4], b[4];
        #pragma unroll
        for (int i = 0; i < 4; i++) a[i] = sDD[(ty * 4 + i) * 273 + m0 + mm];
        #pragma unroll
        for (int j = 0; j < 4; j++) b[j] = sPC[mm * 65 + tx * 4 + j];
        #pragma unroll
        for (int i = 0; i < 4; i++)
            #pragma unroll
            for (int j = 0; j < 4; j++)
                oacc[i][j] = fmaf(a[i], b[j], oacc[i][j]);
    }
}

__global__ __launch_bounds__(256) void pass3_q(const float* __restrict__ qin,
                                               const float* __restrict__ proj,
                                               float* __restrict__ out) {
    extern __shared__ float sm[];
    float* sQ    = sm;            // 64*65 = 4160
    float* sPC   = sm + 4160;     // 64*65 = 4160 (proj chunk, later ctx chunk)
    float* sDD   = sm + 8320;     // 64*273 = 17472
    float* sKs   = sm + 25792;    // 272
    float* sdiag = sm + 26064;    // 64
    float* srmax = sm + 26128;    // 64
    float* sden  = sm + 26192;    // 64    (total 26256 floats = 105024 B)

    const int tid = threadIdx.x, tx = tid & 15, ty = tid >> 4;
    const int bh = blockIdx.x >> 8, nt = blockIdx.x & 255;
    const float* qb = qin + ((size_t)(bh * NSEQ + nt * 64)) * DDIM;

    for (int e = tid; e < 4096; e += 256) {
        int n = e >> 6, d = e & 63;
        sQ[n * 65 + d] = qb[e] * dn_const();
    }
    for (int e = tid; e < MDIM; e += 256) sKs[e] = g_ksum[bh * MPAD + e];
    __syncthreads();
    if (tid < 64) {
        float s = 0.f;
        #pragma unroll
        for (int d = 0; d < 64; d++) { float vv = sQ[tid * 65 + d]; s = fmaf(vv, vv, s); }
        sdiag[tid] = 0.5f * s;
    }

    float rmax[4] = {-CUDART_INF_F, -CUDART_INF_F, -CUDART_INF_F, -CUDART_INF_F};

    for (int mc = 0; mc < 5; mc++) {
        const int m0 = mc * 64;
        __syncthreads();
        for (int e = tid; e < 4096; e += 256) {
            int mm = e >> 6, d = e & 63;
            int m = m0 + mm;
            sPC[mm * 65 + d] = (m < MDIM) ? proj[m * DDIM + d] : 0.f;
        }
        __syncthreads();

        float acc[4][4] = {};
        #pragma unroll 16
        for (int kk = 0; kk < 64; kk++) {
            float a[4], b[4];
            #pragma unroll
            for (int i = 0; i < 4; i++) a[i] = sQ[(ty * 4 + i) * 65 + kk];
            #pragma unroll
            for (int j = 0; j < 4; j++) b[j] = sPC[(tx * 4 + j) * 65 + kk];
            #pragma unroll
            for (int i = 0; i < 4; i++)
                #pragma unroll
                for (int j = 0; j < 4; j++)
                    acc[i][j] = fmaf(a[i], b[j], acc[i][j]);
        }
        #pragma unroll
        for (int i = 0; i < 4; i++) {
            float mv = -CUDART_INF_F;
            #pragma unroll
            for (int j = 0; j < 4; j++) {
                int m = m0 + tx * 4 + j;
                if (m < MDIM) {
                    sDD[(ty * 4 + i) * 273 + m] = acc[i][j];
                    mv = fmaxf(mv, acc[i][j]);
                }
            }
            #pragma unroll
            for (int off = 8; off; off >>= 1)
                mv = fmaxf(mv, __shfl_xor_sync(0xffffffffu, mv, off));
            rmax[i] = fmaxf(rmax[i], mv);
        }
    }
    if (tx == 0) {
        #pragma unroll
        for (int i = 0; i < 4; i++) srmax[ty * 4 + i] = rmax[i];
    }
    __syncthreads();

    // exp transform in place: qp = ratio*(exp(dd - diag - rowmax) + eps)
    for (int e = tid; e < 64 * 273; e += 256) {
        int n = e / 273, m = e - n * 273;
        float vv = 0.f;
        if (m < MDIM)
            vv = ratio_const() * (__expf(sDD[e] - sdiag[n] - srmax[n]) + EPSV);
        sDD[e] = vv;
    }
    __syncthreads();

    if (tid < 64) {
        float den = 0.f;
        for (int m = 0; m < MDIM; m++) den = fmaf(sDD[tid * 273 + m], sKs[m], den);
        sden[tid] = 1.f / den;
    }

    float oacc[4][4] = {};
    for (int mc = 0; mc < 5; mc++) {
        const int m0 = mc * 64;
        __syncthreads();
        for (int e = tid; e < 4096; e += 256) {
            int mm = e >> 6, d = e & 63;
            sPC[mm * 65 + d] = g_ctx[(size_t)(bh * MPAD + m0 + mm) * DDIM + d];
        }
        __syncthreads();
        if (mc < 4) gemm2_chunk<64>(sDD, sPC, ty, tx, m0, oacc);
        else        gemm2_chunk<10>(sDD, sPC, ty, tx, m0, oacc);
    }
    __syncthreads();

    float* ob = out + ((size_t)(bh * NSEQ + nt * 64)) * DDIM;
    #pragma unroll
    for (int i = 0; i < 4; i++) {
        int row = ty * 4 + i;
        float di = sden[row];
        *reinterpret_cast<float4*>(&ob[(size_t)row * DDIM + tx * 4]) =
            make_float4(oacc[i][0] * di, oacc[i][1] * di, oacc[i][2] * di, oacc[i][3] * di);
    }
}

// ---------------------------------------------------------------------------
extern "C" void kernel_launch(void* const* d_in, const int* in_sizes, int n_in,
                              void* d_out, int out_size) {
    const float* q    = (const float*)d_in[0];
    const float* k    = (const float*)d_in[1];
    const float* v    = (const float*)d_in[2];
    const float* proj = (const float*)d_in[3];
    float* out = (float*)d_out;

    cudaFuncSetAttribute(pass3_q, cudaFuncAttributeMaxDynamicSharedMemorySize, 26256 * 4);

    init_kernel<<<1, 32>>>();
    pass1_k<<<BH * NT, 256>>>(k, proj);
    pass2a<<<BH * 5 * NSPLIT, 256>>>(v);
    pass2b<<<(BH * MPAD * DDIM + 255) / 256, 256>>>();
    pass3_q<<<BH * NT, 256, 26256 * 4>>>(q, proj, out);
}

// round 4
// speedup vs baseline: 1.0052x; 1.0052x over previous
#include <cuda_runtime.h>
#include <math_constants.h>

// Problem constants (B=2, H=8 -> BH=16; N=16384; D=64; M=266)
#define BH   16
#define NSEQ 16384
#define DDIM 64
#define MDIM 266
#define MP   272      // padded M stride for scratch (16B-aligned rows)
#define MPAD 320      // padded M for context (5 chunks of 64)
#define NT   256      // NSEQ/64 row tiles
#define NSPLIT 16     // deterministic split-K over N for context

__device__ __align__(16) float g_ddk[(size_t)BH * NSEQ * MP];      // dd_k - diag_k
__device__ float g_headmax[BH];
__device__ __align__(16) float g_ctx_part[(size_t)BH * NSPLIT * MPAD * DDIM];
__device__ float g_ksum_part[BH * NSPLIT * MPAD];
__device__ __align__(16) float g_ctx[BH * MPAD * DDIM];
__device__ float g_ksum[BH * MPAD];

__device__ __forceinline__ float dn_const()    { return 0.35355339059327379f; }  // 64^-0.25
__device__ __forceinline__ float ratio_const() { return 0.06131393394849658f; }  // 266^-0.5
#define EPSV 1e-4f

__device__ __forceinline__ void atomicMaxFloat(float* addr, float val) {
    int* ai = (int*)addr;
    int old = *ai;
    while (__int_as_float(old) < val) {
        int prev = atomicCAS(ai, old, __float_as_int(val));
        if (prev == old) return;
        old = prev;
    }
}

__global__ void init_kernel() {
    if (threadIdx.x < BH) g_headmax[threadIdx.x] = -CUDART_INF_F;
}

// ---------------------------------------------------------------------------
// Pass 1: dd_k tile GEMM. Stores (dd - diag) to scratch; per-head max of dd.
// grid = BH * NT blocks of 256 threads. 64x266 output per block, k-dim 64.
// ---------------------------------------------------------------------------
__global__ __launch_bounds__(256) void pass1_k(const float* __restrict__ kin,
                                               const float* __restrict__ proj) {
    __shared__ float sK[64 * 65];
    __shared__ float sP[64 * 65];
    __shared__ float sdiag[64];
    __shared__ float swred[8];
    const int tid = threadIdx.x, tx = tid & 15, ty = tid >> 4;
    const int bh = blockIdx.x >> 8, nt = blockIdx.x & 255;
    const float* kb = kin + ((size_t)(bh * NSEQ + nt * 64)) * DDIM;

    for (int e = tid; e < 4096; e += 256) {
        int n = e >> 6, d = e & 63;
        sK[n * 65 + d] = kb[e] * dn_const();
    }
    __syncthreads();
    if (tid < 64) {
        float s = 0.f;
        #pragma unroll
        for (int d = 0; d < 64; d++) { float vv = sK[tid * 65 + d]; s = fmaf(vv, vv, s); }
        sdiag[tid] = 0.5f * s;   // 0.5 * dn^2 * sum(x^2) via pre-scaled rows
    }

    float tmax = -CUDART_INF_F;
    const size_t rb = ((size_t)(bh * NSEQ + nt * 64)) * MP;

    for (int mc = 0; mc < 5; mc++) {
        const int m0 = mc * 64;
        __syncthreads();
        for (int e = tid; e < 4096; e += 256) {
            int mm = e >> 6, d = e & 63;
            int m = m0 + mm;
            sP[mm * 65 + d] = (m < MDIM) ? proj[m * DDIM + d] : 0.f;
        }
        __syncthreads();

        float acc[4][4] = {};
        #pragma unroll 16
        for (int kk = 0; kk < 64; kk++) {
            float a[4], b[4];
            #pragma unroll
            for (int i = 0; i < 4; i++) a[i] = sK[(ty * 4 + i) * 65 + kk];
            #pragma unroll
            for (int j = 0; j < 4; j++) b[j] = sP[(tx * 4 + j) * 65 + kk];
            #pragma unroll
            for (int i = 0; i < 4; i++)
                #pragma unroll
                for (int j = 0; j < 4; j++)
                    acc[i][j] = fmaf(a[i], b[j], acc[i][j]);
        }

        if (mc < 4) {
            #pragma unroll
            for (int i = 0; i < 4; i++) {
                int row = ty * 4 + i;
                float dg = sdiag[row];
                tmax = fmaxf(tmax, fmaxf(fmaxf(acc[i][0], acc[i][1]),
                                         fmaxf(acc[i][2], acc[i][3])));
                float4 vv = make_float4(acc[i][0] - dg, acc[i][1] - dg,
                                        acc[i][2] - dg, acc[i][3] - dg);
                *reinterpret_cast<float4*>(&g_ddk[rb + (size_t)row * MP + m0 + tx * 4]) = vv;
            }
        } else {
            #pragma unroll
            for (int i = 0; i < 4; i++) {
                int row = ty * 4 + i;
                float dg = sdiag[row];
                #pragma unroll
                for (int j = 0; j < 4; j++) {
                    int m = m0 + tx * 4 + j;
                    if (m < MDIM) {
                        tmax = fmaxf(tmax, acc[i][j]);
                        g_ddk[rb + (size_t)row * MP + m] = acc[i][j] - dg;
                    }
                }
            }
        }
    }

    #pragma unroll
    for (int off = 16; off; off >>= 1)
        tmax = fmaxf(tmax, __shfl_xor_sync(0xffffffffu, tmax, off));
    if ((tid & 31) == 0) swred[tid >> 5] = tmax;
    __syncthreads();
    if (tid == 0) {
        float m = swred[0];
        #pragma unroll
        for (int w = 1; w < 8; w++) m = fmaxf(m, swred[w]);
        atomicMaxFloat(&g_headmax[bh], m);
    }
}

// ---------------------------------------------------------------------------
// Pass 2a: kp = ratio*(exp(scratch - stab)+eps); partial context kp^T v and
// partial ksum over a fixed 1024-row N split. Deterministic (no float atomics).
// grid = BH * 5 * NSPLIT
// ---------------------------------------------------------------------------
__global__ __launch_bounds__(256) void pass2a(const float* __restrict__ vin) {
    __shared__ float sKP[64 * 65];
    __shared__ float sV[64 * 65];
    const int tid = threadIdx.x, tx = tid & 15, ty = tid >> 4;
    const int split = blockIdx.x & 15;
    const int mc = (blockIdx.x >> 4) % 5;
    const int bh = blockIdx.x / 80;
    const float stab = g_headmax[bh];
    const int m0 = mc * 64;

    float acc[4][4] = {};
    float ksl = 0.f;

    for (int t = 0; t < 16; t++) {
        const int nb = split * 1024 + t * 64;
        __syncthreads();
        for (int e = tid; e < 4096; e += 256) {
            int nn = e >> 6, c = e & 63;
            size_t nrow = (size_t)(bh * NSEQ + nb + nn);
            float kp = 0.f;
            int m = m0 + c;
            if (m < MDIM) {
                float x = g_ddk[nrow * MP + m];
                kp = ratio_const() * (__expf(x - stab) + EPSV);
            }
            sKP[nn * 65 + c] = kp;
            sV[nn * 65 + c] = vin[nrow * DDIM + c];
        }
        __syncthreads();
        if (tid < 64) {
            #pragma unroll
            for (int nn = 0; nn < 64; nn++) ksl += sKP[nn * 65 + tid];
        }
        #pragma unroll 8
        for (int nn = 0; nn < 64; nn++) {
            float a[4], b[4];
            #pragma unroll
            for (int i = 0; i < 4; i++) a[i] = sKP[nn * 65 + ty * 4 + i];
            #pragma unroll
            for (int j = 0; j < 4; j++) b[j] = sV[nn * 65 + tx * 4 + j];
            #pragma unroll
            for (int i = 0; i < 4; i++)
                #pragma unroll
                for (int j = 0; j < 4; j++)
                    acc[i][j] = fmaf(a[i], b[j], acc[i][j]);
        }
    }

    const size_t pb = (size_t)(bh * NSPLIT + split) * (MPAD * DDIM);
    #pragma unroll
    for (int i = 0; i < 4; i++) {
        int m = m0 + ty * 4 + i;
        *reinterpret_cast<float4*>(&g_ctx_part[pb + (size_t)m * DDIM + tx * 4]) =
            make_float4(acc[i][0], acc[i][1], acc[i][2], acc[i][3]);
    }
    if (tid < 64)
        g_ksum_part[(bh * NSPLIT + split) * MPAD + m0 + tid] = ksl;
}

// ---------------------------------------------------------------------------
// Pass 2b: reduce split-K partials (fixed order -> deterministic).
// ---------------------------------------------------------------------------
__global__ __launch_bounds__(256) void pass2b() {
    int gid = blockIdx.x * 256 + threadIdx.x;
    if (gid < BH * MPAD * DDIM) {
        int bh = gid / (MPAD * DDIM);
        int rem = gid - bh * (MPAD * DDIM);
        float s = 0.f;
        #pragma unroll
        for (int sp = 0; sp < NSPLIT; sp++)
            s += g_ctx_part[(size_t)(bh * NSPLIT + sp) * (MPAD * DDIM) + rem];
        g_ctx[gid] = s;
    }
    if (gid < BH * MPAD) {
        int bh = gid / MPAD, m = gid - bh * MPAD;
        float s = 0.f;
        #pragma unroll
        for (int sp = 0; sp < NSPLIT; sp++)
            s += g_ksum_part[(bh * NSPLIT + sp) * MPAD + m];
        g_ksum[gid] = s;
    }
}

// ---------------------------------------------------------------------------
// Pass 3: fused q side. dd_q GEMM -> row max -> exp -> qp@context + denom.
// grid = BH * NT, dynamic smem.
// ---------------------------------------------------------------------------
template <int MEND>
__device__ __forceinline__ void gemm2_chunk(const float* sDD, const float* sPC,
                                            int ty, int tx, int m0, float oacc[4][4]) {
    #pragma unroll
    for (int mm = 0; mm < MEND; mm++) {
        float a[4], b[4];
        #pragma unroll
        for (int i = 0; i < 4; i++) a[i] = sDD[(ty * 4 + i) * 273 + m0 + mm];
        #pragma unroll
        for (int j = 0; j < 4; j++) b[j] = sPC[mm * 65 + tx * 4 + j];
        #pragma unroll
        for (int i = 0; i < 4; i++)
            #pragma unroll
            for (int j = 0; j < 4; j++)
                oacc[i][j] = fmaf(a[i], b[j], oacc[i][j]);
    }
}

__global__ __launch_bounds__(256) void pass3_q(const float* __restrict__ qin,
                                               const float* __restrict__ proj,
                                               float* __restrict__ out) {
    extern __shared__ float sm[];
    float* sQ    = sm;            // 64*65 = 4160
    float* sPC   = sm + 4160;     // 64*65 = 4160 (proj chunk, later ctx chunk)
    float* sDD   = sm + 8320;     // 64*273 = 17472
    float* sKs   = sm + 25792;    // 272
    float* sdiag = sm + 26064;    // 64
    float* srmax = sm + 26128;    // 64
    float* sden  = sm + 26192;    // 64    (total 26256 floats = 105024 B)

    const int tid = threadIdx.x, tx = tid & 15, ty = tid >> 4;
    const int bh = blockIdx.x >> 8, nt = blockIdx.x & 255;
    const float* qb = qin + ((size_t)(bh * NSEQ + nt * 64)) * DDIM;

    for (int e = tid; e < 4096; e += 256) {
        int n = e >> 6, d = e & 63;
        sQ[n * 65 + d] = qb[e] * dn_const();
    }
    for (int e = tid; e < MDIM; e += 256) sKs[e] = g_ksum[bh * MPAD + e];
    __syncthreads();
    if (tid < 64) {
        float s = 0.f;
        #pragma unroll
        for (int d = 0; d < 64; d++) { float vv = sQ[tid * 65 + d]; s = fmaf(vv, vv, s); }
        sdiag[tid] = 0.5f * s;
    }

    float rmax[4] = {-CUDART_INF_F, -CUDART_INF_F, -CUDART_INF_F, -CUDART_INF_F};

    for (int mc = 0; mc < 5; mc++) {
        const int m0 = mc * 64;
        __syncthreads();
        for (int e = tid; e < 4096; e += 256) {
            int mm = e >> 6, d = e & 63;
            int m = m0 + mm;
            sPC[mm * 65 + d] = (m < MDIM) ? proj[m * DDIM + d] : 0.f;
        }
        __syncthreads();

        float acc[4][4] = {};
        #pragma unroll 16
        for (int kk = 0; kk < 64; kk++) {
            float a[4], b[4];
            #pragma unroll
            for (int i = 0; i < 4; i++) a[i] = sQ[(ty * 4 + i) * 65 + kk];
            #pragma unroll
            for (int j = 0; j < 4; j++) b[j] = sPC[(tx * 4 + j) * 65 + kk];
            #pragma unroll
            for (int i = 0; i < 4; i++)
                #pragma unroll
                for (int j = 0; j < 4; j++)
                    acc[i][j] = fmaf(a[i], b[j], acc[i][j]);
        }
        #pragma unroll
        for (int i = 0; i < 4; i++) {
            float mv = -CUDART_INF_F;
            #pragma unroll
            for (int j = 0; j < 4; j++) {
                int m = m0 + tx * 4 + j;
                if (m < MDIM) {
                    sDD[(ty * 4 + i) * 273 + m] = acc[i][j];
                    mv = fmaxf(mv, acc[i][j]);
                }
            }
            #pragma unroll
            for (int off = 8; off; off >>= 1)
                mv = fmaxf(mv, __shfl_xor_sync(0xffffffffu, mv, off));
            rmax[i] = fmaxf(rmax[i], mv);
        }
    }
    if (tx == 0) {
        #pragma unroll
        for (int i = 0; i < 4; i++) srmax[ty * 4 + i] = rmax[i];
    }
    __syncthreads();

    // exp transform in place: qp = ratio*(exp(dd - diag - rowmax) + eps)
    for (int e = tid; e < 64 * 273; e += 256) {
        int n = e / 273, m = e - n * 273;
        float vv = 0.f;
        if (m < MDIM)
            vv = ratio_const() * (__expf(sDD[e] - sdiag[n] - srmax[n]) + EPSV);
        sDD[e] = vv;
    }
    __syncthreads();

    if (tid < 64) {
        float den = 0.f;
        for (int m = 0; m < MDIM; m++) den = fmaf(sDD[tid * 273 + m], sKs[m], den);
        sden[tid] = 1.f / den;
    }

    float oacc[4][4] = {};
    for (int mc = 0; mc < 5; mc++) {
        const int m0 = mc * 64;
        __syncthreads();
        for (int e = tid; e < 4096; e += 256) {
            int mm = e >> 6, d = e & 63;
            sPC[mm * 65 + d] = g_ctx[(size_t)(bh * MPAD + m0 + mm) * DDIM + d];
        }
        __syncthreads();
        if (mc < 4) gemm2_chunk<64>(sDD, sPC, ty, tx, m0, oacc);
        else        gemm2_chunk<10>(sDD, sPC, ty, tx, m0, oacc);
    }
    __syncthreads();

    float* ob = out + ((size_t)(bh * NSEQ + nt * 64)) * DDIM;
    #pragma unroll
    for (int i = 0; i < 4; i++) {
        int row = ty * 4 + i;
        float di = sden[row];
        *reinterpret_cast<float4*>(&ob[(size_t)row * DDIM + tx * 4]) =
            make_float4(oacc[i][0] * di, oacc[i][1] * di, oacc[i][2] * di, oacc[i][3] * di);
    }
}

// ---------------------------------------------------------------------------
extern "C" void kernel_launch(void* const* d_in, const int* in_sizes, int n_in,
                              void* d_out, int out_size) {
    const float* q    = (const float*)d_in[0];
    const float* k    = (const float*)d_in[1];
    const float* v    = (const float*)d_in[2];
    const float* proj = (const float*)d_in[3];
    float* out = (float*)d_out;

    cudaFuncSetAttribute(pass3_q, cudaFuncAttributeMaxDynamicSharedMemorySize, 26256 * 4);

    init_kernel<<<1, 32>>>();
    pass1_k<<<BH * NT, 256>>>(k, proj);
    pass2a<<<BH * 5 * NSPLIT, 256>>>(v);
    pass2b<<<(BH * MPAD * DDIM + 255) / 256, 256>>>();
    pass3_q<<<BH * NT, 256, 26256 * 4>>>(q, proj, out);
}

// round 6
// speedup vs baseline: 1.4165x; 1.4092x over previous
#include <cuda_runtime.h>
#include <cuda_bf16.h>
#include <math_constants.h>
#include <cstdint>

// B=2,H=8 -> BHN=16; N=16384; D=64; M=266 (pad 288)
#define BHN  16
#define NSEQ 16384
#define MDIM 266
#define MP   272
#define DN    0.35355339059327379f
#define RATIO 0.06131393394849658f
#define EPSV  1e-4f

__device__ float g_headmax[BHN];
__device__ __align__(16) float g_ddk[(size_t)BHN * NSEQ * MP];
__device__ __align__(16) float g_ctx_part[(size_t)BHN * 16 * 320 * 80];
__device__ __align__(16) unsigned short g_projB0[288 * 72];
__device__ __align__(16) unsigned short g_projB1[288 * 72];
__device__ __align__(16) unsigned short g_ctxB0[BHN * 80 * 288];
__device__ __align__(16) unsigned short g_ctxB1[BHN * 80 * 288];

// ---- smem byte offsets ----
// pass1/pass3 stage 1
#define XH 0u
#define XL 9216u
#define PH 18432u
#define PL 59904u
// pass1 tail
#define P_DIAG 101376u
#define P_SWM  101632u
#define SMEM1  101664u
// pass3 stage 2 (overlaps stage 1; valid after syncthreads)
#define QPH 0u
#define QPL 37888u
#define CTH 75776u
#define CTL 123136u
#define Q_DIAG 170496u
#define Q_SRM  170752u
#define SMEM3  171264u
// pass2a (static smem)
#define KH 0u
#define KL 9216u
#define VH 18432u
#define VL 29952u

__device__ __forceinline__ uint32_t smem_u32(const void* p) {
    uint32_t a;
    asm("{ .reg .u64 t; cvta.to.shared.u64 t, %1; cvt.u32.u64 %0, t; }" : "=r"(a) : "l"(p));
    return a;
}
__device__ __forceinline__ void ldm4(uint32_t f[4], uint32_t a) {
    asm volatile("ldmatrix.sync.aligned.m8n8.x4.shared.b16 {%0,%1,%2,%3}, [%4];"
        : "=r"(f[0]), "=r"(f[1]), "=r"(f[2]), "=r"(f[3]) : "r"(a));
}
__device__ __forceinline__ void mma16816(float c[4], const uint32_t a[4],
                                         uint32_t b0, uint32_t b1) {
    asm volatile("mma.sync.aligned.m16n8k16.row.col.f32.bf16.bf16.f32 "
        "{%0,%1,%2,%3},{%4,%5,%6,%7},{%8,%9},{%0,%1,%2,%3};"
        : "+f"(c[0]), "+f"(c[1]), "+f"(c[2]), "+f"(c[3])
        : "r"(a[0]), "r"(a[1]), "r"(a[2]), "r"(a[3]), "r"(b0), "r"(b1));
}

// hi/lo 3-product warp GEMM. C stripe: 16 rows x (2*NTP*8) cols.
// A: [16 rows][K] bf16 at aH/aL (byte base incl. row offset), row stride ldaB bytes.
// B: [cols][K] bf16 at bH/bL (byte base incl. col offset), row stride ldbB bytes.
template <int NTP, int KS>
__device__ __forceinline__ void wgemm(float C[][4], uint32_t aH, uint32_t aL, int ldaB,
                                      uint32_t bH, uint32_t bL, int ldbB, int lane) {
    const uint32_t ao = (uint32_t)(lane & 15) * ldaB + (uint32_t)(lane >> 4) * 16;
    const uint32_t bo = (uint32_t)(lane & 15) * ldbB + (uint32_t)(lane >> 4) * 16;
    for (int ks = 0; ks < KS; ks++) {
        uint32_t ah[4], al[4];
        ldm4(ah, aH + ao + ks * 32);
        ldm4(al, aL + ao + ks * 32);
        #pragma unroll
        for (int tp = 0; tp < NTP; tp++) {
            uint32_t bh[4], bl[4];
            ldm4(bh, bH + bo + tp * 16 * ldbB + ks * 32);
            ldm4(bl, bL + bo + tp * 16 * ldbB + ks * 32);
            mma16816(C[2 * tp], ah, bh[0], bh[2]);
            mma16816(C[2 * tp], ah, bl[0], bl[2]);
            mma16816(C[2 * tp], al, bh[0], bh[2]);
            mma16816(C[2 * tp + 1], ah, bh[1], bh[3]);
            mma16816(C[2 * tp + 1], ah, bl[1], bl[3]);
            mma16816(C[2 * tp + 1], al, bh[1], bh[3]);
        }
    }
}

__device__ __forceinline__ void bsplit(float x, uint16_t& h, uint16_t& l) {
    __nv_bfloat16 hb = __float2bfloat16(x);
    __nv_bfloat16 lb = __float2bfloat16(x - __bfloat162float(hb));
    h = __bfloat16_as_ushort(hb);
    l = __bfloat16_as_ushort(lb);
}
__device__ __forceinline__ void atomicMaxFloat(float* addr, float val) {
    int* ai = (int*)addr;
    int old = *ai;
    while (__int_as_float(old) < val) {
        int prev = atomicCAS(ai, old, __float_as_int(val));
        if (prev == old) return;
        old = prev;
    }
}

// stage 64x64 fp32 rows -> scaled bf16 hi/lo [64][72-stride] + diag
__device__ __forceinline__ void stage_x(const float* __restrict__ src, uint8_t* sm,
                                        uint32_t offH, uint32_t offL, float* diag, int tid) {
    const int r = tid >> 2, c0 = (tid & 3) * 16;
    const float4* p = (const float4*)(src + (size_t)r * 64 + c0);
    uint32_t h[8], l[8];
    float sq = 0.f;
    #pragma unroll
    for (int j = 0; j < 4; j++) {
        float4 t = p[j];
        float v[4] = {t.x * DN, t.y * DN, t.z * DN, t.w * DN};
        #pragma unroll
        for (int e = 0; e < 4; e += 2) {
            uint16_t h0, l0, h1, l1;
            bsplit(v[e], h0, l0);
            bsplit(v[e + 1], h1, l1);
            h[j * 2 + e / 2] = (uint32_t)h0 | ((uint32_t)h1 << 16);
            l[j * 2 + e / 2] = (uint32_t)l0 | ((uint32_t)l1 << 16);
        }
        sq = fmaf(v[0], v[0], fmaf(v[1], v[1], fmaf(v[2], v[2], fmaf(v[3], v[3], sq))));
    }
    uint32_t ba = (uint32_t)r * 144 + (uint32_t)c0 * 2;
    *(uint4*)(sm + offH + ba)      = make_uint4(h[0], h[1], h[2], h[3]);
    *(uint4*)(sm + offH + ba + 16) = make_uint4(h[4], h[5], h[6], h[7]);
    *(uint4*)(sm + offL + ba)      = make_uint4(l[0], l[1], l[2], l[3]);
    *(uint4*)(sm + offL + ba + 16) = make_uint4(l[4], l[5], l[6], l[7]);
    sq += __shfl_xor_sync(~0u, sq, 1);
    sq += __shfl_xor_sync(~0u, sq, 2);
    if ((tid & 3) == 0) diag[r] = 0.5f * sq;
}
__device__ __forceinline__ void copy_proj(uint8_t* sm, int tid) {
    for (int i = tid; i < 2592; i += 256) {
        ((uint4*)(sm + PH))[i] = ((const uint4*)g_projB0)[i];
        ((uint4*)(sm + PL))[i] = ((const uint4*)g_projB1)[i];
    }
}

__global__ void prep(const float* __restrict__ proj) {
    int gid = blockIdx.x * 256 + threadIdx.x;   // 288*256 = 73728 = 288*64*4
    int r = gid >> 6, c = gid & 63;
    float v = (r < MDIM) ? proj[r * 64 + c] : 0.f;
    uint16_t h, l;
    bsplit(v, h, l);
    g_projB0[r * 72 + c] = h;
    g_projB1[r * 72 + c] = l;
    if (gid < BHN) g_headmax[gid] = -CUDART_INF_F;
}

// ---------------------------------------------------------------------------
// pass1: dd_k = (k*dn)@P^T via HMMA; store dd-diag; head max. grid = 16*256.
// ---------------------------------------------------------------------------
__global__ __launch_bounds__(256) void pass1(const float* __restrict__ kin) {
    extern __shared__ __align__(16) uint8_t sm[];
    uint32_t sb = smem_u32(sm);
    float* diag = (float*)(sm + P_DIAG);
    float* swm = (float*)(sm + P_SWM);
    const int tid = threadIdx.x, w = tid >> 5, lane = tid & 31;
    const int bh = blockIdx.x >> 8, nt = blockIdx.x & 255;
    const int row0 = (w >> 1) * 16, col0 = (w & 1) * 144;

    copy_proj(sm, tid);
    stage_x(kin + (size_t)(bh * NSEQ + nt * 64) * 64, sm, XH, XL, diag, tid);
    __syncthreads();

    float C[18][4] = {};
    wgemm<9, 4>(C, sb + XH + row0 * 144, sb + XL + row0 * 144, 144,
                sb + PH + col0 * 144, sb + PL + col0 * 144, 144, lane);

    const int r1 = row0 + (lane >> 2), r2 = r1 + 8;
    const float d1 = diag[r1], d2 = diag[r2];
    const size_t rb = (size_t)(bh * NSEQ + nt * 64) * MP;
    float tmax = -CUDART_INF_F;
    #pragma unroll
    for (int t = 0; t < 18; t++) {
        int col = col0 + t * 8 + (lane & 3) * 2;
        if (col < MDIM) {
            tmax = fmaxf(tmax, fmaxf(fmaxf(C[t][0], C[t][1]), fmaxf(C[t][2], C[t][3])));
            *(float2*)&g_ddk[rb + (size_t)r1 * MP + col] = make_float2(C[t][0] - d1, C[t][1] - d1);
            *(float2*)&g_ddk[rb + (size_t)r2 * MP + col] = make_float2(C[t][2] - d2, C[t][3] - d2);
        }
    }
    #pragma unroll
    for (int o = 16; o; o >>= 1) tmax = fmaxf(tmax, __shfl_xor_sync(~0u, tmax, o));
    if (lane == 0) swm[w] = tmax;
    __syncthreads();
    if (tid == 0) {
        float m = swm[0];
        #pragma unroll
        for (int i = 1; i < 8; i++) m = fmaxf(m, swm[i]);
        atomicMaxFloat(&g_headmax[bh], m);
    }
}

// ---------------------------------------------------------------------------
// pass2a: kp from scratch; context kp^T v (+ ksum via ones row) via HMMA.
// grid = 16 heads * 5 mc * 16 splits. C accumulates over 16 n-chunks.
// ---------------------------------------------------------------------------
__global__ __launch_bounds__(256) void pass2a(const float* __restrict__ vin) {
    __shared__ __align__(16) uint8_t sm[41472];
    uint32_t sb = smem_u32(sm);
    const int tid = threadIdx.x, w = tid >> 5, lane = tid & 31;
    const int split = blockIdx.x & 15, mc = (blockIdx.x >> 4) % 5, bh = blockIdx.x / 80;
    const float stab = g_headmax[bh];
    const int m0 = mc * 64;
    const int row0 = (w >> 1) * 16, cw = w & 1, c2o = cw * 48;
    const size_t bhn0 = (size_t)bh * NSEQ;

    // vT rows 64..79: row 64 = ones (ksum), rest zero
    for (int i = tid; i < 1024; i += 256) {
        int rr = 64 + (i >> 6), c = i & 63;
        *(uint16_t*)(sm + VH + rr * 144 + c * 2) = (rr == 64) ? (uint16_t)0x3F80 : (uint16_t)0;
        *(uint16_t*)(sm + VL + rr * 144 + c * 2) = 0;
    }

    float C[6][4] = {};
    for (int t = 0; t < 16; t++) {
        const size_t n0 = bhn0 + (size_t)split * 1024 + t * 64;
        __syncthreads();
        for (int e = tid; e < 4096; e += 256) {
            int mm = e & 63, nn = e >> 6;
            int m = m0 + mm;
            float kp = 0.f;
            if (m < MDIM) {
                float x = g_ddk[(n0 + nn) * MP + m];
                kp = RATIO * (__expf(x - stab) + EPSV);
            }
            uint16_t h, l;
            bsplit(kp, h, l);
            *(uint16_t*)(sm + KH + mm * 144 + nn * 2) = h;
            *(uint16_t*)(sm + KL + mm * 144 + nn * 2) = l;
        }
        for (int e = tid; e < 4096; e += 256) {
            int dd = e & 63, nn = e >> 6;
            float x = vin[(n0 + nn) * 64 + dd];
            uint16_t h, l;
            bsplit(x, h, l);
            *(uint16_t*)(sm + VH + dd * 144 + nn * 2) = h;
            *(uint16_t*)(sm + VL + dd * 144 + nn * 2) = l;
        }
        __syncthreads();
        if (cw == 0)
            wgemm<3, 4>(C, sb + KH + row0 * 144, sb + KL + row0 * 144, 144,
                        sb + VH, sb + VL, 144, lane);
        else
            wgemm<2, 4>(C, sb + KH + row0 * 144, sb + KL + row0 * 144, 144,
                        sb + VH + 48 * 144, sb + VL + 48 * 144, 144, lane);
    }
    const int r1 = row0 + (lane >> 2), r2 = r1 + 8;
    float* pb = g_ctx_part + ((size_t)(bh * 16 + split) * 320 + m0) * 80;
    const int nst = cw ? 4 : 6;
    for (int t = 0; t < nst; t++) {
        int col = c2o + t * 8 + (lane & 3) * 2;
        *(float2*)(pb + (size_t)r1 * 80 + col) = make_float2(C[t][0], C[t][1]);
        *(float2*)(pb + (size_t)r2 * 80 + col) = make_float2(C[t][2], C[t][3]);
    }
}

// ---------------------------------------------------------------------------
// pass2b: reduce splits (fixed order); emit bf16 hi/lo ctx^T [bh][80][288].
// Row d=64 is ksum; d=65..79 and m>=266 are zeros.
// ---------------------------------------------------------------------------
__global__ __launch_bounds__(256) void pass2b() {
    int gid = blockIdx.x * 256 + threadIdx.x;
    if (gid >= BHN * 288 * 80) return;
    int bh = gid / (288 * 80);
    int rem = gid % (288 * 80);
    int m = rem / 80, d = rem % 80;
    float s = 0.f;
    #pragma unroll
    for (int sp = 0; sp < 16; sp++)
        s += g_ctx_part[((size_t)(bh * 16 + sp) * 320 + m) * 80 + d];
    uint16_t h, l;
    bsplit(s, h, l);
    g_ctxB0[(size_t)bh * 23040 + d * 288 + m] = h;
    g_ctxB1[(size_t)bh * 23040 + d * 288 + m] = l;
}

// ---------------------------------------------------------------------------
// pass3: fused q side. GEMM1 -> rowmax -> exp -> GEMM2 (denom = col 64).
// grid = 16*256.
// ---------------------------------------------------------------------------
__global__ __launch_bounds__(256) void pass3(const float* __restrict__ qin,
                                             float* __restrict__ out) {
    extern __shared__ __align__(16) uint8_t sm[];
    uint32_t sb = smem_u32(sm);
    float* diag = (float*)(sm + Q_DIAG);
    float* srm = (float*)(sm + Q_SRM);    // [2][64] rowmax halves; reused as sden[64]
    const int tid = threadIdx.x, w = tid >> 5, lane = tid & 31;
    const int bh = blockIdx.x >> 8, nt = blockIdx.x & 255;
    const int row0 = (w >> 1) * 16, cw = w & 1, col0 = cw * 144;

    copy_proj(sm, tid);
    stage_x(qin + (size_t)(bh * NSEQ + nt * 64) * 64, sm, XH, XL, diag, tid);
    __syncthreads();

    float C[18][4] = {};
    wgemm<9, 4>(C, sb + XH + row0 * 144, sb + XL + row0 * 144, 144,
                sb + PH + col0 * 144, sb + PL + col0 * 144, 144, lane);

    const int r1 = row0 + (lane >> 2), r2 = r1 + 8;
    const float d1 = diag[r1], d2 = diag[r2];
    float m1 = -CUDART_INF_F, m2 = -CUDART_INF_F;
    #pragma unroll
    for (int t = 0; t < 18; t++) {
        int col = col0 + t * 8 + (lane & 3) * 2;
        if (col < MDIM) {
            m1 = fmaxf(m1, fmaxf(C[t][0], C[t][1]));
            m2 = fmaxf(m2, fmaxf(C[t][2], C[t][3]));
        }
    }
    m1 = fmaxf(m1, __shfl_xor_sync(~0u, m1, 1));
    m1 = fmaxf(m1, __shfl_xor_sync(~0u, m1, 2));
    m2 = fmaxf(m2, __shfl_xor_sync(~0u, m2, 1));
    m2 = fmaxf(m2, __shfl_xor_sync(~0u, m2, 2));
    if ((lane & 3) == 0) {
        srm[cw * 64 + r1] = m1;
        srm[cw * 64 + r2] = m2;
    }
    __syncthreads();   // all GEMM1 reads done; proj/X smem may be overwritten now
    const float rmA = fmaxf(srm[r1], srm[64 + r1]);
    const float rmB = fmaxf(srm[r2], srm[64 + r2]);

    // qp = ratio*(exp(dd - diag - rowmax)+eps), bf16 hi/lo into [64][296]
    #pragma unroll
    for (int t = 0; t < 18; t++) {
        int col = col0 + t * 8 + (lane & 3) * 2;
        float q0 = 0.f, q1 = 0.f, q2 = 0.f, q3 = 0.f;
        if (col < MDIM) {
            q0 = RATIO * (__expf(C[t][0] - d1 - rmA) + EPSV);
            q1 = RATIO * (__expf(C[t][1] - d1 - rmA) + EPSV);
            q2 = RATIO * (__expf(C[t][2] - d2 - rmB) + EPSV);
            q3 = RATIO * (__expf(C[t][3] - d2 - rmB) + EPSV);
        }
        uint16_t h0, l0, h1, l1;
        bsplit(q0, h0, l0); bsplit(q1, h1, l1);
        *(uint32_t*)(sm + QPH + r1 * 592 + col * 2) = (uint32_t)h0 | ((uint32_t)h1 << 16);
        *(uint32_t*)(sm + QPL + r1 * 592 + col * 2) = (uint32_t)l0 | ((uint32_t)l1 << 16);
        bsplit(q2, h0, l0); bsplit(q3, h1, l1);
        *(uint32_t*)(sm + QPH + r2 * 592 + col * 2) = (uint32_t)h0 | ((uint32_t)h1 << 16);
        *(uint32_t*)(sm + QPL + r2 * 592 + col * 2) = (uint32_t)l0 | ((uint32_t)l1 << 16);
    }
    // ctx^T [80][288] -> smem [80][296]
    {
        const uint4* s0 = (const uint4*)(g_ctxB0 + (size_t)bh * 23040);
        const uint4* s1 = (const uint4*)(g_ctxB1 + (size_t)bh * 23040);
        for (int i = tid; i < 2880; i += 256) {
            int rr = i / 36, kk = i % 36;
            *(uint4*)(sm + CTH + rr * 592 + kk * 16) = s0[i];
            *(uint4*)(sm + CTL + rr * 592 + kk * 16) = s1[i];
        }
    }
    __syncthreads();

    float C2[6][4] = {};
    if (cw == 0)
        wgemm<3, 18>(C2, sb + QPH + row0 * 592, sb + QPL + row0 * 592, 592,
                     sb + CTH, sb + CTL, 592, lane);
    else
        wgemm<2, 18>(C2, sb + QPH + row0 * 592, sb + QPL + row0 * 592, 592,
                     sb + CTH + 48 * 592, sb + CTL + 48 * 592, 592, lane);

    // denominator = C2 col 64 (cw==1, tile 2, lane&3==0)
    if (cw == 1 && (lane & 3) == 0) {
        srm[r1] = C2[2][0];
        srm[r2] = C2[2][2];
    }
    __syncthreads();
    const float i1 = 1.f / srm[r1], i2 = 1.f / srm[r2];
    float* ob = out + (size_t)(bh * NSEQ + nt * 64) * 64;
    const int c2o = cw * 48;
    const int nst = cw ? 2 : 6;   // cw1 stores cols 48..63 only
    for (int t = 0; t < nst; t++) {
        int col = c2o + t * 8 + (lane & 3) * 2;
        *(float2*)(ob + (size_t)r1 * 64 + col) = make_float2(C2[t][0] * i1, C2[t][1] * i1);
        *(float2*)(ob + (size_t)r2 * 64 + col) = make_float2(C2[t][2] * i2, C2[t][3] * i2);
    }
}

// ---------------------------------------------------------------------------
extern "C" void kernel_launch(void* const* d_in, const int* in_sizes, int n_in,
                              void* d_out, int out_size) {
    const float* q    = (const float*)d_in[0];
    const float* k    = (const float*)d_in[1];
    const float* v    = (const float*)d_in[2];
    const float* proj = (const float*)d_in[3];
    float* out = (float*)d_out;

    cudaFuncSetAttribute(pass1, cudaFuncAttributeMaxDynamicSharedMemorySize, SMEM1);
    cudaFuncSetAttribute(pass3, cudaFuncAttributeMaxDynamicSharedMemorySize, SMEM3);

    prep<<<288, 256>>>(proj);
    pass1<<<BHN * 256, 256, SMEM1>>>(k);
    pass2a<<<BHN * 5 * 16, 256>>>(v);
    pass2b<<<(BHN * 288 * 80 + 255) / 256, 256>>>();
    pass3<<<BHN * 256, 256, SMEM3>>>(q, out);
}

// round 8
// speedup vs baseline: 1.8218x; 1.2861x over previous
#include <cuda_runtime.h>
#include <cuda_bf16.h>
#include <math_constants.h>
#include <cstdint>

// B=2,H=8 -> BHN=16; N=16384; D=64; M=266 (pad 288/320)
#define BHN  16
#define NSEQ 16384
#define MDIM 266
#define MP   272
#define DN    0.35355339059327379f
#define RATIO 0.06131393394849658f
#define EPSV  1e-4f

__device__ float g_headmax[BHN];
__device__ __align__(16) float g_ddk[(size_t)BHN * NSEQ * MP];
__device__ __align__(16) float g_ctx_part[(size_t)BHN * 16 * 320 * 80];
__device__ __align__(16) unsigned short g_projB0[288 * 72];
__device__ __align__(16) unsigned short g_projB1[288 * 72];
__device__ __align__(16) unsigned short g_ctxB0[BHN * 80 * 288];
__device__ __align__(16) unsigned short g_ctxB1[BHN * 80 * 288];

// ---- smem byte offsets: pass1/pass3 ----
#define XH 0u
#define XL 9216u
#define PH 18432u
#define PL 59904u
#define P_DIAG 101376u
#define P_SWM  101632u
#define SMEM1  101664u
#define QPH 0u
#define QPL 37888u
#define CTH 75776u
#define CTL 123136u
#define Q_DIAG 170496u
#define Q_SRM  170752u
#define SMEM3  171264u
// ---- pass2a (dynamic): kp [64][328]u16 hi/lo, v [64][88]u16 hi/lo ----
#define KH2 0u
#define KL2 41984u
#define VH2 83968u
#define VL2 95232u
#define SMEM2 106496u
#define SA 656      // kp row stride bytes
#define SB 176      // v row stride bytes

__device__ __forceinline__ uint32_t smem_u32(const void* p) {
    uint32_t a;
    asm("{ .reg .u64 t; cvta.to.shared.u64 t, %1; cvt.u32.u64 %0, t; }" : "=r"(a) : "l"(p));
    return a;
}
__device__ __forceinline__ void ldm4(uint32_t f[4], uint32_t a) {
    asm volatile("ldmatrix.sync.aligned.m8n8.x4.shared.b16 {%0,%1,%2,%3}, [%4];"
        : "=r"(f[0]), "=r"(f[1]), "=r"(f[2]), "=r"(f[3]) : "r"(a));
}
__device__ __forceinline__ void ldm4t(uint32_t f[4], uint32_t a) {
    asm volatile("ldmatrix.sync.aligned.m8n8.x4.trans.shared.b16 {%0,%1,%2,%3}, [%4];"
        : "=r"(f[0]), "=r"(f[1]), "=r"(f[2]), "=r"(f[3]) : "r"(a));
}
__device__ __forceinline__ void mma16816(float c[4], const uint32_t a[4],
                                         uint32_t b0, uint32_t b1) {
    asm volatile("mma.sync.aligned.m16n8k16.row.col.f32.bf16.bf16.f32 "
        "{%0,%1,%2,%3},{%4,%5,%6,%7},{%8,%9},{%0,%1,%2,%3};"
        : "+f"(c[0]), "+f"(c[1]), "+f"(c[2]), "+f"(c[3])
        : "r"(a[0]), "r"(a[1]), "r"(a[2]), "r"(a[3]), "r"(b0), "r"(b1));
}

// hi/lo 3-product warp GEMM (non-trans operands; pass1/pass3)
template <int NTP, int KS>
__device__ __forceinline__ void wgemm(float C[][4], uint32_t aH, uint32_t aL, int ldaB,
                                      uint32_t bH, uint32_t bL, int ldbB, int lane) {
    const uint32_t ao = (uint32_t)(lane & 15) * ldaB + (uint32_t)(lane >> 4) * 16;
    const uint32_t bo = (uint32_t)(lane & 15) * ldbB + (uint32_t)(lane >> 4) * 16;
    for (int ks = 0; ks < KS; ks++) {
        uint32_t ah[4], al[4];
        ldm4(ah, aH + ao + ks * 32);
        ldm4(al, aL + ao + ks * 32);
        #pragma unroll
        for (int tp = 0; tp < NTP; tp++) {
            uint32_t bh[4], bl[4];
            ldm4(bh, bH + bo + tp * 16 * ldbB + ks * 32);
            ldm4(bl, bL + bo + tp * 16 * ldbB + ks * 32);
            mma16816(C[2 * tp], ah, bh[0], bh[2]);
            mma16816(C[2 * tp], ah, bl[0], bl[2]);
            mma16816(C[2 * tp], al, bh[0], bh[2]);
            mma16816(C[2 * tp + 1], ah, bh[1], bh[3]);
            mma16816(C[2 * tp + 1], ah, bl[1], bl[3]);
            mma16816(C[2 * tp + 1], al, bh[1], bh[3]);
        }
    }
}

__device__ __forceinline__ void bsplit(float x, uint16_t& h, uint16_t& l) {
    __nv_bfloat16 hb = __float2bfloat16(x);
    __nv_bfloat16 lb = __float2bfloat16(x - __bfloat162float(hb));
    h = __bfloat16_as_ushort(hb);
    l = __bfloat16_as_ushort(lb);
}
__device__ __forceinline__ uint32_t bpack(float a, float b, uint32_t& lo) {
    uint16_t h0, l0, h1, l1;
    bsplit(a, h0, l0);
    bsplit(b, h1, l1);
    lo = (uint32_t)l0 | ((uint32_t)l1 << 16);
    return (uint32_t)h0 | ((uint32_t)h1 << 16);
}
__device__ __forceinline__ void atomicMaxFloat(float* addr, float val) {
    int* ai = (int*)addr;
    int old = *ai;
    while (__int_as_float(old) < val) {
        int prev = atomicCAS(ai, old, __float_as_int(val));
        if (prev == old) return;
        old = prev;
    }
}

// stage 64x64 fp32 rows -> scaled bf16 hi/lo [64][72-stride] + diag (pass1/pass3)
__device__ __forceinline__ void stage_x(const float* __restrict__ src, uint8_t* sm,
                                        uint32_t offH, uint32_t offL, float* diag, int tid) {
    const int r = tid >> 2, c0 = (tid & 3) * 16;
    const float4* p = (const float4*)(src + (size_t)r * 64 + c0);
    uint32_t h[8], l[8];
    float sq = 0.f;
    #pragma unroll
    for (int j = 0; j < 4; j++) {
        float4 t = p[j];
        float v[4] = {t.x * DN, t.y * DN, t.z * DN, t.w * DN};
        h[j * 2]     = bpack(v[0], v[1], l[j * 2]);
        h[j * 2 + 1] = bpack(v[2], v[3], l[j * 2 + 1]);
        sq = fmaf(v[0], v[0], fmaf(v[1], v[1], fmaf(v[2], v[2], fmaf(v[3], v[3], sq))));
    }
    uint32_t ba = (uint32_t)r * 144 + (uint32_t)c0 * 2;
    *(uint4*)(sm + offH + ba)      = make_uint4(h[0], h[1], h[2], h[3]);
    *(uint4*)(sm + offH + ba + 16) = make_uint4(h[4], h[5], h[6], h[7]);
    *(uint4*)(sm + offL + ba)      = make_uint4(l[0], l[1], l[2], l[3]);
    *(uint4*)(sm + offL + ba + 16) = make_uint4(l[4], l[5], l[6], l[7]);
    sq += __shfl_xor_sync(~0u, sq, 1);
    sq += __shfl_xor_sync(~0u, sq, 2);
    if ((tid & 3) == 0) diag[r] = 0.5f * sq;
}
__device__ __forceinline__ void copy_proj(uint8_t* sm, int tid) {
    for (int i = tid; i < 2592; i += 256) {
        ((uint4*)(sm + PH))[i] = ((const uint4*)g_projB0)[i];
        ((uint4*)(sm + PL))[i] = ((const uint4*)g_projB1)[i];
    }
}

__global__ void prep(const float* __restrict__ proj) {
    int gid = blockIdx.x * 256 + threadIdx.x;
    int r = gid >> 6, c = gid & 63;
    float v = (r < MDIM) ? proj[r * 64 + c] : 0.f;
    uint16_t h, l;
    bsplit(v, h, l);
    g_projB0[r * 72 + c] = h;
    g_projB1[r * 72 + c] = l;
    if (gid < BHN) g_headmax[gid] = -CUDART_INF_F;
}

// ---------------------------------------------------------------------------
// pass1: dd_k = (k*dn)@P^T via HMMA; store dd-diag; head max. grid = 16*256.
// ---------------------------------------------------------------------------
__global__ __launch_bounds__(256) void pass1(const float* __restrict__ kin) {
    extern __shared__ __align__(16) uint8_t sm[];
    uint32_t sb = smem_u32(sm);
    float* diag = (float*)(sm + P_DIAG);
    float* swm = (float*)(sm + P_SWM);
    const int tid = threadIdx.x, w = tid >> 5, lane = tid & 31;
    const int bh = blockIdx.x >> 8, nt = blockIdx.x & 255;
    const int row0 = (w >> 1) * 16, col0 = (w & 1) * 144;

    copy_proj(sm, tid);
    stage_x(kin + (size_t)(bh * NSEQ + nt * 64) * 64, sm, XH, XL, diag, tid);
    __syncthreads();

    float C[18][4] = {};
    wgemm<9, 4>(C, sb + XH + row0 * 144, sb + XL + row0 * 144, 144,
                sb + PH + col0 * 144, sb + PL + col0 * 144, 144, lane);

    const int r1 = row0 + (lane >> 2), r2 = r1 + 8;
    const float d1 = diag[r1], d2 = diag[r2];
    const size_t rb = (size_t)(bh * NSEQ + nt * 64) * MP;
    float tmax = -CUDART_INF_F;
    #pragma unroll
    for (int t = 0; t < 18; t++) {
        int col = col0 + t * 8 + (lane & 3) * 2;
        if (col < MDIM) {
            tmax = fmaxf(tmax, fmaxf(fmaxf(C[t][0], C[t][1]), fmaxf(C[t][2], C[t][3])));
            *(float2*)&g_ddk[rb + (size_t)r1 * MP + col] = make_float2(C[t][0] - d1, C[t][1] - d1);
            *(float2*)&g_ddk[rb + (size_t)r2 * MP + col] = make_float2(C[t][2] - d2, C[t][3] - d2);
        }
    }
    #pragma unroll
    for (int o = 16; o; o >>= 1) tmax = fmaxf(tmax, __shfl_xor_sync(~0u, tmax, o));
    if (lane == 0) swm[w] = tmax;
    __syncthreads();
    if (tid == 0) {
        float m = swm[0];
        #pragma unroll
        for (int i = 1; i < 8; i++) m = fmaxf(m, swm[i]);
        atomicMaxFloat(&g_headmax[bh], m);
    }
}

// ---------------------------------------------------------------------------
// pass2a: per (head, split) block, full M=320, trans-ldmatrix operands.
// kp smem [n=64][m=328], v smem [n=64][d=88] (col 64 = ones -> ksum).
// grid = 16*16, 320 threads (10 warps x 2 row-tiles of 16 m).
// ---------------------------------------------------------------------------
__global__ __launch_bounds__(320) void pass2a(const float* __restrict__ vin) {
    extern __shared__ __align__(16) uint8_t sm[];
    uint32_t sb = smem_u32(sm);
    const int tid = threadIdx.x, w = tid >> 5, lane = tid & 31;
    const int bh = blockIdx.x >> 4, split = blockIdx.x & 15;
    const float stab = g_headmax[bh];

    // one-time pads: kp m>=266 zero (mp 133..163); v cols 64..87 (ones col 64)
    for (int i = tid; i < 64 * 31; i += 320) {
        int n = i / 31, mp = 133 + i % 31;
        *(uint32_t*)(sm + KH2 + n * SA + mp * 4) = 0u;
        *(uint32_t*)(sm + KL2 + n * SA + mp * 4) = 0u;
    }
    for (int i = tid; i < 64 * 12; i += 320) {
        int n = i / 12, c = i % 12;
        *(uint32_t*)(sm + VH2 + n * SB + 128 + c * 4) = (c == 0) ? 0x3F80u : 0u;
        *(uint32_t*)(sm + VL2 + n * SB + 128 + c * 4) = 0u;
    }

    const uint32_t lo_ = ((uint32_t)(lane & 7) + (uint32_t)((lane >> 4) & 1) * 8);
    const uint32_t aoff = lo_ * SA + (uint32_t)((lane >> 3) & 1) * 16;
    const uint32_t boff = lo_ * SB + (uint32_t)((lane >> 3) & 1) * 16;
    const int m0w = w * 32;   // warp m base (2 tiles of 16)

    float C[2][10][4] = {};
    for (int t = 0; t < 16; t++) {
        const size_t n0 = (size_t)bh * NSEQ + (size_t)split * 1024 + t * 64;
        __syncthreads();
        // stage kp: [n][m] u32 pairs, conflict-free
        for (int i = tid; i < 64 * 133; i += 320) {
            int n = i / 133, mp = i % 133;
            float2 dd = *(const float2*)&g_ddk[(n0 + n) * MP + mp * 2];
            float k0 = RATIO * (__expf(dd.x - stab) + EPSV);
            float k1 = RATIO * (__expf(dd.y - stab) + EPSV);
            uint32_t lw, hw = bpack(k0, k1, lw);
            *(uint32_t*)(sm + KH2 + n * SA + mp * 4) = hw;
            *(uint32_t*)(sm + KL2 + n * SA + mp * 4) = lw;
        }
        // stage v natural [n][d]
        for (int i = tid; i < 64 * 32; i += 320) {
            int n = i >> 5, dp = i & 31;
            float2 vv = *(const float2*)&vin[(n0 + n) * 64 + dp * 2];
            uint32_t lw, hw = bpack(vv.x, vv.y, lw);
            *(uint32_t*)(sm + VH2 + n * SB + dp * 4) = hw;
            *(uint32_t*)(sm + VL2 + n * SB + dp * 4) = lw;
        }
        __syncthreads();
        // MMA: K=64 (4 ks), B hoisted across the 2 row-tiles
        for (int ks = 0; ks < 4; ks++) {
            uint32_t bh4[5][4], bl4[5][4];
            #pragma unroll
            for (int tp = 0; tp < 5; tp++) {
                ldm4t(bh4[tp], sb + VH2 + boff + ks * 16 * SB + tp * 32);
                ldm4t(bl4[tp], sb + VL2 + boff + ks * 16 * SB + tp * 32);
            }
            #pragma unroll
            for (int rt = 0; rt < 2; rt++) {
                uint32_t ah[4], al[4];
                ldm4t(ah, sb + KH2 + aoff + ks * 16 * SA + (m0w + rt * 16) * 2);
                ldm4t(al, sb + KL2 + aoff + ks * 16 * SA + (m0w + rt * 16) * 2);
                #pragma unroll
                for (int tp = 0; tp < 5; tp++) {
                    mma16816(C[rt][2 * tp], ah, bh4[tp][0], bh4[tp][2]);
                    mma16816(C[rt][2 * tp], ah, bl4[tp][0], bl4[tp][2]);
                    mma16816(C[rt][2 * tp], al, bh4[tp][0], bh4[tp][2]);
                    mma16816(C[rt][2 * tp + 1], ah, bh4[tp][1], bh4[tp][3]);
                    mma16816(C[rt][2 * tp + 1], ah, bl4[tp][1], bl4[tp][3]);
                    mma16816(C[rt][2 * tp + 1], al, bh4[tp][1], bh4[tp][3]);
                }
            }
        }
    }
    // store partials [m][80]
    float* pb = g_ctx_part + (size_t)(bh * 16 + split) * (320 * 80);
    #pragma unroll
    for (int rt = 0; rt < 2; rt++) {
        int r1 = m0w + rt * 16 + (lane >> 2), r2 = r1 + 8;
        #pragma unroll
        for (int tp = 0; tp < 5; tp++) {
            int col = tp * 16 + (lane & 3) * 2;
            *(float2*)(pb + (size_t)r1 * 80 + col)     = make_float2(C[rt][2 * tp][0], C[rt][2 * tp][1]);
            *(float2*)(pb + (size_t)r2 * 80 + col)     = make_float2(C[rt][2 * tp][2], C[rt][2 * tp][3]);
            *(float2*)(pb + (size_t)r1 * 80 + col + 8) = make_float2(C[rt][2 * tp + 1][0], C[rt][2 * tp + 1][1]);
            *(float2*)(pb + (size_t)r2 * 80 + col + 8) = make_float2(C[rt][2 * tp + 1][2], C[rt][2 * tp + 1][3]);
        }
    }
}

// ---------------------------------------------------------------------------
// pass2b: reduce splits; emit bf16 hi/lo ctx^T [bh][80][288] (d=64 is ksum).
// ---------------------------------------------------------------------------
__global__ __launch_bounds__(256) void pass2b() {
    int gid = blockIdx.x * 256 + threadIdx.x;
    if (gid >= BHN * 288 * 80) return;
    int bh = gid / (288 * 80);
    int rem = gid % (288 * 80);
    int m = rem / 80, d = rem % 80;
    float s = 0.f;
    #pragma unroll
    for (int sp = 0; sp < 16; sp++)
        s += g_ctx_part[((size_t)(bh * 16 + sp) * 320 + m) * 80 + d];
    uint16_t h, l;
    bsplit(s, h, l);
    g_ctxB0[(size_t)bh * 23040 + d * 288 + m] = h;
    g_ctxB1[(size_t)bh * 23040 + d * 288 + m] = l;
}

// ---------------------------------------------------------------------------
// pass3: fused q side. GEMM1 -> rowmax -> exp -> GEMM2 (denom = col 64).
// ---------------------------------------------------------------------------
__global__ __launch_bounds__(256) void pass3(const float* __restrict__ qin,
                                             float* __restrict__ out) {
    extern __shared__ __align__(16) uint8_t sm[];
    uint32_t sb = smem_u32(sm);
    float* diag = (float*)(sm + Q_DIAG);
    float* srm = (float*)(sm + Q_SRM);
    const int tid = threadIdx.x, w = tid >> 5, lane = tid & 31;
    const int bh = blockIdx.x >> 8, nt = blockIdx.x & 255;
    const int row0 = (w >> 1) * 16, cw = w & 1, col0 = cw * 144;

    copy_proj(sm, tid);
    stage_x(qin + (size_t)(bh * NSEQ + nt * 64) * 64, sm, XH, XL, diag, tid);
    __syncthreads();

    float C[18][4] = {};
    wgemm<9, 4>(C, sb + XH + row0 * 144, sb + XL + row0 * 144, 144,
                sb + PH + col0 * 144, sb + PL + col0 * 144, 144, lane);

    const int r1 = row0 + (lane >> 2), r2 = r1 + 8;
    const float d1 = diag[r1], d2 = diag[r2];
    float m1 = -CUDART_INF_F, m2 = -CUDART_INF_F;
    #pragma unroll
    for (int t = 0; t < 18; t++) {
        int col = col0 + t * 8 + (lane & 3) * 2;
        if (col < MDIM) {
            m1 = fmaxf(m1, fmaxf(C[t][0], C[t][1]));
            m2 = fmaxf(m2, fmaxf(C[t][2], C[t][3]));
        }
    }
    m1 = fmaxf(m1, __shfl_xor_sync(~0u, m1, 1));
    m1 = fmaxf(m1, __shfl_xor_sync(~0u, m1, 2));
    m2 = fmaxf(m2, __shfl_xor_sync(~0u, m2, 1));
    m2 = fmaxf(m2, __shfl_xor_sync(~0u, m2, 2));
    if ((lane & 3) == 0) {
        srm[cw * 64 + r1] = m1;
        srm[cw * 64 + r2] = m2;
    }
    __syncthreads();
    const float rmA = fmaxf(srm[r1], srm[64 + r1]);
    const float rmB = fmaxf(srm[r2], srm[64 + r2]);

    #pragma unroll
    for (int t = 0; t < 18; t++) {
        int col = col0 + t * 8 + (lane & 3) * 2;
        float q0 = 0.f, q1 = 0.f, q2 = 0.f, q3 = 0.f;
        if (col < MDIM) {
            q0 = RATIO * (__expf(C[t][0] - d1 - rmA) + EPSV);
            q1 = RATIO * (__expf(C[t][1] - d1 - rmA) + EPSV);
            q2 = RATIO * (__expf(C[t][2] - d2 - rmB) + EPSV);
            q3 = RATIO * (__expf(C[t][3] - d2 - rmB) + EPSV);
        }
        uint32_t lw, hw;
        hw = bpack(q0, q1, lw);
        *(uint32_t*)(sm + QPH + r1 * 592 + col * 2) = hw;
        *(uint32_t*)(sm + QPL + r1 * 592 + col * 2) = lw;
        hw = bpack(q2, q3, lw);
        *(uint32_t*)(sm + QPH + r2 * 592 + col * 2) = hw;
        *(uint32_t*)(sm + QPL + r2 * 592 + col * 2) = lw;
    }
    {
        const uint4* s0 = (const uint4*)(g_ctxB0 + (size_t)bh * 23040);
        const uint4* s1 = (const uint4*)(g_ctxB1 + (size_t)bh * 23040);
        for (int i = tid; i < 2880; i += 256) {
            int rr = i / 36, kk = i % 36;
            *(uint4*)(sm + CTH + rr * 592 + kk * 16) = s0[i];
            *(uint4*)(sm + CTL + rr * 592 + kk * 16) = s1[i];
        }
    }
    __syncthreads();

    float C2[6][4] = {};
    if (cw == 0)
        wgemm<3, 18>(C2, sb + QPH + row0 * 592, sb + QPL + row0 * 592, 592,
                     sb + CTH, sb + CTL, 592, lane);
    else
        wgemm<2, 18>(C2, sb + QPH + row0 * 592, sb + QPL + row0 * 592, 592,
                     sb + CTH + 48 * 592, sb + CTL + 48 * 592, 592, lane);

    if (cw == 1 && (lane & 3) == 0) {
        srm[r1] = C2[2][0];
        srm[r2] = C2[2][2];
    }
    __syncthreads();
    const float i1 = 1.f / srm[r1], i2 = 1.f / srm[r2];
    float* ob = out + (size_t)(bh * NSEQ + nt * 64) * 64;
    const int c2o = cw * 48;
    const int nst = cw ? 2 : 6;
    for (int t = 0; t < nst; t++) {
        int col = c2o + t * 8 + (lane & 3) * 2;
        *(float2*)(ob + (size_t)r1 * 64 + col) = make_float2(C2[t][0] * i1, C2[t][1] * i1);
        *(float2*)(ob + (size_t)r2 * 64 + col) = make_float2(C2[t][2] * i2, C2[t][3] * i2);
    }
}

// ---------------------------------------------------------------------------
extern "C" void kernel_launch(void* const* d_in, const int* in_sizes, int n_in,
                              void* d_out, int out_size) {
    const float* q    = (const float*)d_in[0];
    const float* k    = (const float*)d_in[1];
    const float* v    = (const float*)d_in[2];
    const float* proj = (const float*)d_in[3];
    float* out = (float*)d_out;

    cudaFuncSetAttribute(pass1, cudaFuncAttributeMaxDynamicSharedMemorySize, SMEM1);
    cudaFuncSetAttribute(pass2a, cudaFuncAttributeMaxDynamicSharedMemorySize, SMEM2);
    cudaFuncSetAttribute(pass3, cudaFuncAttributeMaxDynamicSharedMemorySize, SMEM3);

    prep<<<288, 256>>>(proj);
    pass1<<<BHN * 256, 256, SMEM1>>>(k);
    pass2a<<<BHN * 16, 320, SMEM2>>>(v);
    pass2b<<<(BHN * 288 * 80 + 255) / 256, 256>>>();
    pass3<<<BHN * 256, 256, SMEM3>>>(q, out);
}

// round 9
// speedup vs baseline: 1.8450x; 1.0128x over previous
#include <cuda_runtime.h>
#include <cuda_bf16.h>
#include <math_constants.h>
#include <cstdint>

// B=2,H=8 -> BHN=16; N=16384; D=64; M=266 (pad 288/320)
#define BHN  16
#define NSEQ 16384
#define MDIM 266
#define NSPL 32
#define DN    0.35355339059327379f
#define RATIO 0.06131393394849658f
#define EPSV  1e-4f

__device__ float g_headmax[BHN];
__device__ __align__(16) float g_ctx_part[(size_t)BHN * NSPL * 320 * 80];
__device__ __align__(16) unsigned short g_projB0[320 * 72];
__device__ __align__(16) unsigned short g_projB1[320 * 72];
__device__ __align__(16) unsigned short g_ctxB0[BHN * 80 * 288];
__device__ __align__(16) unsigned short g_ctxB1[BHN * 80 * 288];

// ---- smem byte offsets: pass1max / pass3 (stage-1 shared layout) ----
#define XH 0u
#define XL 9216u
#define PH 18432u
#define PL 59904u
#define P_SWM  101376u
#define SMEM1M 101408u
#define QPH 0u
#define QPL 37888u
#define CTH 75776u
#define CTL 123136u
#define Q_DIAG 170496u
#define Q_SRM  170752u
#define SMEM3  171264u
// ---- pass2a ----
#define PH2   0u          // proj hi [320][72] stride 144 -> 46080
#define PL2   46080u
#define KH2   92160u      // kp hi [64][SA]
#define KL2   134144u
#define VH2   176128u     // v hi [64][SB]
#define VL2   187392u
#define XH2   198656u     // k hi [64][144]
#define XL2   207872u
#define DIAG2 217088u
#define SMEM2 217344u
#define SA 656
#define SB 176

__device__ __forceinline__ uint32_t smem_u32(const void* p) {
    uint32_t a;
    asm("{ .reg .u64 t; cvta.to.shared.u64 t, %1; cvt.u32.u64 %0, t; }" : "=r"(a) : "l"(p));
    return a;
}
__device__ __forceinline__ void ldm4(uint32_t f[4], uint32_t a) {
    asm volatile("ldmatrix.sync.aligned.m8n8.x4.shared.b16 {%0,%1,%2,%3}, [%4];"
        : "=r"(f[0]), "=r"(f[1]), "=r"(f[2]), "=r"(f[3]) : "r"(a));
}
__device__ __forceinline__ void ldm4t(uint32_t f[4], uint32_t a) {
    asm volatile("ldmatrix.sync.aligned.m8n8.x4.trans.shared.b16 {%0,%1,%2,%3}, [%4];"
        : "=r"(f[0]), "=r"(f[1]), "=r"(f[2]), "=r"(f[3]) : "r"(a));
}
__device__ __forceinline__ void mma16816(float c[4], const uint32_t a[4],
                                         uint32_t b0, uint32_t b1) {
    asm volatile("mma.sync.aligned.m16n8k16.row.col.f32.bf16.bf16.f32 "
        "{%0,%1,%2,%3},{%4,%5,%6,%7},{%8,%9},{%0,%1,%2,%3};"
        : "+f"(c[0]), "+f"(c[1]), "+f"(c[2]), "+f"(c[3])
        : "r"(a[0]), "r"(a[1]), "r"(a[2]), "r"(a[3]), "r"(b0), "r"(b1));
}

// hi/lo 3-product warp GEMM (non-trans operands)
template <int NTP, int KS>
__device__ __forceinline__ void wgemm(float C[][4], uint32_t aH, uint32_t aL, int ldaB,
                                      uint32_t bH, uint32_t bL, int ldbB, int lane) {
    const uint32_t ao = (uint32_t)(lane & 15) * ldaB + (uint32_t)(lane >> 4) * 16;
    const uint32_t bo = (uint32_t)(lane & 15) * ldbB + (uint32_t)(lane >> 4) * 16;
    for (int ks = 0; ks < KS; ks++) {
        uint32_t ah[4], al[4];
        ldm4(ah, aH + ao + ks * 32);
        ldm4(al, aL + ao + ks * 32);
        #pragma unroll
        for (int tp = 0; tp < NTP; tp++) {
            uint32_t bh[4], bl[4];
            ldm4(bh, bH + bo + tp * 16 * ldbB + ks * 32);
            ldm4(bl, bL + bo + tp * 16 * ldbB + ks * 32);
            mma16816(C[2 * tp], ah, bh[0], bh[2]);
            mma16816(C[2 * tp], ah, bl[0], bl[2]);
            mma16816(C[2 * tp], al, bh[0], bh[2]);
            mma16816(C[2 * tp + 1], ah, bh[1], bh[3]);
            mma16816(C[2 * tp + 1], ah, bl[1], bl[3]);
            mma16816(C[2 * tp + 1], al, bh[1], bh[3]);
        }
    }
}

__device__ __forceinline__ void bsplit(float x, uint16_t& h, uint16_t& l) {
    __nv_bfloat16 hb = __float2bfloat16(x);
    __nv_bfloat16 lb = __float2bfloat16(x - __bfloat162float(hb));
    h = __bfloat16_as_ushort(hb);
    l = __bfloat16_as_ushort(lb);
}
__device__ __forceinline__ uint32_t bpack(float a, float b, uint32_t& lo) {
    uint16_t h0, l0, h1, l1;
    bsplit(a, h0, l0);
    bsplit(b, h1, l1);
    lo = (uint32_t)l0 | ((uint32_t)l1 << 16);
    return (uint32_t)h0 | ((uint32_t)h1 << 16);
}
__device__ __forceinline__ void atomicMaxFloat(float* addr, float val) {
    int* ai = (int*)addr;
    int old = *ai;
    while (__int_as_float(old) < val) {
        int prev = atomicCAS(ai, old, __float_as_int(val));
        if (prev == old) return;
        old = prev;
    }
}

// stage 64x64 fp32 rows -> scaled bf16 hi/lo [64][72-stride] (+ optional diag)
// requires tid < 256
__device__ __forceinline__ void stage_x(const float* __restrict__ src, uint8_t* sm,
                                        uint32_t offH, uint32_t offL, float* diag, int tid) {
    const int r = tid >> 2, c0 = (tid & 3) * 16;
    const float4* p = (const float4*)(src + (size_t)r * 64 + c0);
    uint32_t h[8], l[8];
    float sq = 0.f;
    #pragma unroll
    for (int j = 0; j < 4; j++) {
        float4 t = p[j];
        float v[4] = {t.x * DN, t.y * DN, t.z * DN, t.w * DN};
        h[j * 2]     = bpack(v[0], v[1], l[j * 2]);
        h[j * 2 + 1] = bpack(v[2], v[3], l[j * 2 + 1]);
        sq = fmaf(v[0], v[0], fmaf(v[1], v[1], fmaf(v[2], v[2], fmaf(v[3], v[3], sq))));
    }
    uint32_t ba = (uint32_t)r * 144 + (uint32_t)c0 * 2;
    *(uint4*)(sm + offH + ba)      = make_uint4(h[0], h[1], h[2], h[3]);
    *(uint4*)(sm + offH + ba + 16) = make_uint4(h[4], h[5], h[6], h[7]);
    *(uint4*)(sm + offL + ba)      = make_uint4(l[0], l[1], l[2], l[3]);
    *(uint4*)(sm + offL + ba + 16) = make_uint4(l[4], l[5], l[6], l[7]);
    if (diag) {
        sq += __shfl_xor_sync(~0u, sq, 1);
        sq += __shfl_xor_sync(~0u, sq, 2);
        if ((tid & 3) == 0) diag[r] = 0.5f * sq;
    }
}

__global__ void prep(const float* __restrict__ proj) {
    int gid = blockIdx.x * 256 + threadIdx.x;   // 320*64
    int r = gid >> 6, c = gid & 63;
    float v = (r < MDIM) ? proj[r * 64 + c] : 0.f;
    uint16_t h, l;
    bsplit(v, h, l);
    g_projB0[r * 72 + c] = h;
    g_projB1[r * 72 + c] = l;
    if (gid < BHN) g_headmax[gid] = -CUDART_INF_F;
}

// ---------------------------------------------------------------------------
// pass1max: dd_k GEMM, per-head max only (no stores). grid = 16*256.
// ---------------------------------------------------------------------------
__global__ __launch_bounds__(256) void pass1max(const float* __restrict__ kin) {
    extern __shared__ __align__(16) uint8_t sm[];
    uint32_t sb = smem_u32(sm);
    float* swm = (float*)(sm + P_SWM);
    const int tid = threadIdx.x, w = tid >> 5, lane = tid & 31;
    const int bh = blockIdx.x >> 8, nt = blockIdx.x & 255;
    const int row0 = (w >> 1) * 16, col0 = (w & 1) * 144;

    for (int i = tid; i < 2592; i += 256) {
        ((uint4*)(sm + PH))[i] = ((const uint4*)g_projB0)[i];
        ((uint4*)(sm + PL))[i] = ((const uint4*)g_projB1)[i];
    }
    stage_x(kin + (size_t)(bh * NSEQ + nt * 64) * 64, sm, XH, XL, nullptr, tid);
    __syncthreads();

    float C[18][4] = {};
    wgemm<9, 4>(C, sb + XH + row0 * 144, sb + XL + row0 * 144, 144,
                sb + PH + col0 * 144, sb + PL + col0 * 144, 144, lane);

    float tmax = -CUDART_INF_F;
    #pragma unroll
    for (int t = 0; t < 18; t++) {
        int col = col0 + t * 8 + (lane & 3) * 2;
        if (col < MDIM)
            tmax = fmaxf(tmax, fmaxf(fmaxf(C[t][0], C[t][1]), fmaxf(C[t][2], C[t][3])));
    }
    #pragma unroll
    for (int o = 16; o; o >>= 1) tmax = fmaxf(tmax, __shfl_xor_sync(~0u, tmax, o));
    if (lane == 0) swm[w] = tmax;
    __syncthreads();
    if (tid == 0) {
        float m = swm[0];
        #pragma unroll
        for (int i = 1; i < 8; i++) m = fmaxf(m, swm[i]);
        atomicMaxFloat(&g_headmax[bh], m);
    }
}

// ---------------------------------------------------------------------------
// pass2a: recompute dd via GEMM1, exp->kp smem, GEMM2 context (+ksum col).
// grid = 16*NSPL, 320 threads (10 warps x 32-m stripes).
// ---------------------------------------------------------------------------
__global__ __launch_bounds__(320) void pass2a(const float* __restrict__ kin,
                                              const float* __restrict__ vin) {
    extern __shared__ __align__(16) uint8_t sm[];
    uint32_t sb = smem_u32(sm);
    float* diag = (float*)(sm + DIAG2);
    const int tid = threadIdx.x, w = tid >> 5, lane = tid & 31;
    const int bh = blockIdx.x >> 5, split = blockIdx.x & 31;
    const float stab = g_headmax[bh];
    const int m0w = w * 32;

    // proj hi/lo [320][72] -> smem (rows >=266 already zero in global image)
    for (int i = tid; i < 2880; i += 320) {
        ((uint4*)(sm + PH2))[i] = ((const uint4*)g_projB0)[i];
        ((uint4*)(sm + PL2))[i] = ((const uint4*)g_projB1)[i];
    }
    // v pad cols 64..87: col 64 = ones (ksum), rest zero
    for (int i = tid; i < 64 * 12; i += 320) {
        int n = i / 12, c = i % 12;
        *(uint32_t*)(sm + VH2 + n * SB + 128 + c * 4) = (c == 0) ? 0x3F80u : 0u;
        *(uint32_t*)(sm + VL2 + n * SB + 128 + c * 4) = 0u;
    }

    const uint32_t ao1 = (uint32_t)(lane & 15) * 144u + (uint32_t)(lane >> 4) * 16u;
    const uint32_t lo_ = ((uint32_t)(lane & 7) + (uint32_t)((lane >> 4) & 1) * 8);
    const uint32_t aoff = lo_ * SA + (uint32_t)((lane >> 3) & 1) * 16;
    const uint32_t boff = lo_ * SB + (uint32_t)((lane >> 3) & 1) * 16;
    const int lr = lane >> 2, lc = (lane & 3) * 2;

    float C[2][10][4] = {};
    for (int t = 0; t < 8; t++) {
        const size_t n0 = (size_t)bh * NSEQ + (size_t)split * 512 + t * 64;
        __syncthreads();
        if (tid < 256)
            stage_x(kin + n0 * 64, sm, XH2, XL2, diag, tid);
        for (int i = tid; i < 64 * 32; i += 320) {
            int n = i >> 5, dp = i & 31;
            float2 vv = *(const float2*)&vin[(n0 + n) * 64 + dp * 2];
            uint32_t lw, hw = bpack(vv.x, vv.y, lw);
            *(uint32_t*)(sm + VH2 + n * SB + dp * 4) = hw;
            *(uint32_t*)(sm + VL2 + n * SB + dp * 4) = lw;
        }
        __syncthreads();

        // GEMM1: dd[n=64][m stripe 32] transient
        float C1[4][4][4] = {};
        for (int ks = 0; ks < 4; ks++) {
            uint32_t pbh[2][4], pbl[2][4];
            #pragma unroll
            for (int tp = 0; tp < 2; tp++) {
                ldm4(pbh[tp], sb + PH2 + (m0w + tp * 16) * 144 + ao1 + ks * 32);
                ldm4(pbl[tp], sb + PL2 + (m0w + tp * 16) * 144 + ao1 + ks * 32);
            }
            #pragma unroll
            for (int rt = 0; rt < 4; rt++) {
                uint32_t ah[4], al[4];
                ldm4(ah, sb + XH2 + rt * 16 * 144 + ao1 + ks * 32);
                ldm4(al, sb + XL2 + rt * 16 * 144 + ao1 + ks * 32);
                #pragma unroll
                for (int tp = 0; tp < 2; tp++) {
                    mma16816(C1[rt][2 * tp], ah, pbh[tp][0], pbh[tp][2]);
                    mma16816(C1[rt][2 * tp], ah, pbl[tp][0], pbl[tp][2]);
                    mma16816(C1[rt][2 * tp], al, pbh[tp][0], pbh[tp][2]);
                    mma16816(C1[rt][2 * tp + 1], ah, pbh[tp][1], pbh[tp][3]);
                    mma16816(C1[rt][2 * tp + 1], ah, pbl[tp][1], pbl[tp][3]);
                    mma16816(C1[rt][2 * tp + 1], al, pbh[tp][1], pbh[tp][3]);
                }
            }
        }
        // exp -> kp smem [n][m]
        #pragma unroll
        for (int rt = 0; rt < 4; rt++) {
            int r1 = rt * 16 + lr, r2 = r1 + 8;
            float dA = diag[r1], dB = diag[r2];
            #pragma unroll
            for (int t8 = 0; t8 < 4; t8++) {
                int m = m0w + t8 * 8 + lc;
                float k0 = 0.f, k1 = 0.f, k2 = 0.f, k3 = 0.f;
                if (m < MDIM) {
                    k0 = RATIO * (__expf(C1[rt][t8][0] - dA - stab) + EPSV);
                    k1 = RATIO * (__expf(C1[rt][t8][1] - dA - stab) + EPSV);
                    k2 = RATIO * (__expf(C1[rt][t8][2] - dB - stab) + EPSV);
                    k3 = RATIO * (__expf(C1[rt][t8][3] - dB - stab) + EPSV);
                }
                uint32_t lw, hw;
                hw = bpack(k0, k1, lw);
                *(uint32_t*)(sm + KH2 + r1 * SA + m * 2) = hw;
                *(uint32_t*)(sm + KL2 + r1 * SA + m * 2) = lw;
                hw = bpack(k2, k3, lw);
                *(uint32_t*)(sm + KH2 + r2 * SA + m * 2) = hw;
                *(uint32_t*)(sm + KL2 + r2 * SA + m * 2) = lw;
            }
        }
        __syncthreads();

        // GEMM2: context += kp^T(trans) x v(trans)
        for (int ks = 0; ks < 4; ks++) {
            uint32_t bh4[5][4], bl4[5][4];
            #pragma unroll
            for (int tp = 0; tp < 5; tp++) {
                ldm4t(bh4[tp], sb + VH2 + boff + ks * 16 * SB + tp * 32);
                ldm4t(bl4[tp], sb + VL2 + boff + ks * 16 * SB + tp * 32);
            }
            #pragma unroll
            for (int rt = 0; rt < 2; rt++) {
                uint32_t ah[4], al[4];
                ldm4t(ah, sb + KH2 + aoff + ks * 16 * SA + (m0w + rt * 16) * 2);
                ldm4t(al, sb + KL2 + aoff + ks * 16 * SA + (m0w + rt * 16) * 2);
                #pragma unroll
                for (int tp = 0; tp < 5; tp++) {
                    mma16816(C[rt][2 * tp], ah, bh4[tp][0], bh4[tp][2]);
                    mma16816(C[rt][2 * tp], ah, bl4[tp][0], bl4[tp][2]);
                    mma16816(C[rt][2 * tp], al, bh4[tp][0], bh4[tp][2]);
                    mma16816(C[rt][2 * tp + 1], ah, bh4[tp][1], bh4[tp][3]);
                    mma16816(C[rt][2 * tp + 1], ah, bl4[tp][1], bl4[tp][3]);
                    mma16816(C[rt][2 * tp + 1], al, bh4[tp][1], bh4[tp][3]);
                }
            }
        }
    }
    // store partials [m][80]
    float* pb = g_ctx_part + (size_t)(bh * NSPL + split) * (320 * 80);
    #pragma unroll
    for (int rt = 0; rt < 2; rt++) {
        int r1 = m0w + rt * 16 + lr, r2 = r1 + 8;
        #pragma unroll
        for (int tp = 0; tp < 5; tp++) {
            int col = tp * 16 + lc;
            *(float2*)(pb + (size_t)r1 * 80 + col)     = make_float2(C[rt][2 * tp][0], C[rt][2 * tp][1]);
            *(float2*)(pb + (size_t)r2 * 80 + col)     = make_float2(C[rt][2 * tp][2], C[rt][2 * tp][3]);
            *(float2*)(pb + (size_t)r1 * 80 + col + 8) = make_float2(C[rt][2 * tp + 1][0], C[rt][2 * tp + 1][1]);
            *(float2*)(pb + (size_t)r2 * 80 + col + 8) = make_float2(C[rt][2 * tp + 1][2], C[rt][2 * tp + 1][3]);
        }
    }
}

// ---------------------------------------------------------------------------
// pass2b: reduce splits; emit bf16 hi/lo ctx^T [bh][80][288] (d=64 is ksum).
// ---------------------------------------------------------------------------
__global__ __launch_bounds__(256) void pass2b() {
    int gid = blockIdx.x * 256 + threadIdx.x;
    if (gid >= BHN * 288 * 80) return;
    int bh = gid / (288 * 80);
    int rem = gid % (288 * 80);
    int m = rem / 80, d = rem % 80;
    float s = 0.f;
    #pragma unroll
    for (int sp = 0; sp < NSPL; sp++)
        s += g_ctx_part[((size_t)(bh * NSPL + sp) * 320 + m) * 80 + d];
    uint16_t h, l;
    bsplit(s, h, l);
    g_ctxB0[(size_t)bh * 23040 + d * 288 + m] = h;
    g_ctxB1[(size_t)bh * 23040 + d * 288 + m] = l;
}

// ---------------------------------------------------------------------------
// pass3: fused q side. GEMM1 -> rowmax -> exp -> GEMM2 (denom = col 64).
// ---------------------------------------------------------------------------
__global__ __launch_bounds__(256) void pass3(const float* __restrict__ qin,
                                             float* __restrict__ out) {
    extern __shared__ __align__(16) uint8_t sm[];
    uint32_t sb = smem_u32(sm);
    float* diag = (float*)(sm + Q_DIAG);
    float* srm = (float*)(sm + Q_SRM);
    const int tid = threadIdx.x, w = tid >> 5, lane = tid & 31;
    const int bh = blockIdx.x >> 8, nt = blockIdx.x & 255;
    const int row0 = (w >> 1) * 16, cw = w & 1, col0 = cw * 144;

    for (int i = tid; i < 2592; i += 256) {
        ((uint4*)(sm + PH))[i] = ((const uint4*)g_projB0)[i];
        ((uint4*)(sm + PL))[i] = ((const uint4*)g_projB1)[i];
    }
    stage_x(qin + (size_t)(bh * NSEQ + nt * 64) * 64, sm, XH, XL, diag, tid);
    __syncthreads();

    float C[18][4] = {};
    wgemm<9, 4>(C, sb + XH + row0 * 144, sb + XL + row0 * 144, 144,
                sb + PH + col0 * 144, sb + PL + col0 * 144, 144, lane);

    const int r1 = row0 + (lane >> 2), r2 = r1 + 8;
    const float d1 = diag[r1], d2 = diag[r2];
    float m1 = -CUDART_INF_F, m2 = -CUDART_INF_F;
    #pragma unroll
    for (int t = 0; t < 18; t++) {
        int col = col0 + t * 8 + (lane & 3) * 2;
        if (col < MDIM) {
            m1 = fmaxf(m1, fmaxf(C[t][0], C[t][1]));
            m2 = fmaxf(m2, fmaxf(C[t][2], C[t][3]));
        }
    }
    m1 = fmaxf(m1, __shfl_xor_sync(~0u, m1, 1));
    m1 = fmaxf(m1, __shfl_xor_sync(~0u, m1, 2));
    m2 = fmaxf(m2, __shfl_xor_sync(~0u, m2, 1));
    m2 = fmaxf(m2, __shfl_xor_sync(~0u, m2, 2));
    if ((lane & 3) == 0) {
        srm[cw * 64 + r1] = m1;
        srm[cw * 64 + r2] = m2;
    }
    __syncthreads();
    const float rmA = fmaxf(srm[r1], srm[64 + r1]);
    const float rmB = fmaxf(srm[r2], srm[64 + r2]);

    #pragma unroll
    for (int t = 0; t < 18; t++) {
        int col = col0 + t * 8 + (lane & 3) * 2;
        float q0 = 0.f, q1 = 0.f, q2 = 0.f, q3 = 0.f;
        if (col < MDIM) {
            q0 = RATIO * (__expf(C[t][0] - d1 - rmA) + EPSV);
            q1 = RATIO * (__expf(C[t][1] - d1 - rmA) + EPSV);
            q2 = RATIO * (__expf(C[t][2] - d2 - rmB) + EPSV);
            q3 = RATIO * (__expf(C[t][3] - d2 - rmB) + EPSV);
        }
        uint32_t lw, hw;
        hw = bpack(q0, q1, lw);
        *(uint32_t*)(sm + QPH + r1 * 592 + col * 2) = hw;
        *(uint32_t*)(sm + QPL + r1 * 592 + col * 2) = lw;
        hw = bpack(q2, q3, lw);
        *(uint32_t*)(sm + QPH + r2 * 592 + col * 2) = hw;
        *(uint32_t*)(sm + QPL + r2 * 592 + col * 2) = lw;
    }
    {
        const uint4* s0 = (const uint4*)(g_ctxB0 + (size_t)bh * 23040);
        const uint4* s1 = (const uint4*)(g_ctxB1 + (size_t)bh * 23040);
        for (int i = tid; i < 2880; i += 256) {
            int rr = i / 36, kk = i % 36;
            *(uint4*)(sm + CTH + rr * 592 + kk * 16) = s0[i];
            *(uint4*)(sm + CTL + rr * 592 + kk * 16) = s1[i];
        }
    }
    __syncthreads();

    float C2[6][4] = {};
    if (cw == 0)
        wgemm<3, 18>(C2, sb + QPH + row0 * 592, sb + QPL + row0 * 592, 592,
                     sb + CTH, sb + CTL, 592, lane);
    else
        wgemm<2, 18>(C2, sb + QPH + row0 * 592, sb + QPL + row0 * 592, 592,
                     sb + CTH + 48 * 592, sb + CTL + 48 * 592, 592, lane);

    if (cw == 1 && (lane & 3) == 0) {
        srm[r1] = C2[2][0];
        srm[r2] = C2[2][2];
    }
    __syncthreads();
    const float i1 = 1.f / srm[r1], i2 = 1.f / srm[r2];
    float* ob = out + (size_t)(bh * NSEQ + nt * 64) * 64;
    const int c2o = cw * 48;
    const int nst = cw ? 2 : 6;
    for (int t = 0; t < nst; t++) {
        int col = c2o + t * 8 + (lane & 3) * 2;
        *(float2*)(ob + (size_t)r1 * 64 + col) = make_float2(C2[t][0] * i1, C2[t][1] * i1);
        *(float2*)(ob + (size_t)r2 * 64 + col) = make_float2(C2[t][2] * i2, C2[t][3] * i2);
    }
}

// ---------------------------------------------------------------------------
extern "C" void kernel_launch(void* const* d_in, const int* in_sizes, int n_in,
                              void* d_out, int out_size) {
    const float* q    = (const float*)d_in[0];
    const float* k    = (const float*)d_in[1];
    const float* v    = (const float*)d_in[2];
    const float* proj = (const float*)d_in[3];
    float* out = (float*)d_out;

    cudaFuncSetAttribute(pass1max, cudaFuncAttributeMaxDynamicSharedMemorySize, SMEM1M);
    cudaFuncSetAttribute(pass2a, cudaFuncAttributeMaxDynamicSharedMemorySize, SMEM2);
    cudaFuncSetAttribute(pass3, cudaFuncAttributeMaxDynamicSharedMemorySize, SMEM3);

    prep<<<80, 256>>>(proj);
    pass1max<<<BHN * 256, 256, SMEM1M>>>(k);
    pass2a<<<BHN * NSPL, 320, SMEM2>>>(k, v);
    pass2b<<<(BHN * 288 * 80 + 255) / 256, 256>>>();
    pass3<<<BHN * 256, 256, SMEM3>>>(q, out);
}

// round 11
// speedup vs baseline: 1.9889x; 1.0780x over previous
#include <cuda_runtime.h>
#include <cuda_bf16.h>
#include <math_constants.h>
#include <cstdint>

// B=2,H=8 -> BHN=16; N=16384; D=64; M=266 (pad 288/320)
#define BHN  16
#define NSEQ 16384
#define MDIM 266
#define NSPL 32
#define SSCALE 0.51011868f    // 64^-0.25 * log2(e)
#define DIAGF  0.34657359f    // 0.5 * ln(2)  (log2-domain diag from SSCALE-scaled rows)
#define EPSV   1e-4f

__device__ float g_headmax[BHN];
__device__ __align__(16) float g_ctx_part[(size_t)BHN * NSPL * 320 * 80];
__device__ __align__(16) unsigned short g_projB0[320 * 72];
__device__ __align__(16) unsigned short g_projB1[320 * 72];
__device__ __align__(16) unsigned short g_ctxB0[BHN * 80 * 288];
__device__ __align__(16) unsigned short g_ctxB1[BHN * 80 * 288];

// ---- smem offsets: pass1max / pass3 ----
#define XH 0u
#define XL 9216u
#define PH 18432u
#define PL 59904u
#define P_SWM  101376u
#define SMEM1M 101408u
#define QPH 0u
#define QPL 37888u
#define CTH 75776u
#define CTL 123136u
#define Q_DIAG 170496u
#define Q_SRM  170752u
#define SMEM3  171264u
// ---- pass2a ----
#define PH2   0u
#define PL2   46080u
#define KH2   92160u
#define KL2   134144u
#define VH2   176128u
#define VL2   187392u
#define XH2   198656u
#define XL2   207872u
#define DIAG2 217088u
#define SMEM2 217344u
#define SA 656
#define SB 176

__device__ __forceinline__ uint32_t smem_u32(const void* p) {
    uint32_t a;
    asm("{ .reg .u64 t; cvta.to.shared.u64 t, %1; cvt.u32.u64 %0, t; }" : "=r"(a) : "l"(p));
    return a;
}
__device__ __forceinline__ void ldm4(uint32_t f[4], uint32_t a) {
    asm volatile("ldmatrix.sync.aligned.m8n8.x4.shared.b16 {%0,%1,%2,%3}, [%4];"
        : "=r"(f[0]), "=r"(f[1]), "=r"(f[2]), "=r"(f[3]) : "r"(a));
}
__device__ __forceinline__ void ldm4t(uint32_t f[4], uint32_t a) {
    asm volatile("ldmatrix.sync.aligned.m8n8.x4.trans.shared.b16 {%0,%1,%2,%3}, [%4];"
        : "=r"(f[0]), "=r"(f[1]), "=r"(f[2]), "=r"(f[3]) : "r"(a));
}
__device__ __forceinline__ void mma16816(float c[4], const uint32_t a[4],
                                         uint32_t b0, uint32_t b1) {
    asm volatile("mma.sync.aligned.m16n8k16.row.col.f32.bf16.bf16.f32 "
        "{%0,%1,%2,%3},{%4,%5,%6,%7},{%8,%9},{%0,%1,%2,%3};"
        : "+f"(c[0]), "+f"(c[1]), "+f"(c[2]), "+f"(c[3])
        : "r"(a[0]), "r"(a[1]), "r"(a[2]), "r"(a[3]), "r"(b0), "r"(b1));
}
__device__ __forceinline__ float ex2f(float x) {
    float r;
    asm("ex2.approx.f32 %0, %1;" : "=f"(r) : "f"(x));
    return r;
}

// hi/lo 3-product warp GEMM (non-trans)
template <int NTP, int KS>
__device__ __forceinline__ void wgemm(float C[][4], uint32_t aH, uint32_t aL, int ldaB,
                                      uint32_t bH, uint32_t bL, int ldbB, int lane) {
    const uint32_t ao = (uint32_t)(lane & 15) * ldaB + (uint32_t)(lane >> 4) * 16;
    const uint32_t bo = (uint32_t)(lane & 15) * ldbB + (uint32_t)(lane >> 4) * 16;
    for (int ks = 0; ks < KS; ks++) {
        uint32_t ah[4], al[4];
        ldm4(ah, aH + ao + ks * 32);
        ldm4(al, aL + ao + ks * 32);
        #pragma unroll
        for (int tp = 0; tp < NTP; tp++) {
            uint32_t bh[4], bl[4];
            ldm4(bh, bH + bo + tp * 16 * ldbB + ks * 32);
            ldm4(bl, bL + bo + tp * 16 * ldbB + ks * 32);
            mma16816(C[2 * tp], ah, bh[0], bh[2]);
            mma16816(C[2 * tp], ah, bl[0], bl[2]);
            mma16816(C[2 * tp], al, bh[0], bh[2]);
            mma16816(C[2 * tp + 1], ah, bh[1], bh[3]);
            mma16816(C[2 * tp + 1], ah, bl[1], bl[3]);
            mma16816(C[2 * tp + 1], al, bh[1], bh[3]);
        }
    }
}

// fast split: hi = truncation (packed via PRMT), lo = RN(x - hi) packed cvt
__device__ __forceinline__ uint32_t bpack2(float a, float b, uint32_t& lo) {
    uint32_t ia = __float_as_uint(a), ib = __float_as_uint(b);
    uint32_t hi = __byte_perm(ia, ib, 0x7632);
    float la = a - __uint_as_float(ia & 0xffff0000u);
    float lb = b - __uint_as_float(ib & 0xffff0000u);
    __nv_bfloat162 t = __floats2bfloat162_rn(la, lb);
    lo = *reinterpret_cast<uint32_t*>(&t);
    return hi;
}
__device__ __forceinline__ void atomicMaxFloat(float* addr, float val) {
    int* ai = (int*)addr;
    int old = *ai;
    while (__int_as_float(old) < val) {
        int prev = atomicCAS(ai, old, __float_as_int(val));
        if (prev == old) return;
        old = prev;
    }
}

// stage 64x64 fp32 -> scaled bf16 hi/lo [64][72] (+optional diag). tid < 256.
__device__ __forceinline__ void stage_x(const float* __restrict__ src, uint8_t* sm,
                                        uint32_t offH, uint32_t offL, float* diag, int tid) {
    const int r = tid >> 2, c0 = (tid & 3) * 16;
    const float4* p = (const float4*)(src + (size_t)r * 64 + c0);
    uint32_t h[8], l[8];
    float sq = 0.f;
    #pragma unroll
    for (int j = 0; j < 4; j++) {
        float4 t = p[j];
        float v[4] = {t.x * SSCALE, t.y * SSCALE, t.z * SSCALE, t.w * SSCALE};
        h[j * 2]     = bpack2(v[0], v[1], l[j * 2]);
        h[j * 2 + 1] = bpack2(v[2], v[3], l[j * 2 + 1]);
        sq = fmaf(v[0], v[0], fmaf(v[1], v[1], fmaf(v[2], v[2], fmaf(v[3], v[3], sq))));
    }
    uint32_t ba = (uint32_t)r * 144 + (uint32_t)c0 * 2;
    *(uint4*)(sm + offH + ba)      = make_uint4(h[0], h[1], h[2], h[3]);
    *(uint4*)(sm + offH + ba + 16) = make_uint4(h[4], h[5], h[6], h[7]);
    *(uint4*)(sm + offL + ba)      = make_uint4(l[0], l[1], l[2], l[3]);
    *(uint4*)(sm + offL + ba + 16) = make_uint4(l[4], l[5], l[6], l[7]);
    if (diag) {
        sq += __shfl_xor_sync(~0u, sq, 1);
        sq += __shfl_xor_sync(~0u, sq, 2);
        if ((tid & 3) == 0) diag[r] = DIAGF * sq;
    }
}

__global__ void prep(const float* __restrict__ proj) {
    int gid = blockIdx.x * 256 + threadIdx.x;   // 320*64
    int r = gid >> 6, c = gid & 63;
    float v = (r < MDIM) ? proj[r * 64 + c] : 0.f;
    uint32_t ib = __float_as_uint(v);
    g_projB0[r * 72 + c] = (unsigned short)(ib >> 16);
    float lv = v - __uint_as_float(ib & 0xffff0000u);
    g_projB1[r * 72 + c] = __bfloat16_as_ushort(__float2bfloat16(lv));
    if (gid < BHN) g_headmax[gid] = -CUDART_INF_F;
}

// ---------------------------------------------------------------------------
// pass1max: per-head max of dd (log2 domain), exact 3-product GEMM. 16*256.
// ---------------------------------------------------------------------------
__global__ __launch_bounds__(256) void pass1max(const float* __restrict__ kin) {
    extern __shared__ __align__(16) uint8_t sm[];
    uint32_t sb = smem_u32(sm);
    float* swm = (float*)(sm + P_SWM);
    const int tid = threadIdx.x, w = tid >> 5, lane = tid & 31;
    const int bh = blockIdx.x >> 8, nt = blockIdx.x & 255;
    const int row0 = (w >> 1) * 16, col0 = (w & 1) * 144;

    for (int i = tid; i < 2592; i += 256) {
        ((uint4*)(sm + PH))[i] = ((const uint4*)g_projB0)[i];
        ((uint4*)(sm + PL))[i] = ((const uint4*)g_projB1)[i];
    }
    stage_x(kin + (size_t)(bh * NSEQ + nt * 64) * 64, sm, XH, XL, nullptr, tid);
    __syncthreads();

    float C[18][4] = {};
    wgemm<9, 4>(C, sb + XH + row0 * 144, sb + XL + row0 * 144, 144,
                sb + PH + col0 * 144, sb + PL + col0 * 144, 144, lane);

    float tmax = -CUDART_INF_F;   // pads give dd=0; true per-head max > 0
    #pragma unroll
    for (int t = 0; t < 18; t++)
        tmax = fmaxf(tmax, fmaxf(fmaxf(C[t][0], C[t][1]), fmaxf(C[t][2], C[t][3])));
    #pragma unroll
    for (int o = 16; o; o >>= 1) tmax = fmaxf(tmax, __shfl_xor_sync(~0u, tmax, o));
    if (lane == 0) swm[w] = tmax;
    __syncthreads();
    if (tid == 0) {
        float m = swm[0];
        #pragma unroll
        for (int i = 1; i < 8; i++) m = fmaxf(m, swm[i]);
        atomicMaxFloat(&g_headmax[bh], m);
    }
}

// ---------------------------------------------------------------------------
// pass2a: recompute dd (3-product), ex2->kp, GEMM2 context (+ksum col 64).
// grid = 16*NSPL, 320 threads.
// ---------------------------------------------------------------------------
__global__ __launch_bounds__(320) void pass2a(const float* __restrict__ kin,
                                              const float* __restrict__ vin) {
    extern __shared__ __align__(16) uint8_t sm[];
    uint32_t sb = smem_u32(sm);
    float* diag = (float*)(sm + DIAG2);
    const int tid = threadIdx.x, w = tid >> 5, lane = tid & 31;
    const int bh = blockIdx.x >> 5, split = blockIdx.x & 31;
    const float stab = g_headmax[bh];
    const int m0w = w * 32;

    for (int i = tid; i < 2880; i += 320) {
        ((uint4*)(sm + PH2))[i] = ((const uint4*)g_projB0)[i];
        ((uint4*)(sm + PL2))[i] = ((const uint4*)g_projB1)[i];
    }
    for (int i = tid; i < 64 * 12; i += 320) {
        int n = i / 12, c = i % 12;
        *(uint32_t*)(sm + VH2 + n * SB + 128 + c * 4) = (c == 0) ? 0x3F80u : 0u;
        *(uint32_t*)(sm + VL2 + n * SB + 128 + c * 4) = 0u;
    }

    const uint32_t ao1 = (uint32_t)(lane & 15) * 144u + (uint32_t)(lane >> 4) * 16u;
    const uint32_t lo_ = ((uint32_t)(lane & 7) + (uint32_t)((lane >> 4) & 1) * 8);
    const uint32_t aoff = lo_ * SA + (uint32_t)((lane >> 3) & 1) * 16;
    const uint32_t boff = lo_ * SB + (uint32_t)((lane >> 3) & 1) * 16;
    const int lr = lane >> 2, lc = (lane & 3) * 2;

    float C[2][10][4] = {};
    for (int t = 0; t < 8; t++) {
        const size_t n0 = (size_t)bh * NSEQ + (size_t)split * 512 + t * 64;
        __syncthreads();
        if (tid < 256)
            stage_x(kin + n0 * 64, sm, XH2, XL2, diag, tid);
        for (int i = tid; i < 64 * 32; i += 320) {
            int n = i >> 5, dp = i & 31;
            float2 vv = *(const float2*)&vin[(n0 + n) * 64 + dp * 2];
            uint32_t lw, hw = bpack2(vv.x, vv.y, lw);
            *(uint32_t*)(sm + VH2 + n * SB + dp * 4) = hw;
            *(uint32_t*)(sm + VL2 + n * SB + dp * 4) = lw;
        }
        __syncthreads();

        float C1[4][4][4] = {};
        for (int ks = 0; ks < 4; ks++) {
            uint32_t pbh[2][4], pbl[2][4];
            #pragma unroll
            for (int tp = 0; tp < 2; tp++) {
                ldm4(pbh[tp], sb + PH2 + (m0w + tp * 16) * 144 + ao1 + ks * 32);
                ldm4(pbl[tp], sb + PL2 + (m0w + tp * 16) * 144 + ao1 + ks * 32);
            }
            #pragma unroll
            for (int rt = 0; rt < 4; rt++) {
                uint32_t ah[4], al[4];
                ldm4(ah, sb + XH2 + rt * 16 * 144 + ao1 + ks * 32);
                ldm4(al, sb + XL2 + rt * 16 * 144 + ao1 + ks * 32);
                #pragma unroll
                for (int tp = 0; tp < 2; tp++) {
                    mma16816(C1[rt][2 * tp], ah, pbh[tp][0], pbh[tp][2]);
                    mma16816(C1[rt][2 * tp], ah, pbl[tp][0], pbl[tp][2]);
                    mma16816(C1[rt][2 * tp], al, pbh[tp][0], pbh[tp][2]);
                    mma16816(C1[rt][2 * tp + 1], ah, pbh[tp][1], pbh[tp][3]);
                    mma16816(C1[rt][2 * tp + 1], ah, pbl[tp][1], pbl[tp][3]);
                    mma16816(C1[rt][2 * tp + 1], al, pbh[tp][1], pbh[tp][3]);
                }
            }
        }
        // kp = ex2(dd - diag - stab) + EPS   (pads harmless: qp=0 downstream)
        #pragma unroll
        for (int rt = 0; rt < 4; rt++) {
            int r1 = rt * 16 + lr, r2 = r1 + 8;
            float sA = diag[r1] + stab, sB = diag[r2] + stab;
            #pragma unroll
            for (int t8 = 0; t8 < 4; t8++) {
                int m = m0w + t8 * 8 + lc;
                float k0 = ex2f(C1[rt][t8][0] - sA) + EPSV;
                float k1 = ex2f(C1[rt][t8][1] - sA) + EPSV;
                float k2 = ex2f(C1[rt][t8][2] - sB) + EPSV;
                float k3 = ex2f(C1[rt][t8][3] - sB) + EPSV;
                uint32_t lw, hw;
                hw = bpack2(k0, k1, lw);
                *(uint32_t*)(sm + KH2 + r1 * SA + m * 2) = hw;
                *(uint32_t*)(sm + KL2 + r1 * SA + m * 2) = lw;
                hw = bpack2(k2, k3, lw);
                *(uint32_t*)(sm + KH2 + r2 * SA + m * 2) = hw;
                *(uint32_t*)(sm + KL2 + r2 * SA + m * 2) = lw;
            }
        }
        __syncthreads();

        for (int ks = 0; ks < 4; ks++) {
            uint32_t bh4[5][4], bl4[5][4];
            #pragma unroll
            for (int tp = 0; tp < 5; tp++) {
                ldm4t(bh4[tp], sb + VH2 + boff + ks * 16 * SB + tp * 32);
                ldm4t(bl4[tp], sb + VL2 + boff + ks * 16 * SB + tp * 32);
            }
            #pragma unroll
            for (int rt = 0; rt < 2; rt++) {
                uint32_t ah[4], al[4];
                ldm4t(ah, sb + KH2 + aoff + ks * 16 * SA + (m0w + rt * 16) * 2);
                ldm4t(al, sb + KL2 + aoff + ks * 16 * SA + (m0w + rt * 16) * 2);
                #pragma unroll
                for (int tp = 0; tp < 5; tp++) {
                    mma16816(C[rt][2 * tp], ah, bh4[tp][0], bh4[tp][2]);
                    mma16816(C[rt][2 * tp], ah, bl4[tp][0], bl4[tp][2]);
                    mma16816(C[rt][2 * tp], al, bh4[tp][0], bh4[tp][2]);
                    mma16816(C[rt][2 * tp + 1], ah, bh4[tp][1], bh4[tp][3]);
                    mma16816(C[rt][2 * tp + 1], ah, bl4[tp][1], bl4[tp][3]);
                    mma16816(C[rt][2 * tp + 1], al, bh4[tp][1], bh4[tp][3]);
                }
            }
        }
    }
    float* pb = g_ctx_part + (size_t)(bh * NSPL + split) * (320 * 80);
    #pragma unroll
    for (int rt = 0; rt < 2; rt++) {
        int r1 = m0w + rt * 16 + lr, r2 = r1 + 8;
        #pragma unroll
        for (int tp = 0; tp < 5; tp++) {
            int col = tp * 16 + lc;
            *(float2*)(pb + (size_t)r1 * 80 + col)     = make_float2(C[rt][2 * tp][0], C[rt][2 * tp][1]);
            *(float2*)(pb + (size_t)r2 * 80 + col)     = make_float2(C[rt][2 * tp][2], C[rt][2 * tp][3]);
            *(float2*)(pb + (size_t)r1 * 80 + col + 8) = make_float2(C[rt][2 * tp + 1][0], C[rt][2 * tp + 1][1]);
            *(float2*)(pb + (size_t)r2 * 80 + col + 8) = make_float2(C[rt][2 * tp + 1][2], C[rt][2 * tp + 1][3]);
        }
    }
}

// ---------------------------------------------------------------------------
// pass2b: reduce splits; emit bf16 hi/lo ctx^T [bh][80][288].
// ---------------------------------------------------------------------------
__global__ __launch_bounds__(256) void pass2b() {
    int gid = blockIdx.x * 256 + threadIdx.x;
    if (gid >= BHN * 288 * 80) return;
    int bh = gid / (288 * 80);
    int rem = gid % (288 * 80);
    int m = rem / 80, d = rem % 80;
    float s = 0.f;
    #pragma unroll
    for (int sp = 0; sp < NSPL; sp++)
        s += g_ctx_part[((size_t)(bh * NSPL + sp) * 320 + m) * 80 + d];
    uint32_t ib = __float_as_uint(s);
    g_ctxB0[(size_t)bh * 23040 + d * 288 + m] = (unsigned short)(ib >> 16);
    float lv = s - __uint_as_float(ib & 0xffff0000u);
    g_ctxB1[(size_t)bh * 23040 + d * 288 + m] = __bfloat16_as_ushort(__float2bfloat16(lv));
}

// ---------------------------------------------------------------------------
// pass3: fused q side. GEMM1 -> rowmax -> ex2 -> GEMM2 (denom = col 64).
// ---------------------------------------------------------------------------
__global__ __launch_bounds__(256) void pass3(const float* __restrict__ qin,
                                             float* __restrict__ out) {
    extern __shared__ __align__(16) uint8_t sm[];
    uint32_t sb = smem_u32(sm);
    float* diag = (float*)(sm + Q_DIAG);
    float* srm = (float*)(sm + Q_SRM);
    const int tid = threadIdx.x, w = tid >> 5, lane = tid & 31;
    const int bh = blockIdx.x >> 8, nt = blockIdx.x & 255;
    const int row0 = (w >> 1) * 16, cw = w & 1, col0 = cw * 144;

    for (int i = tid; i < 2592; i += 256) {
        ((uint4*)(sm + PH))[i] = ((const uint4*)g_projB0)[i];
        ((uint4*)(sm + PL))[i] = ((const uint4*)g_projB1)[i];
    }
    stage_x(qin + (size_t)(bh * NSEQ + nt * 64) * 64, sm, XH, XL, diag, tid);
    __syncthreads();

    float C[18][4] = {};
    wgemm<9, 4>(C, sb + XH + row0 * 144, sb + XL + row0 * 144, 144,
                sb + PH + col0 * 144, sb + PL + col0 * 144, 144, lane);

    const int r1 = row0 + (lane >> 2), r2 = r1 + 8;
    const float d1 = diag[r1], d2 = diag[r2];
    float m1 = -CUDART_INF_F, m2 = -CUDART_INF_F;
    #pragma unroll
    for (int t = 0; t < 18; t++) {
        int col = col0 + t * 8 + (lane & 3) * 2;
        if (col < MDIM) {
            m1 = fmaxf(m1, fmaxf(C[t][0], C[t][1]));
            m2 = fmaxf(m2, fmaxf(C[t][2], C[t][3]));
        }
    }
    m1 = fmaxf(m1, __shfl_xor_sync(~0u, m1, 1));
    m1 = fmaxf(m1, __shfl_xor_sync(~0u, m1, 2));
    m2 = fmaxf(m2, __shfl_xor_sync(~0u, m2, 1));
    m2 = fmaxf(m2, __shfl_xor_sync(~0u, m2, 2));
    if ((lane & 3) == 0) {
        srm[cw * 64 + r1] = m1;
        srm[cw * 64 + r2] = m2;
    }
    __syncthreads();
    const float sA = d1 + fmaxf(srm[r1], srm[64 + r1]);
    const float sB = d2 + fmaxf(srm[r2], srm[64 + r2]);

    #pragma unroll
    for (int t = 0; t < 18; t++) {
        int col = col0 + t * 8 + (lane & 3) * 2;
        float q0 = 0.f, q1 = 0.f, q2 = 0.f, q3 = 0.f;
        if (col < MDIM) {
            q0 = ex2f(C[t][0] - sA) + EPSV;
            q1 = ex2f(C[t][1] - sA) + EPSV;
            q2 = ex2f(C[t][2] - sB) + EPSV;
            q3 = ex2f(C[t][3] - sB) + EPSV;
        }
        uint32_t lw, hw;
        hw = bpack2(q0, q1, lw);
        *(uint32_t*)(sm + QPH + r1 * 592 + col * 2) = hw;
        *(uint32_t*)(sm + QPL + r1 * 592 + col * 2) = lw;
        hw = bpack2(q2, q3, lw);
        *(uint32_t*)(sm + QPH + r2 * 592 + col * 2) = hw;
        *(uint32_t*)(sm + QPL + r2 * 592 + col * 2) = lw;
    }
    {
        const uint4* s0 = (const uint4*)(g_ctxB0 + (size_t)bh * 23040);
        const uint4* s1 = (const uint4*)(g_ctxB1 + (size_t)bh * 23040);
        for (int i = tid; i < 2880; i += 256) {
            int rr = i / 36, kk = i % 36;
            *(uint4*)(sm + CTH + rr * 592 + kk * 16) = s0[i];
            *(uint4*)(sm + CTL + rr * 592 + kk * 16) = s1[i];
        }
    }
    __syncthreads();

    float C2[6][4] = {};
    if (cw == 0)
        wgemm<3, 18>(C2, sb + QPH + row0 * 592, sb + QPL + row0 * 592, 592,
                     sb + CTH, sb + CTL, 592, lane);
    else
        wgemm<2, 18>(C2, sb + QPH + row0 * 592, sb + QPL + row0 * 592, 592,
                     sb + CTH + 48 * 592, sb + CTL + 48 * 592, 592, lane);

    if (cw == 1 && (lane & 3) == 0) {
        srm[r1] = C2[2][0];
        srm[r2] = C2[2][2];
    }
    __syncthreads();
    const float i1 = 1.f / srm[r1], i2 = 1.f / srm[r2];
    float* ob = out + (size_t)(bh * NSEQ + nt * 64) * 64;
    const int c2o = cw * 48;
    const int nst = cw ? 2 : 6;
    for (int t = 0; t < nst; t++) {
        int col = c2o + t * 8 + (lane & 3) * 2;
        *(float2*)(ob + (size_t)r1 * 64 + col) = make_float2(C2[t][0] * i1, C2[t][1] * i1);
        *(float2*)(ob + (size_t)r2 * 64 + col) = make_float2(C2[t][2] * i2, C2[t][3] * i2);
    }
}

// ---------------------------------------------------------------------------
extern "C" void kernel_launch(void* const* d_in, const int* in_sizes, int n_in,
                              void* d_out, int out_size) {
    const float* q    = (const float*)d_in[0];
    const float* k    = (const float*)d_in[1];
    const float* v    = (const float*)d_in[2];
    const float* proj = (const float*)d_in[3];
    float* out = (float*)d_out;

    cudaFuncSetAttribute(pass1max, cudaFuncAttributeMaxDynamicSharedMemorySize, SMEM1M);
    cudaFuncSetAttribute(pass2a, cudaFuncAttributeMaxDynamicSharedMemorySize, SMEM2);
    cudaFuncSetAttribute(pass3, cudaFuncAttributeMaxDynamicSharedMemorySize, SMEM3);

    prep<<<80, 256>>>(proj);
    pass1max<<<BHN * 256, 256, SMEM1M>>>(k);
    pass2a<<<BHN * NSPL, 320, SMEM2>>>(k, v);
    pass2b<<<(BHN * 288 * 80 + 255) / 256, 256>>>();
    pass3<<<BHN * 256, 256, SMEM3>>>(q, out);
}

// round 12
// speedup vs baseline: 2.1866x; 1.0994x over previous
#include <cuda_runtime.h>
#include <cuda_bf16.h>
#include <math_constants.h>
#include <cstdint>

// B=2,H=8 -> BHN=16; N=16384; D=64; M=266 (pad 288/320)
#define BHN  16
#define NSEQ 16384
#define MDIM 266
#define NSPL 32
#define SSCALE 0.51011868f    // 64^-0.25 * log2(e)
#define DIAGF  0.34657359f    // 0.5 * ln(2)  (log2-domain diag from SSCALE-scaled rows)
#define EPSV   1e-4f

__device__ float g_headmax[BHN];
__device__ __align__(16) float g_ctx_part[(size_t)BHN * NSPL * 320 * 80];
__device__ __align__(16) unsigned short g_projB0[320 * 72];
__device__ __align__(16) unsigned short g_projB1[320 * 72];
__device__ __align__(16) unsigned short g_ctxB0[BHN * 80 * 288];
__device__ __align__(16) unsigned short g_ctxB1[BHN * 80 * 288];

// ---- smem offsets: pass3 ----
#define XH 0u
#define XL 9216u
#define PH 18432u
#define PL 59904u
#define QPH 0u
#define QPL 37888u
#define CTH 75776u
#define CTL 123136u
#define Q_DIAG 170496u
#define Q_SRM  170752u
#define SMEM3  171264u
// ---- pass2a ----
#define PH2   0u
#define PL2   46080u
#define KH2   92160u
#define KL2   134144u
#define VH2   176128u
#define VL2   187392u
#define XH2   198656u
#define XL2   207872u
#define DIAG2 217088u
#define SWM2  217344u
#define SMEM2 217408u
#define SA 656
#define SB 176

__device__ __forceinline__ uint32_t smem_u32(const void* p) {
    uint32_t a;
    asm("{ .reg .u64 t; cvta.to.shared.u64 t, %1; cvt.u32.u64 %0, t; }" : "=r"(a) : "l"(p));
    return a;
}
__device__ __forceinline__ void ldm4(uint32_t f[4], uint32_t a) {
    asm volatile("ldmatrix.sync.aligned.m8n8.x4.shared.b16 {%0,%1,%2,%3}, [%4];"
        : "=r"(f[0]), "=r"(f[1]), "=r"(f[2]), "=r"(f[3]) : "r"(a));
}
__device__ __forceinline__ void ldm4t(uint32_t f[4], uint32_t a) {
    asm volatile("ldmatrix.sync.aligned.m8n8.x4.trans.shared.b16 {%0,%1,%2,%3}, [%4];"
        : "=r"(f[0]), "=r"(f[1]), "=r"(f[2]), "=r"(f[3]) : "r"(a));
}
__device__ __forceinline__ void mma16816(float c[4], const uint32_t a[4],
                                         uint32_t b0, uint32_t b1) {
    asm volatile("mma.sync.aligned.m16n8k16.row.col.f32.bf16.bf16.f32 "
        "{%0,%1,%2,%3},{%4,%5,%6,%7},{%8,%9},{%0,%1,%2,%3};"
        : "+f"(c[0]), "+f"(c[1]), "+f"(c[2]), "+f"(c[3])
        : "r"(a[0]), "r"(a[1]), "r"(a[2]), "r"(a[3]), "r"(b0), "r"(b1));
}
__device__ __forceinline__ float ex2f(float x) {
    float r;
    asm("ex2.approx.f32 %0, %1;" : "=f"(r) : "f"(x));
    return r;
}

// hi/lo 3-product warp GEMM (non-trans; pass3)
template <int NTP, int KS>
__device__ __forceinline__ void wgemm(float C[][4], uint32_t aH, uint32_t aL, int ldaB,
                                      uint32_t bH, uint32_t bL, int ldbB, int lane) {
    const uint32_t ao = (uint32_t)(lane & 15) * ldaB + (uint32_t)(lane >> 4) * 16;
    const uint32_t bo = (uint32_t)(lane & 15) * ldbB + (uint32_t)(lane >> 4) * 16;
    for (int ks = 0; ks < KS; ks++) {
        uint32_t ah[4], al[4];
        ldm4(ah, aH + ao + ks * 32);
        ldm4(al, aL + ao + ks * 32);
        #pragma unroll
        for (int tp = 0; tp < NTP; tp++) {
            uint32_t bh[4], bl[4];
            ldm4(bh, bH + bo + tp * 16 * ldbB + ks * 32);
            ldm4(bl, bL + bo + tp * 16 * ldbB + ks * 32);
            mma16816(C[2 * tp], ah, bh[0], bh[2]);
            mma16816(C[2 * tp], ah, bl[0], bl[2]);
            mma16816(C[2 * tp], al, bh[0], bh[2]);
            mma16816(C[2 * tp + 1], ah, bh[1], bh[3]);
            mma16816(C[2 * tp + 1], ah, bl[1], bl[3]);
            mma16816(C[2 * tp + 1], al, bh[1], bh[3]);
        }
    }
}

// fast split: hi = truncation (packed via PRMT), lo = RN(x - hi) packed cvt
__device__ __forceinline__ uint32_t bpack2(float a, float b, uint32_t& lo) {
    uint32_t ia = __float_as_uint(a), ib = __float_as_uint(b);
    uint32_t hi = __byte_perm(ia, ib, 0x7632);
    float la = a - __uint_as_float(ia & 0xffff0000u);
    float lb = b - __uint_as_float(ib & 0xffff0000u);
    __nv_bfloat162 t = __floats2bfloat162_rn(la, lb);
    lo = *reinterpret_cast<uint32_t*>(&t);
    return hi;
}
__device__ __forceinline__ void atomicMaxFloat(float* addr, float val) {
    int* ai = (int*)addr;
    int old = *ai;
    while (__int_as_float(old) < val) {
        int prev = atomicCAS(ai, old, __float_as_int(val));
        if (prev == old) return;
        old = prev;
    }
}

// stage 64x64 fp32 -> scaled bf16 hi/lo [64][72] (+optional diag). tid < 256.
__device__ __forceinline__ void stage_x(const float* __restrict__ src, uint8_t* sm,
                                        uint32_t offH, uint32_t offL, float* diag, int tid) {
    const int r = tid >> 2, c0 = (tid & 3) * 16;
    const float4* p = (const float4*)(src + (size_t)r * 64 + c0);
    uint32_t h[8], l[8];
    float sq = 0.f;
    #pragma unroll
    for (int j = 0; j < 4; j++) {
        float4 t = p[j];
        float v[4] = {t.x * SSCALE, t.y * SSCALE, t.z * SSCALE, t.w * SSCALE};
        h[j * 2]     = bpack2(v[0], v[1], l[j * 2]);
        h[j * 2 + 1] = bpack2(v[2], v[3], l[j * 2 + 1]);
        sq = fmaf(v[0], v[0], fmaf(v[1], v[1], fmaf(v[2], v[2], fmaf(v[3], v[3], sq))));
    }
    uint32_t ba = (uint32_t)r * 144 + (uint32_t)c0 * 2;
    *(uint4*)(sm + offH + ba)      = make_uint4(h[0], h[1], h[2], h[3]);
    *(uint4*)(sm + offH + ba + 16) = make_uint4(h[4], h[5], h[6], h[7]);
    *(uint4*)(sm + offL + ba)      = make_uint4(l[0], l[1], l[2], l[3]);
    *(uint4*)(sm + offL + ba + 16) = make_uint4(l[4], l[5], l[6], l[7]);
    if (diag) {
        sq += __shfl_xor_sync(~0u, sq, 1);
        sq += __shfl_xor_sync(~0u, sq, 2);
        if ((tid & 3) == 0) diag[r] = DIAGF * sq;
    }
}

__global__ void prep(const float* __restrict__ proj) {
    int gid = blockIdx.x * 256 + threadIdx.x;   // 320*64
    int r = gid >> 6, c = gid & 63;
    float v = (r < MDIM) ? proj[r * 64 + c] : 0.f;
    uint32_t ib = __float_as_uint(v);
    g_projB0[r * 72 + c] = (unsigned short)(ib >> 16);
    float lv = v - __uint_as_float(ib & 0xffff0000u);
    g_projB1[r * 72 + c] = __bfloat16_as_ushort(__float2bfloat16(lv));
    if (gid < BHN) g_headmax[gid] = -CUDART_INF_F;
}

// ---------------------------------------------------------------------------
// pass2a: dd via 3-product GEMM1; per-head max of dd (atomicMax);
// kpE = 2^(dd - diag) (NO stab/EPS); GEMM2 ctxE (+ksum col 64, +Vsum row 288).
// grid = 16*NSPL, 320 threads.
// ---------------------------------------------------------------------------
__global__ __launch_bounds__(320) void pass2a(const float* __restrict__ kin,
                                              const float* __restrict__ vin) {
    extern __shared__ __align__(16) uint8_t sm[];
    uint32_t sb = smem_u32(sm);
    float* diag = (float*)(sm + DIAG2);
    float* swm = (float*)(sm + SWM2);
    const int tid = threadIdx.x, w = tid >> 5, lane = tid & 31;
    const int bh = blockIdx.x >> 5, split = blockIdx.x & 31;
    const int m0w = w * 32;

    for (int i = tid; i < 2880; i += 320) {
        ((uint4*)(sm + PH2))[i] = ((const uint4*)g_projB0)[i];
        ((uint4*)(sm + PL2))[i] = ((const uint4*)g_projB1)[i];
    }
    for (int i = tid; i < 64 * 12; i += 320) {
        int n = i / 12, c = i % 12;
        *(uint32_t*)(sm + VH2 + n * SB + 128 + c * 4) = (c == 0) ? 0x3F80u : 0u;
        *(uint32_t*)(sm + VL2 + n * SB + 128 + c * 4) = 0u;
    }

    const uint32_t ao1 = (uint32_t)(lane & 15) * 144u + (uint32_t)(lane >> 4) * 16u;
    const uint32_t lo_ = ((uint32_t)(lane & 7) + (uint32_t)((lane >> 4) & 1) * 8);
    const uint32_t aoff = lo_ * SA + (uint32_t)((lane >> 3) & 1) * 16;
    const uint32_t boff = lo_ * SB + (uint32_t)((lane >> 3) & 1) * 16;
    const int lr = lane >> 2, lc = (lane & 3) * 2;

    float tmax = -CUDART_INF_F;
    float C[2][10][4] = {};
    for (int t = 0; t < 8; t++) {
        const size_t n0 = (size_t)bh * NSEQ + (size_t)split * 512 + t * 64;
        __syncthreads();
        if (tid < 256)
            stage_x(kin + n0 * 64, sm, XH2, XL2, diag, tid);
        for (int i = tid; i < 64 * 32; i += 320) {
            int n = i >> 5, dp = i & 31;
            float2 vv = *(const float2*)&vin[(n0 + n) * 64 + dp * 2];
            uint32_t lw, hw = bpack2(vv.x, vv.y, lw);
            *(uint32_t*)(sm + VH2 + n * SB + dp * 4) = hw;
            *(uint32_t*)(sm + VL2 + n * SB + dp * 4) = lw;
        }
        __syncthreads();

        float C1[4][4][4] = {};
        for (int ks = 0; ks < 4; ks++) {
            uint32_t pbh[2][4], pbl[2][4];
            #pragma unroll
            for (int tp = 0; tp < 2; tp++) {
                ldm4(pbh[tp], sb + PH2 + (m0w + tp * 16) * 144 + ao1 + ks * 32);
                ldm4(pbl[tp], sb + PL2 + (m0w + tp * 16) * 144 + ao1 + ks * 32);
            }
            #pragma unroll
            for (int rt = 0; rt < 4; rt++) {
                uint32_t ah[4], al[4];
                ldm4(ah, sb + XH2 + rt * 16 * 144 + ao1 + ks * 32);
                ldm4(al, sb + XL2 + rt * 16 * 144 + ao1 + ks * 32);
                #pragma unroll
                for (int tp = 0; tp < 2; tp++) {
                    mma16816(C1[rt][2 * tp], ah, pbh[tp][0], pbh[tp][2]);
                    mma16816(C1[rt][2 * tp], ah, pbl[tp][0], pbl[tp][2]);
                    mma16816(C1[rt][2 * tp], al, pbh[tp][0], pbh[tp][2]);
                    mma16816(C1[rt][2 * tp + 1], ah, pbh[tp][1], pbh[tp][3]);
                    mma16816(C1[rt][2 * tp + 1], ah, pbl[tp][1], pbl[tp][3]);
                    mma16816(C1[rt][2 * tp + 1], al, pbh[tp][1], pbh[tp][3]);
                }
            }
        }
        // kpE = 2^(dd - diag); track max(dd); warp 9 stripe: ones col m=288
        #pragma unroll
        for (int rt = 0; rt < 4; rt++) {
            int r1 = rt * 16 + lr, r2 = r1 + 8;
            float dA = diag[r1], dB = diag[r2];
            #pragma unroll
            for (int t8 = 0; t8 < 4; t8++) {
                int m = m0w + t8 * 8 + lc;
                float k0, k1, k2, k3;
                if (m < 288) {
                    float c0 = C1[rt][t8][0], c1 = C1[rt][t8][1];
                    float c2 = C1[rt][t8][2], c3 = C1[rt][t8][3];
                    tmax = fmaxf(tmax, fmaxf(fmaxf(c0, c1), fmaxf(c2, c3)));
                    k0 = ex2f(c0 - dA);
                    k1 = ex2f(c1 - dA);
                    k2 = ex2f(c2 - dB);
                    k3 = ex2f(c3 - dB);
                } else {
                    float o = (m == 288) ? 1.f : 0.f;
                    k0 = o; k2 = o; k1 = 0.f; k3 = 0.f;
                }
                uint32_t lw, hw;
                hw = bpack2(k0, k1, lw);
                *(uint32_t*)(sm + KH2 + r1 * SA + m * 2) = hw;
                *(uint32_t*)(sm + KL2 + r1 * SA + m * 2) = lw;
                hw = bpack2(k2, k3, lw);
                *(uint32_t*)(sm + KH2 + r2 * SA + m * 2) = hw;
                *(uint32_t*)(sm + KL2 + r2 * SA + m * 2) = lw;
            }
        }
        __syncthreads();

        for (int ks = 0; ks < 4; ks++) {
            uint32_t bh4[5][4], bl4[5][4];
            #pragma unroll
            for (int tp = 0; tp < 5; tp++) {
                ldm4t(bh4[tp], sb + VH2 + boff + ks * 16 * SB + tp * 32);
                ldm4t(bl4[tp], sb + VL2 + boff + ks * 16 * SB + tp * 32);
            }
            #pragma unroll
            for (int rt = 0; rt < 2; rt++) {
                uint32_t ah[4], al[4];
                ldm4t(ah, sb + KH2 + aoff + ks * 16 * SA + (m0w + rt * 16) * 2);
                ldm4t(al, sb + KL2 + aoff + ks * 16 * SA + (m0w + rt * 16) * 2);
                #pragma unroll
                for (int tp = 0; tp < 5; tp++) {
                    mma16816(C[rt][2 * tp], ah, bh4[tp][0], bh4[tp][2]);
                    mma16816(C[rt][2 * tp], ah, bl4[tp][0], bl4[tp][2]);
                    mma16816(C[rt][2 * tp], al, bh4[tp][0], bh4[tp][2]);
                    mma16816(C[rt][2 * tp + 1], ah, bh4[tp][1], bh4[tp][3]);
                    mma16816(C[rt][2 * tp + 1], ah, bl4[tp][1], bl4[tp][3]);
                    mma16816(C[rt][2 * tp + 1], al, bh4[tp][1], bh4[tp][3]);
                }
            }
        }
    }
    // block max -> atomic
    #pragma unroll
    for (int o = 16; o; o >>= 1) tmax = fmaxf(tmax, __shfl_xor_sync(~0u, tmax, o));
    if (lane == 0) swm[w] = tmax;
    __syncthreads();
    if (tid == 0) {
        float m = swm[0];
        #pragma unroll
        for (int i = 1; i < 10; i++) m = fmaxf(m, swm[i]);
        atomicMaxFloat(&g_headmax[bh], m);
    }

    float* pb = g_ctx_part + (size_t)(bh * NSPL + split) * (320 * 80);
    #pragma unroll
    for (int rt = 0; rt < 2; rt++) {
        int r1 = m0w + rt * 16 + lr, r2 = r1 + 8;
        #pragma unroll
        for (int tp = 0; tp < 5; tp++) {
            int col = tp * 16 + lc;
            *(float2*)(pb + (size_t)r1 * 80 + col)     = make_float2(C[rt][2 * tp][0], C[rt][2 * tp][1]);
            *(float2*)(pb + (size_t)r2 * 80 + col)     = make_float2(C[rt][2 * tp][2], C[rt][2 * tp][3]);
            *(float2*)(pb + (size_t)r1 * 80 + col + 8) = make_float2(C[rt][2 * tp + 1][0], C[rt][2 * tp + 1][1]);
            *(float2*)(pb + (size_t)r2 * 80 + col + 8) = make_float2(C[rt][2 * tp + 1][2], C[rt][2 * tp + 1][3]);
        }
    }
}

// ---------------------------------------------------------------------------
// pass2b: ctx = 2^(-stab)*ctxE + EPS*Vsum (row 288 holds Vsum / count);
// reduce splits; emit bf16 hi/lo ctx^T [bh][80][288].
// ---------------------------------------------------------------------------
__global__ __launch_bounds__(256) void pass2b() {
    int gid = blockIdx.x * 256 + threadIdx.x;
    if (gid >= BHN * 288 * 80) return;
    int bh = gid / (288 * 80);
    int rem = gid % (288 * 80);
    int m = rem / 80, d = rem % 80;
    const float scale = ex2f(-g_headmax[bh]);
    const float* base = g_ctx_part + (size_t)bh * NSPL * (320 * 80);
    float s = 0.f, vs = 0.f;
    #pragma unroll
    for (int sp = 0; sp < NSPL; sp++) {
        s  += base[((size_t)sp * 320 + m) * 80 + d];
        vs += base[((size_t)sp * 320 + 288) * 80 + d];
    }
    float f = fmaf(EPSV, vs, scale * s);
    uint32_t ib = __float_as_uint(f);
    g_ctxB0[(size_t)bh * 23040 + d * 288 + m] = (unsigned short)(ib >> 16);
    float lv = f - __uint_as_float(ib & 0xffff0000u);
    g_ctxB1[(size_t)bh * 23040 + d * 288 + m] = __bfloat16_as_ushort(__float2bfloat16(lv));
}

// ---------------------------------------------------------------------------
// pass3: fused q side. GEMM1 -> rowmax -> ex2 -> GEMM2 (denom = col 64).
// ---------------------------------------------------------------------------
__global__ __launch_bounds__(256) void pass3(const float* __restrict__ qin,
                                             float* __restrict__ out) {
    extern __shared__ __align__(16) uint8_t sm[];
    uint32_t sb = smem_u32(sm);
    float* diag = (float*)(sm + Q_DIAG);
    float* srm = (float*)(sm + Q_SRM);
    const int tid = threadIdx.x, w = tid >> 5, lane = tid & 31;
    const int bh = blockIdx.x >> 8, nt = blockIdx.x & 255;
    const int row0 = (w >> 1) * 16, cw = w & 1, col0 = cw * 144;

    for (int i = tid; i < 2592; i += 256) {
        ((uint4*)(sm + PH))[i] = ((const uint4*)g_projB0)[i];
        ((uint4*)(sm + PL))[i] = ((const uint4*)g_projB1)[i];
    }
    stage_x(qin + (size_t)(bh * NSEQ + nt * 64) * 64, sm, XH, XL, diag, tid);
    __syncthreads();

    float C[18][4] = {};
    wgemm<9, 4>(C, sb + XH + row0 * 144, sb + XL + row0 * 144, 144,
                sb + PH + col0 * 144, sb + PL + col0 * 144, 144, lane);

    const int r1 = row0 + (lane >> 2), r2 = r1 + 8;
    const float d1 = diag[r1], d2 = diag[r2];
    float m1 = -CUDART_INF_F, m2 = -CUDART_INF_F;
    #pragma unroll
    for (int t = 0; t < 18; t++) {
        int col = col0 + t * 8 + (lane & 3) * 2;
        if (col < MDIM) {
            m1 = fmaxf(m1, fmaxf(C[t][0], C[t][1]));
            m2 = fmaxf(m2, fmaxf(C[t][2], C[t][3]));
        }
    }
    m1 = fmaxf(m1, __shfl_xor_sync(~0u, m1, 1));
    m1 = fmaxf(m1, __shfl_xor_sync(~0u, m1, 2));
    m2 = fmaxf(m2, __shfl_xor_sync(~0u, m2, 1));
    m2 = fmaxf(m2, __shfl_xor_sync(~0u, m2, 2));
    if ((lane & 3) == 0) {
        srm[cw * 64 + r1] = m1;
        srm[cw * 64 + r2] = m2;
    }
    __syncthreads();
    const float sA = d1 + fmaxf(srm[r1], srm[64 + r1]);
    const float sB = d2 + fmaxf(srm[r2], srm[64 + r2]);

    #pragma unroll
    for (int t = 0; t < 18; t++) {
        int col = col0 + t * 8 + (lane & 3) * 2;
        float q0 = 0.f, q1 = 0.f, q2 = 0.f, q3 = 0.f;
        if (col < MDIM) {
            q0 = ex2f(C[t][0] - sA) + EPSV;
            q1 = ex2f(C[t][1] - sA) + EPSV;
            q2 = ex2f(C[t][2] - sB) + EPSV;
            q3 = ex2f(C[t][3] - sB) + EPSV;
        }
        uint32_t lw, hw;
        hw = bpack2(q0, q1, lw);
        *(uint32_t*)(sm + QPH + r1 * 592 + col * 2) = hw;
        *(uint32_t*)(sm + QPL + r1 * 592 + col * 2) = lw;
        hw = bpack2(q2, q3, lw);
        *(uint32_t*)(sm + QPH + r2 * 592 + col * 2) = hw;
        *(uint32_t*)(sm + QPL + r2 * 592 + col * 2) = lw;
    }
    {
        const uint4* s0 = (const uint4*)(g_ctxB0 + (size_t)bh * 23040);
        const uint4* s1 = (const uint4*)(g_ctxB1 + (size_t)bh * 23040);
        for (int i = tid; i < 2880; i += 256) {
            int rr = i / 36, kk = i % 36;
            *(uint4*)(sm + CTH + rr * 592 + kk * 16) = s0[i];
            *(uint4*)(sm + CTL + rr * 592 + kk * 16) = s1[i];
        }
    }
    __syncthreads();

    float C2[6][4] = {};
    if (cw == 0)
        wgemm<3, 18>(C2, sb + QPH + row0 * 592, sb + QPL + row0 * 592, 592,
                     sb + CTH, sb + CTL, 592, lane);
    else
        wgemm<2, 18>(C2, sb + QPH + row0 * 592, sb + QPL + row0 * 592, 592,
                     sb + CTH + 48 * 592, sb + CTL + 48 * 592, 592, lane);

    if (cw == 1 && (lane & 3) == 0) {
        srm[r1] = C2[2][0];
        srm[r2] = C2[2][2];
    }
    __syncthreads();
    const float i1 = 1.f / srm[r1], i2 = 1.f / srm[r2];
    float* ob = out + (size_t)(bh * NSEQ + nt * 64) * 64;
    const int c2o = cw * 48;
    const int nst = cw ? 2 : 6;
    for (int t = 0; t < nst; t++) {
        int col = c2o + t * 8 + (lane & 3) * 2;
        *(float2*)(ob + (size_t)r1 * 64 + col) = make_float2(C2[t][0] * i1, C2[t][1] * i1);
        *(float2*)(ob + (size_t)r2 * 64 + col) = make_float2(C2[t][2] * i2, C2[t][3] * i2);
    }
}

// ---------------------------------------------------------------------------
extern "C" void kernel_launch(void* const* d_in, const int* in_sizes, int n_in,
                              void* d_out, int out_size) {
    const float* q    = (const float*)d_in[0];
    const float* k    = (const float*)d_in[1];
    const float* v    = (const float*)d_in[2];
    const float* proj = (const float*)d_in[3];
    float* out = (float*)d_out;

    cudaFuncSetAttribute(pass2a, cudaFuncAttributeMaxDynamicSharedMemorySize, SMEM2);
    cudaFuncSetAttribute(pass3, cudaFuncAttributeMaxDynamicSharedMemorySize, SMEM3);

    prep<<<80, 256>>>(proj);
    pass2a<<<BHN * NSPL, 320, SMEM2>>>(k, v);
    pass2b<<<(BHN * 288 * 80 + 255) / 256, 256>>>();
    pass3<<<BHN * 256, 256, SMEM3>>>(q, out);
}

// round 13
// speedup vs baseline: 2.5937x; 1.1862x over previous
#include <cuda_runtime.h>
#include <cuda_bf16.h>
#include <math_constants.h>
#include <cstdint>

// B=2,H=8 -> BHN=16; N=16384; D=64; M=266 (pad 288/320)
#define BHN  16
#define NSEQ 16384
#define MDIM 266
#define NSPL 32
#define SSCALE 0.51011868f    // 64^-0.25 * log2(e)
#define DIAGF  0.34657359f    // 0.5 * ln(2)
#define EPSV   1e-4f

__device__ float g_headmax[BHN];
__device__ __align__(16) float g_ctx_part[(size_t)BHN * NSPL * 320 * 80];
__device__ __align__(16) unsigned short g_projB0[320 * 72];
__device__ __align__(16) unsigned short g_projB1[320 * 72];
__device__ __align__(16) unsigned short g_ctxB0[BHN * 80 * 288];
__device__ __align__(16) unsigned short g_ctxB1[BHN * 80 * 288];

// ---- smem offsets: pass3 ----
#define XH 0u
#define XL 9216u
#define PH 18432u
#define PL 59904u
#define QPH 0u
#define QPL 37888u
#define CTH 75776u
#define CTL 123136u
#define PART 75776u          // fp32 partials [4][64][80] after CT is dead
#define Q_DIAG 170496u
#define Q_SRM  170752u       // [4][64] floats
#define SMEM3  171776u
// ---- pass2a ----
#define PH2   0u
#define PL2   46080u
#define KH2   92160u
#define KL2   134144u
#define VH2   176128u
#define VL2   187392u
#define XH2   198656u
#define XL2   207872u
#define DIAG2 217088u
#define SWM2  217344u        // 20 floats
#define SMEM2 217440u
#define SA 656
#define SB 176

__device__ __forceinline__ uint32_t smem_u32(const void* p) {
    uint32_t a;
    asm("{ .reg .u64 t; cvta.to.shared.u64 t, %1; cvt.u32.u64 %0, t; }" : "=r"(a) : "l"(p));
    return a;
}
__device__ __forceinline__ void ldm4(uint32_t f[4], uint32_t a) {
    asm volatile("ldmatrix.sync.aligned.m8n8.x4.shared.b16 {%0,%1,%2,%3}, [%4];"
        : "=r"(f[0]), "=r"(f[1]), "=r"(f[2]), "=r"(f[3]) : "r"(a));
}
__device__ __forceinline__ void ldm4t(uint32_t f[4], uint32_t a) {
    asm volatile("ldmatrix.sync.aligned.m8n8.x4.trans.shared.b16 {%0,%1,%2,%3}, [%4];"
        : "=r"(f[0]), "=r"(f[1]), "=r"(f[2]), "=r"(f[3]) : "r"(a));
}
__device__ __forceinline__ void mma16816(float c[4], const uint32_t a[4],
                                         uint32_t b0, uint32_t b1) {
    asm volatile("mma.sync.aligned.m16n8k16.row.col.f32.bf16.bf16.f32 "
        "{%0,%1,%2,%3},{%4,%5,%6,%7},{%8,%9},{%0,%1,%2,%3};"
        : "+f"(c[0]), "+f"(c[1]), "+f"(c[2]), "+f"(c[3])
        : "r"(a[0]), "r"(a[1]), "r"(a[2]), "r"(a[3]), "r"(b0), "r"(b1));
}
__device__ __forceinline__ float ex2f(float x) {
    float r;
    asm("ex2.approx.f32 %0, %1;" : "=f"(r) : "f"(x));
    return r;
}

// hi/lo 3-product warp GEMM (non-trans operands)
template <int NTP, int KS>
__device__ __forceinline__ void wgemm(float C[][4], uint32_t aH, uint32_t aL, int ldaB,
                                      uint32_t bH, uint32_t bL, int ldbB, int lane) {
    const uint32_t ao = (uint32_t)(lane & 15) * ldaB + (uint32_t)(lane >> 4) * 16;
    const uint32_t bo = (uint32_t)(lane & 15) * ldbB + (uint32_t)(lane >> 4) * 16;
    for (int ks = 0; ks < KS; ks++) {
        uint32_t ah[4], al[4];
        ldm4(ah, aH + ao + ks * 32);
        ldm4(al, aL + ao + ks * 32);
        #pragma unroll
        for (int tp = 0; tp < NTP; tp++) {
            uint32_t bh[4], bl[4];
            ldm4(bh, bH + bo + tp * 16 * ldbB + ks * 32);
            ldm4(bl, bL + bo + tp * 16 * ldbB + ks * 32);
            mma16816(C[2 * tp], ah, bh[0], bh[2]);
            mma16816(C[2 * tp], ah, bl[0], bl[2]);
            mma16816(C[2 * tp], al, bh[0], bh[2]);
            mma16816(C[2 * tp + 1], ah, bh[1], bh[3]);
            mma16816(C[2 * tp + 1], ah, bl[1], bl[3]);
            mma16816(C[2 * tp + 1], al, bh[1], bh[3]);
        }
    }
}

// fast split: hi = truncation (PRMT), lo = RN(x - hi) packed cvt
__device__ __forceinline__ uint32_t bpack2(float a, float b, uint32_t& lo) {
    uint32_t ia = __float_as_uint(a), ib = __float_as_uint(b);
    uint32_t hi = __byte_perm(ia, ib, 0x7632);
    float la = a - __uint_as_float(ia & 0xffff0000u);
    float lb = b - __uint_as_float(ib & 0xffff0000u);
    __nv_bfloat162 t = __floats2bfloat162_rn(la, lb);
    lo = *reinterpret_cast<uint32_t*>(&t);
    return hi;
}
__device__ __forceinline__ void atomicMaxFloat(float* addr, float val) {
    int* ai = (int*)addr;
    int old = *ai;
    while (__int_as_float(old) < val) {
        int prev = atomicCAS(ai, old, __float_as_int(val));
        if (prev == old) return;
        old = prev;
    }
}

// stage 64x64 fp32 -> scaled bf16 hi/lo [64][72] (+optional diag). tid < 256 only.
__device__ __forceinline__ void stage_x(const float* __restrict__ src, uint8_t* sm,
                                        uint32_t offH, uint32_t offL, float* diag, int tid) {
    const int r = tid >> 2, c0 = (tid & 3) * 16;
    const float4* p = (const float4*)(src + (size_t)r * 64 + c0);
    uint32_t h[8], l[8];
    float sq = 0.f;
    #pragma unroll
    for (int j = 0; j < 4; j++) {
        float4 t = p[j];
        float v[4] = {t.x * SSCALE, t.y * SSCALE, t.z * SSCALE, t.w * SSCALE};
        h[j * 2]     = bpack2(v[0], v[1], l[j * 2]);
        h[j * 2 + 1] = bpack2(v[2], v[3], l[j * 2 + 1]);
        sq = fmaf(v[0], v[0], fmaf(v[1], v[1], fmaf(v[2], v[2], fmaf(v[3], v[3], sq))));
    }
    uint32_t ba = (uint32_t)r * 144 + (uint32_t)c0 * 2;
    *(uint4*)(sm + offH + ba)      = make_uint4(h[0], h[1], h[2], h[3]);
    *(uint4*)(sm + offH + ba + 16) = make_uint4(h[4], h[5], h[6], h[7]);
    *(uint4*)(sm + offL + ba)      = make_uint4(l[0], l[1], l[2], l[3]);
    *(uint4*)(sm + offL + ba + 16) = make_uint4(l[4], l[5], l[6], l[7]);
    if (diag) {
        sq += __shfl_xor_sync(~0u, sq, 1);
        sq += __shfl_xor_sync(~0u, sq, 2);
        if ((tid & 3) == 0) diag[r] = DIAGF * sq;
    }
}

__global__ void prep(const float* __restrict__ proj) {
    int gid = blockIdx.x * 256 + threadIdx.x;   // 320*64
    int r = gid >> 6, c = gid & 63;
    float v = (r < MDIM) ? proj[r * 64 + c] : 0.f;
    uint32_t ib = __float_as_uint(v);
    g_projB0[r * 72 + c] = (unsigned short)(ib >> 16);
    float lv = v - __uint_as_float(ib & 0xffff0000u);
    g_projB1[r * 72 + c] = __bfloat16_as_ushort(__float2bfloat16(lv));
    if (gid < BHN) g_headmax[gid] = -CUDART_INF_F;
}

// ---------------------------------------------------------------------------
// pass2a: 640 threads, 20 warps (one 16-m stripe each).
// dd via 3-product GEMM1; head max; kpE = 2^(dd - diag); GEMM2 ctxE
// (+ksum col 64, +Vsum row 288). grid = 16*NSPL.
// ---------------------------------------------------------------------------
__global__ __launch_bounds__(640) void pass2a(const float* __restrict__ kin,
                                              const float* __restrict__ vin) {
    extern __shared__ __align__(16) uint8_t sm[];
    uint32_t sb = smem_u32(sm);
    float* diag = (float*)(sm + DIAG2);
    float* swm = (float*)(sm + SWM2);
    const int tid = threadIdx.x, w = tid >> 5, lane = tid & 31;
    const int bh = blockIdx.x >> 5, split = blockIdx.x & 31;
    const int m0w = w * 16;

    for (int i = tid; i < 2880; i += 640) {
        ((uint4*)(sm + PH2))[i] = ((const uint4*)g_projB0)[i];
        ((uint4*)(sm + PL2))[i] = ((const uint4*)g_projB1)[i];
    }
    for (int i = tid; i < 64 * 12; i += 640) {
        int n = i / 12, c = i % 12;
        *(uint32_t*)(sm + VH2 + n * SB + 128 + c * 4) = (c == 0) ? 0x3F80u : 0u;
        *(uint32_t*)(sm + VL2 + n * SB + 128 + c * 4) = 0u;
    }

    const uint32_t ao1 = (uint32_t)(lane & 15) * 144u + (uint32_t)(lane >> 4) * 16u;
    const uint32_t lo_ = ((uint32_t)(lane & 7) + (uint32_t)((lane >> 4) & 1) * 8);
    const uint32_t aoff = lo_ * SA + (uint32_t)((lane >> 3) & 1) * 16;
    const uint32_t boff = lo_ * SB + (uint32_t)((lane >> 3) & 1) * 16;
    const int lr = lane >> 2, lc = (lane & 3) * 2;

    float tmax = -CUDART_INF_F;
    float C[10][4] = {};
    for (int t = 0; t < 8; t++) {
        const size_t n0 = (size_t)bh * NSEQ + (size_t)split * 512 + t * 64;
        __syncthreads();
        if (tid < 256)
            stage_x(kin + n0 * 64, sm, XH2, XL2, diag, tid);
        for (int i = tid; i < 64 * 32; i += 640) {
            int n = i >> 5, dp = i & 31;
            float2 vv = *(const float2*)&vin[(n0 + n) * 64 + dp * 2];
            uint32_t lw, hw = bpack2(vv.x, vv.y, lw);
            *(uint32_t*)(sm + VH2 + n * SB + dp * 4) = hw;
            *(uint32_t*)(sm + VL2 + n * SB + dp * 4) = lw;
        }
        __syncthreads();

        // GEMM1: dd[n=64][m stripe 16]
        float C1[4][2][4] = {};
        for (int ks = 0; ks < 4; ks++) {
            uint32_t pbh[4], pbl[4];
            ldm4(pbh, sb + PH2 + m0w * 144 + ao1 + ks * 32);
            ldm4(pbl, sb + PL2 + m0w * 144 + ao1 + ks * 32);
            #pragma unroll
            for (int rt = 0; rt < 4; rt++) {
                uint32_t ah[4], al[4];
                ldm4(ah, sb + XH2 + rt * 16 * 144 + ao1 + ks * 32);
                ldm4(al, sb + XL2 + rt * 16 * 144 + ao1 + ks * 32);
                mma16816(C1[rt][0], ah, pbh[0], pbh[2]);
                mma16816(C1[rt][0], ah, pbl[0], pbl[2]);
                mma16816(C1[rt][0], al, pbh[0], pbh[2]);
                mma16816(C1[rt][1], ah, pbh[1], pbh[3]);
                mma16816(C1[rt][1], ah, pbl[1], pbl[3]);
                mma16816(C1[rt][1], al, pbh[1], pbh[3]);
            }
        }
        // kpE = 2^(dd - diag); track max(dd); warp 18 stripe: ones col m=288
        #pragma unroll
        for (int rt = 0; rt < 4; rt++) {
            int r1 = rt * 16 + lr, r2 = r1 + 8;
            float dA = diag[r1], dB = diag[r2];
            #pragma unroll
            for (int t8 = 0; t8 < 2; t8++) {
                int m = m0w + t8 * 8 + lc;
                float k0, k1, k2, k3;
                if (m < 288) {
                    float c0 = C1[rt][t8][0], c1 = C1[rt][t8][1];
                    float c2 = C1[rt][t8][2], c3 = C1[rt][t8][3];
                    tmax = fmaxf(tmax, fmaxf(fmaxf(c0, c1), fmaxf(c2, c3)));
                    k0 = ex2f(c0 - dA);
                    k1 = ex2f(c1 - dA);
                    k2 = ex2f(c2 - dB);
                    k3 = ex2f(c3 - dB);
                } else {
                    float o = (m == 288) ? 1.f : 0.f;
                    k0 = o; k2 = o; k1 = 0.f; k3 = 0.f;
                }
                uint32_t lw, hw;
                hw = bpack2(k0, k1, lw);
                *(uint32_t*)(sm + KH2 + r1 * SA + m * 2) = hw;
                *(uint32_t*)(sm + KL2 + r1 * SA + m * 2) = lw;
                hw = bpack2(k2, k3, lw);
                *(uint32_t*)(sm + KH2 + r2 * SA + m * 2) = hw;
                *(uint32_t*)(sm + KL2 + r2 * SA + m * 2) = lw;
            }
        }
        __syncthreads();

        // GEMM2: ctxE[m stripe 16][80] += kp^T x v
        for (int ks = 0; ks < 4; ks++) {
            uint32_t ah[4], al[4];
            ldm4t(ah, sb + KH2 + aoff + ks * 16 * SA + m0w * 2);
            ldm4t(al, sb + KL2 + aoff + ks * 16 * SA + m0w * 2);
            #pragma unroll
            for (int tp = 0; tp < 5; tp++) {
                uint32_t bh4[4], bl4[4];
                ldm4t(bh4, sb + VH2 + boff + ks * 16 * SB + tp * 32);
                ldm4t(bl4, sb + VL2 + boff + ks * 16 * SB + tp * 32);
                mma16816(C[2 * tp], ah, bh4[0], bh4[2]);
                mma16816(C[2 * tp], ah, bl4[0], bl4[2]);
                mma16816(C[2 * tp], al, bh4[0], bh4[2]);
                mma16816(C[2 * tp + 1], ah, bh4[1], bh4[3]);
                mma16816(C[2 * tp + 1], ah, bl4[1], bl4[3]);
                mma16816(C[2 * tp + 1], al, bh4[1], bh4[3]);
            }
        }
    }
    // block max -> atomic
    #pragma unroll
    for (int o = 16; o; o >>= 1) tmax = fmaxf(tmax, __shfl_xor_sync(~0u, tmax, o));
    if (lane == 0) swm[w] = tmax;
    __syncthreads();
    if (tid == 0) {
        float m = swm[0];
        #pragma unroll
        for (int i = 1; i < 20; i++) m = fmaxf(m, swm[i]);
        atomicMaxFloat(&g_headmax[bh], m);
    }

    float* pb = g_ctx_part + (size_t)(bh * NSPL + split) * (320 * 80);
    {
        int r1 = m0w + lr, r2 = r1 + 8;
        #pragma unroll
        for (int tp = 0; tp < 5; tp++) {
            int col = tp * 16 + lc;
            *(float2*)(pb + (size_t)r1 * 80 + col)     = make_float2(C[2 * tp][0], C[2 * tp][1]);
            *(float2*)(pb + (size_t)r2 * 80 + col)     = make_float2(C[2 * tp][2], C[2 * tp][3]);
            *(float2*)(pb + (size_t)r1 * 80 + col + 8) = make_float2(C[2 * tp + 1][0], C[2 * tp + 1][1]);
            *(float2*)(pb + (size_t)r2 * 80 + col + 8) = make_float2(C[2 * tp + 1][2], C[2 * tp + 1][3]);
        }
    }
}

// ---------------------------------------------------------------------------
// pass2b: ctx = 2^(-stab)*ctxE + EPS*Vsum; reduce splits; emit bf16 hi/lo.
// ---------------------------------------------------------------------------
__global__ __launch_bounds__(256) void pass2b() {
    int gid = blockIdx.x * 256 + threadIdx.x;
    if (gid >= BHN * 288 * 80) return;
    int bh = gid / (288 * 80);
    int rem = gid % (288 * 80);
    int m = rem / 80, d = rem % 80;
    const float scale = ex2f(-g_headmax[bh]);
    const float* base = g_ctx_part + (size_t)bh * NSPL * (320 * 80);
    float s = 0.f, vs = 0.f;
    #pragma unroll
    for (int sp = 0; sp < NSPL; sp++) {
        s  += base[((size_t)sp * 320 + m) * 80 + d];
        vs += base[((size_t)sp * 320 + 288) * 80 + d];
    }
    float f = fmaf(EPSV, vs, scale * s);
    uint32_t ib = __float_as_uint(f);
    g_ctxB0[(size_t)bh * 23040 + d * 288 + m] = (unsigned short)(ib >> 16);
    float lv = f - __uint_as_float(ib & 0xffff0000u);
    g_ctxB1[(size_t)bh * 23040 + d * 288 + m] = __bfloat16_as_ushort(__float2bfloat16(lv));
}

// ---------------------------------------------------------------------------
// pass3: 512 threads, 16 warps = 4 row stripes x 4 col groups.
// GEMM1 col split {80,64,64,80}; GEMM2 split-K {5,5,4,4} + smem reduce.
// ---------------------------------------------------------------------------
__global__ __launch_bounds__(512) void pass3(const float* __restrict__ qin,
                                             float* __restrict__ out) {
    extern __shared__ __align__(16) uint8_t sm[];
    uint32_t sb = smem_u32(sm);
    float* diag = (float*)(sm + Q_DIAG);
    float* srm = (float*)(sm + Q_SRM);
    float* part = (float*)(sm + PART);
    const int tid = threadIdx.x, w = tid >> 5, lane = tid & 31;
    const int bh = blockIdx.x >> 8, nt = blockIdx.x & 255;
    const int rs = w >> 2, cg = w & 3;
    const int row0 = rs * 16;
    const int col0 = (cg == 0) ? 0 : (cg == 1) ? 80 : (cg == 2) ? 144 : 208;
    const int ntp = (cg == 0 || cg == 3) ? 5 : 4;

    for (int i = tid; i < 2592; i += 512) {
        ((uint4*)(sm + PH))[i] = ((const uint4*)g_projB0)[i];
        ((uint4*)(sm + PL))[i] = ((const uint4*)g_projB1)[i];
    }
    if (tid < 256)
        stage_x(qin + (size_t)(bh * NSEQ + nt * 64) * 64, sm, XH, XL, diag, tid);
    __syncthreads();

    float C[10][4] = {};
    if (ntp == 5)
        wgemm<5, 4>(C, sb + XH + row0 * 144, sb + XL + row0 * 144, 144,
                    sb + PH + col0 * 144, sb + PL + col0 * 144, 144, lane);
    else
        wgemm<4, 4>(C, sb + XH + row0 * 144, sb + XL + row0 * 144, 144,
                    sb + PH + col0 * 144, sb + PL + col0 * 144, 144, lane);

    const int lr = lane >> 2, lc = (lane & 3) * 2;
    const int r1 = row0 + lr, r2 = r1 + 8;
    const float d1 = diag[r1], d2 = diag[r2];
    float m1 = -CUDART_INF_F, m2 = -CUDART_INF_F;
    #pragma unroll
    for (int t = 0; t < 10; t++) {
        if (t >= 2 * ntp) break;
        int col = col0 + t * 8 + lc;
        if (col < MDIM) {
            m1 = fmaxf(m1, fmaxf(C[t][0], C[t][1]));
            m2 = fmaxf(m2, fmaxf(C[t][2], C[t][3]));
        }
    }
    m1 = fmaxf(m1, __shfl_xor_sync(~0u, m1, 1));
    m1 = fmaxf(m1, __shfl_xor_sync(~0u, m1, 2));
    m2 = fmaxf(m2, __shfl_xor_sync(~0u, m2, 1));
    m2 = fmaxf(m2, __shfl_xor_sync(~0u, m2, 2));
    if ((lane & 3) == 0) {
        srm[cg * 64 + r1] = m1;
        srm[cg * 64 + r2] = m2;
    }
    __syncthreads();
    const float rmax1 = fmaxf(fmaxf(srm[r1], srm[64 + r1]),
                              fmaxf(srm[128 + r1], srm[192 + r1]));
    const float rmax2 = fmaxf(fmaxf(srm[r2], srm[64 + r2]),
                              fmaxf(srm[128 + r2], srm[192 + r2]));
    const float sA = d1 + rmax1, sB = d2 + rmax2;

    // qp = 2^(dd - diag - rowmax) + EPS -> QP smem (cols >= MDIM zeroed)
    #pragma unroll
    for (int t = 0; t < 10; t++) {
        if (t >= 2 * ntp) break;
        int col = col0 + t * 8 + lc;
        float q0 = 0.f, q1 = 0.f, q2 = 0.f, q3 = 0.f;
        if (col < MDIM) {
            q0 = ex2f(C[t][0] - sA) + EPSV;
            q1 = ex2f(C[t][1] - sA) + EPSV;
            q2 = ex2f(C[t][2] - sB) + EPSV;
            q3 = ex2f(C[t][3] - sB) + EPSV;
        }
        uint32_t lw, hw;
        hw = bpack2(q0, q1, lw);
        *(uint32_t*)(sm + QPH + r1 * 592 + col * 2) = hw;
        *(uint32_t*)(sm + QPL + r1 * 592 + col * 2) = lw;
        hw = bpack2(q2, q3, lw);
        *(uint32_t*)(sm + QPH + r2 * 592 + col * 2) = hw;
        *(uint32_t*)(sm + QPL + r2 * 592 + col * 2) = lw;
    }
    // ct^T [80][288] -> smem [80][296]
    {
        const uint4* s0 = (const uint4*)(g_ctxB0 + (size_t)bh * 23040);
        const uint4* s1 = (const uint4*)(g_ctxB1 + (size_t)bh * 23040);
        for (int i = tid; i < 2880; i += 512) {
            int rr = i / 36, kk = i % 36;
            *(uint4*)(sm + CTH + rr * 592 + kk * 16) = s0[i];
            *(uint4*)(sm + CTL + rr * 592 + kk * 16) = s1[i];
        }
    }
    __syncthreads();

    // GEMM2 split-K: cg ks chunks {0..4, 5..9, 10..13, 14..17}
    const int ks0 = (cg < 2) ? cg * 5 : 10 + (cg - 2) * 4;
    float C2[10][4] = {};
    if (cg < 2)
        wgemm<5, 5>(C2, sb + QPH + row0 * 592 + ks0 * 32, sb + QPL + row0 * 592 + ks0 * 32, 592,
                    sb + CTH + ks0 * 32, sb + CTL + ks0 * 32, 592, lane);
    else
        wgemm<5, 4>(C2, sb + QPH + row0 * 592 + ks0 * 32, sb + QPL + row0 * 592 + ks0 * 32, 592,
                    sb + CTH + ks0 * 32, sb + CTL + ks0 * 32, 592, lane);
    __syncthreads();   // all QP/CT reads done; PART may overwrite CT region

    #pragma unroll
    for (int tp = 0; tp < 5; tp++) {
        int col = tp * 16 + lc;
        *(float2*)&part[(size_t)(cg * 64 + r1) * 80 + col]     = make_float2(C2[2 * tp][0], C2[2 * tp][1]);
        *(float2*)&part[(size_t)(cg * 64 + r2) * 80 + col]     = make_float2(C2[2 * tp][2], C2[2 * tp][3]);
        *(float2*)&part[(size_t)(cg * 64 + r1) * 80 + col + 8] = make_float2(C2[2 * tp + 1][0], C2[2 * tp + 1][1]);
        *(float2*)&part[(size_t)(cg * 64 + r2) * 80 + col + 8] = make_float2(C2[2 * tp + 1][2], C2[2 * tp + 1][3]);
    }
    __syncthreads();

    // final reduce + divide + store: thread -> row r, 8 cols
    {
        const int r = tid >> 3, c0 = (tid & 7) * 8;
        float den = part[(size_t)r * 80 + 64] + part[(size_t)(64 + r) * 80 + 64] +
                    part[(size_t)(128 + r) * 80 + 64] + part[(size_t)(192 + r) * 80 + 64];
        float rcp = 1.f / den;
        float4 s0 = make_float4(0.f, 0.f, 0.f, 0.f), s1 = s0;
        #pragma unroll
        for (int cgk = 0; cgk < 4; cgk++) {
            const float* p = &part[(size_t)(cgk * 64 + r) * 80 + c0];
            float4 a = *(const float4*)p;
            float4 b = *(const float4*)(p + 4);
            s0.x += a.x; s0.y += a.y; s0.z += a.z; s0.w += a.w;
            s1.x += b.x; s1.y += b.y; s1.z += b.z; s1.w += b.w;
        }
        float* ob = out + ((size_t)(bh * NSEQ + nt * 64) + r) * 64 + c0;
        *(float4*)ob       = make_float4(s0.x * rcp, s0.y * rcp, s0.z * rcp, s0.w * rcp);
        *(float4*)(ob + 4) = make_float4(s1.x * rcp, s1.y * rcp, s1.z * rcp, s1.w * rcp);
    }
}

// ---------------------------------------------------------------------------
extern "C" void kernel_launch(void* const* d_in, const int* in_sizes, int n_in,
                              void* d_out, int out_size) {
    const float* q    = (const float*)d_in[0];
    const float* k    = (const float*)d_in[1];
    const float* v    = (const float*)d_in[2];
    const float* proj = (const float*)d_in[3];
    float* out = (float*)d_out;

    cudaFuncSetAttribute(pass2a, cudaFuncAttributeMaxDynamicSharedMemorySize, SMEM2);
    cudaFuncSetAttribute(pass3, cudaFuncAttributeMaxDynamicSharedMemorySize, SMEM3);

    prep<<<80, 256>>>(proj);
    pass2a<<<BHN * NSPL, 640, SMEM2>>>(k, v);
    pass2b<<<(BHN * 288 * 80 + 255) / 256, 256>>>();
    pass3<<<BHN * 256, 512, SMEM3>>>(q, out);
}

// round 17
// speedup vs baseline: 2.5991x; 1.0021x over previous
#include <cuda_runtime.h>
#include <cuda_bf16.h>
#include <math_constants.h>
#include <cstdint>

#define BHN  16
#define NSEQ 16384
#define MDIM 266
#define NSPL 32
#define SSCALE 0.51011868f
#define DIAGF  0.34657359f
#define EPSV   1e-4f

__device__ float g_headmax[BHN];
__device__ __align__(16) float g_ctx_part[(size_t)BHN * NSPL * 320 * 80];
__device__ __align__(16) unsigned short g_projB0[320 * 72];
__device__ __align__(16) unsigned short g_projB1[320 * 72];
__device__ __align__(16) unsigned short g_ctxB0[BHN * 80 * 288];
__device__ __align__(16) unsigned short g_ctxB1[BHN * 80 * 288];

// ---- pass3 smem ----
#define XH 0u
#define XL 9216u
#define PH 18432u
#define PL 59904u
#define CTH3 0u
#define CTL3 47360u
#define PART 0u
#define Q_DIAG 101376u
#define Q_SRM  101632u
#define SMEM3  102656u
// ---- pass2a smem ----
#define PH2   0u
#define PL2   46080u
#define VH2   92160u
#define VL2   103424u
#define XH2   114688u
#define XL2   123904u
#define DIAG2 133120u
#define SWM2  133376u
#define SMEM2 133472u
#define SB 176

__device__ __forceinline__ uint32_t smem_u32(const void* p) {
    uint32_t a;
    asm("{ .reg .u64 t; cvta.to.shared.u64 t, %1; cvt.u32.u64 %0, t; }" : "=r"(a) : "l"(p));
    return a;
}
__device__ __forceinline__ void ldm4(uint32_t f[4], uint32_t a) {
    asm volatile("ldmatrix.sync.aligned.m8n8.x4.shared.b16 {%0,%1,%2,%3}, [%4];"
        : "=r"(f[0]), "=r"(f[1]), "=r"(f[2]), "=r"(f[3]) : "r"(a));
}
__device__ __forceinline__ void ldm4t(uint32_t f[4], uint32_t a) {
    asm volatile("ldmatrix.sync.aligned.m8n8.x4.trans.shared.b16 {%0,%1,%2,%3}, [%4];"
        : "=r"(f[0]), "=r"(f[1]), "=r"(f[2]), "=r"(f[3]) : "r"(a));
}
__device__ __forceinline__ uint32_t movm(uint32_t x) {
    uint32_t d;
    asm volatile("movmatrix.sync.aligned.m8n8.trans.b16 %0, %1;" : "=r"(d) : "r"(x));
    return d;
}
__device__ __forceinline__ void mma16816(float c[4], const uint32_t a[4],
                                         uint32_t b0, uint32_t b1) {
    asm volatile("mma.sync.aligned.m16n8k16.row.col.f32.bf16.bf16.f32 "
        "{%0,%1,%2,%3},{%4,%5,%6,%7},{%8,%9},{%0,%1,%2,%3};"
        : "+f"(c[0]), "+f"(c[1]), "+f"(c[2]), "+f"(c[3])
        : "r"(a[0]), "r"(a[1]), "r"(a[2]), "r"(a[3]), "r"(b0), "r"(b1));
}
__device__ __forceinline__ float ex2f(float x) {
    float r;
    asm("ex2.approx.f32 %0, %1;" : "=f"(r) : "f"(x));
    return r;
}

// hi/lo 3-product warp GEMM (non-trans operands; GEMM1s)
template <int NTP, int KS>
__device__ __forceinline__ void wgemm(float C[][4], uint32_t aH, uint32_t aL, int ldaB,
                                      uint32_t bH, uint32_t bL, int ldbB, int lane) {
    const uint32_t ao = (uint32_t)(lane & 15) * ldaB + (uint32_t)(lane >> 4) * 16;
    const uint32_t bo = (uint32_t)(lane & 15) * ldbB + (uint32_t)(lane >> 4) * 16;
    for (int ks = 0; ks < KS; ks++) {
        uint32_t ah[4], al[4];
        ldm4(ah, aH + ao + ks * 32);
        ldm4(al, aL + ao + ks * 32);
        #pragma unroll
        for (int tp = 0; tp < NTP; tp++) {
            uint32_t bh[4], bl[4];
            ldm4(bh, bH + bo + tp * 16 * ldbB + ks * 32);
            ldm4(bl, bL + bo + tp * 16 * ldbB + ks * 32);
            mma16816(C[2 * tp], ah, bh[0], bh[2]);
            mma16816(C[2 * tp], ah, bl[0], bl[2]);
            mma16816(C[2 * tp], al, bh[0], bh[2]);
            mma16816(C[2 * tp + 1], ah, bh[1], bh[3]);
            mma16816(C[2 * tp + 1], ah, bl[1], bl[3]);
            mma16816(C[2 * tp + 1], al, bh[1], bh[3]);
        }
    }
}

__device__ __forceinline__ uint32_t bpack2(float a, float b, uint32_t& lo) {
    uint32_t ia = __float_as_uint(a), ib = __float_as_uint(b);
    uint32_t hi = __byte_perm(ia, ib, 0x7632);
    float la = a - __uint_as_float(ia & 0xffff0000u);
    float lb = b - __uint_as_float(ib & 0xffff0000u);
    __nv_bfloat162 t = __floats2bfloat162_rn(la, lb);
    lo = *reinterpret_cast<uint32_t*>(&t);
    return hi;
}
__device__ __forceinline__ void atomicMaxFloat(float* addr, float val) {
    int* ai = (int*)addr;
    int old = *ai;
    while (__int_as_float(old) < val) {
        int prev = atomicCAS(ai, old, __float_as_int(val));
        if (prev == old) return;
        old = prev;
    }
}

// stage 64x64 fp32 -> scaled bf16 hi/lo [64][72] (+optional diag). tid < 256.
__device__ __forceinline__ void stage_x(const float* __restrict__ src, uint8_t* sm,
                                        uint32_t offH, uint32_t offL, float* diag, int tid) {
    const int r = tid >> 2, c0 = (tid & 3) * 16;
    const float4* p = (const float4*)(src + (size_t)r * 64 + c0);
    uint32_t h[8], l[8];
    float sq = 0.f;
    #pragma unroll
    for (int j = 0; j < 4; j++) {
        float4 t = p[j];
        float v[4] = {t.x * SSCALE, t.y * SSCALE, t.z * SSCALE, t.w * SSCALE};
        h[j * 2]     = bpack2(v[0], v[1], l[j * 2]);
        h[j * 2 + 1] = bpack2(v[2], v[3], l[j * 2 + 1]);
        sq = fmaf(v[0], v[0], fmaf(v[1], v[1], fmaf(v[2], v[2], fmaf(v[3], v[3], sq))));
    }
    uint32_t ba = (uint32_t)r * 144 + (uint32_t)c0 * 2;
    *(uint4*)(sm + offH + ba)      = make_uint4(h[0], h[1], h[2], h[3]);
    *(uint4*)(sm + offH + ba + 16) = make_uint4(h[4], h[5], h[6], h[7]);
    *(uint4*)(sm + offL + ba)      = make_uint4(l[0], l[1], l[2], l[3]);
    *(uint4*)(sm + offL + ba + 16) = make_uint4(l[4], l[5], l[6], l[7]);
    if (diag) {
        sq += __shfl_xor_sync(~0u, sq, 1);
        sq += __shfl_xor_sync(~0u, sq, 2);
        if ((tid & 3) == 0) diag[r] = DIAGF * sq;
    }
}

__global__ void prep(const float* __restrict__ proj) {
    int gid = blockIdx.x * 256 + threadIdx.x;
    int r = gid >> 6, c = gid & 63;
    float v = (r < MDIM) ? proj[r * 64 + c] : 0.f;
    uint32_t ib = __float_as_uint(v);
    g_projB0[r * 72 + c] = (unsigned short)(ib >> 16);
    float lv = v - __uint_as_float(ib & 0xffff0000u);
    g_projB1[r * 72 + c] = __bfloat16_as_ushort(__float2bfloat16(lv));
    if (gid < BHN) g_headmax[gid] = -CUDART_INF_F;
}

// ---------------------------------------------------------------------------
// pass2a: 640 threads, 20 warps. GEMM1 -> exp in regs -> movmatrix -> GEMM2.
// ---------------------------------------------------------------------------
__global__ __launch_bounds__(640) void pass2a(const float* __restrict__ kin,
                                              const float* __restrict__ vin) {
    extern __shared__ __align__(16) uint8_t sm[];
    uint32_t sb = smem_u32(sm);
    float* diag = (float*)(sm + DIAG2);
    float* swm = (float*)(sm + SWM2);
    const int tid = threadIdx.x, w = tid >> 5, lane = tid & 31;
    const int bh = blockIdx.x >> 5, split = blockIdx.x & 31;
    const int m0w = w * 16;
    const int lr = lane >> 2, lc = (lane & 3) * 2;

    for (int i = tid; i < 2880; i += 640) {
        ((uint4*)(sm + PH2))[i] = ((const uint4*)g_projB0)[i];
        ((uint4*)(sm + PL2))[i] = ((const uint4*)g_projB1)[i];
    }
    for (int i = tid; i < 64 * 12; i += 640) {
        int n = i / 12, c = i % 12;
        *(uint32_t*)(sm + VH2 + n * SB + 128 + c * 4) = (c == 0) ? 0x3F80u : 0u;
        *(uint32_t*)(sm + VL2 + n * SB + 128 + c * 4) = 0u;
    }

    const uint32_t ao1 = (uint32_t)(lane & 15) * 144u + (uint32_t)(lane >> 4) * 16u;
    const uint32_t lo_ = ((uint32_t)(lane & 7) + (uint32_t)((lane >> 4) & 1) * 8);
    const uint32_t boff = lo_ * SB + (uint32_t)((lane >> 3) & 1) * 16;

    float tmax = -CUDART_INF_F;
    float C[10][4] = {};
    for (int t = 0; t < 8; t++) {
        const size_t n0 = (size_t)bh * NSEQ + (size_t)split * 512 + t * 64;
        __syncthreads();
        if (tid < 256)
            stage_x(kin + n0 * 64, sm, XH2, XL2, diag, tid);
        for (int i = tid; i < 64 * 32; i += 640) {
            int n = i >> 5, dp = i & 31;
            float2 vv = *(const float2*)&vin[(n0 + n) * 64 + dp * 2];
            uint32_t lw, hw = bpack2(vv.x, vv.y, lw);
            *(uint32_t*)(sm + VH2 + n * SB + dp * 4) = hw;
            *(uint32_t*)(sm + VL2 + n * SB + dp * 4) = lw;
        }
        __syncthreads();

        uint32_t ah2[4][4], al2[4][4];   // per rt (k16 = 16 n) A-frags of kp^T
        if (w < 18) {
            // GEMM1: dd[n=64][m stripe 16]
            float C1[4][2][4] = {};
            for (int ks = 0; ks < 4; ks++) {
                uint32_t pbh[4], pbl[4];
                ldm4(pbh, sb + PH2 + m0w * 144 + ao1 + ks * 32);
                ldm4(pbl, sb + PL2 + m0w * 144 + ao1 + ks * 32);
                #pragma unroll
                for (int rt = 0; rt < 4; rt++) {
                    uint32_t ah[4], al[4];
                    ldm4(ah, sb + XH2 + rt * 16 * 144 + ao1 + ks * 32);
                    ldm4(al, sb + XL2 + rt * 16 * 144 + ao1 + ks * 32);
                    mma16816(C1[rt][0], ah, pbh[0], pbh[2]);
                    mma16816(C1[rt][0], ah, pbl[0], pbl[2]);
                    mma16816(C1[rt][0], al, pbh[0], pbh[2]);
                    mma16816(C1[rt][1], ah, pbh[1], pbh[3]);
                    mma16816(C1[rt][1], ah, pbl[1], pbl[3]);
                    mma16816(C1[rt][1], al, pbh[1], pbh[3]);
                }
            }
            // exp -> hi/lo A-frags via movmatrix (m<288 always here)
            #pragma unroll
            for (int rt = 0; rt < 4; rt++) {
                float dA = diag[rt * 16 + lr], dB = diag[rt * 16 + lr + 8];
                #pragma unroll
                for (int sub = 0; sub < 2; sub++) {
                    float c0 = C1[rt][sub][0], c1 = C1[rt][sub][1];
                    float c2 = C1[rt][sub][2], c3 = C1[rt][sub][3];
                    tmax = fmaxf(tmax, fmaxf(fmaxf(c0, c1), fmaxf(c2, c3)));
                    float k0 = ex2f(c0 - dA), k1 = ex2f(c1 - dA);
                    float k2 = ex2f(c2 - dB), k3 = ex2f(c3 - dB);
                    uint32_t l01, l23;
                    uint32_t h01 = bpack2(k0, k1, l01);
                    uint32_t h23 = bpack2(k2, k3, l23);
                    ah2[rt][sub]     = movm(h01);   // [m 0-7 or 8-15][n 0-7]
                    ah2[rt][sub + 2] = movm(h23);   // [..][n 8-15]
                    al2[rt][sub]     = movm(l01);
                    al2[rt][sub + 2] = movm(l23);
                }
            }
        } else if (w == 18) {
            // Vsum row: kp^T row m=288 (rel 0) = ones
            uint32_t one = (lr == 0) ? 0x3F803F80u : 0u;
            #pragma unroll
            for (int rt = 0; rt < 4; rt++) {
                ah2[rt][0] = one; ah2[rt][1] = 0u; ah2[rt][2] = one; ah2[rt][3] = 0u;
                al2[rt][0] = 0u;  al2[rt][1] = 0u; al2[rt][2] = 0u;  al2[rt][3] = 0u;
            }
        }

        // GEMM2: ctxE[m stripe 16][80] += kp^T x v  (rt = k16 chunk)
        if (w < 19) {
            #pragma unroll
            for (int rt = 0; rt < 4; rt++) {
                #pragma unroll
                for (int tp = 0; tp < 5; tp++) {
                    uint32_t bh4[4], bl4[4];
                    ldm4t(bh4, sb + VH2 + boff + rt * 16 * SB + tp * 32);
                    ldm4t(bl4, sb + VL2 + boff + rt * 16 * SB + tp * 32);
                    mma16816(C[2 * tp], ah2[rt], bh4[0], bh4[2]);
                    mma16816(C[2 * tp], ah2[rt], bl4[0], bl4[2]);
                    mma16816(C[2 * tp], al2[rt], bh4[0], bh4[2]);
                    mma16816(C[2 * tp + 1], ah2[rt], bh4[1], bh4[3]);
                    mma16816(C[2 * tp + 1], ah2[rt], bl4[1], bl4[3]);
                    mma16816(C[2 * tp + 1], al2[rt], bh4[1], bh4[3]);
                }
            }
        }
    }
    #pragma unroll
    for (int o = 16; o; o >>= 1) tmax = fmaxf(tmax, __shfl_xor_sync(~0u, tmax, o));
    if (lane == 0) swm[w] = tmax;
    __syncthreads();
    if (tid == 0) {
        float m = swm[0];
        #pragma unroll
        for (int i = 1; i < 18; i++) m = fmaxf(m, swm[i]);
        atomicMaxFloat(&g_headmax[bh], m);
    }

    if (w < 19) {
        float* pb = g_ctx_part + (size_t)(bh * NSPL + split) * (320 * 80);
        int r1 = m0w + lr, r2 = r1 + 8;
        #pragma unroll
        for (int tp = 0; tp < 5; tp++) {
            int col = tp * 16 + lc;
            *(float2*)(pb + (size_t)r1 * 80 + col)     = make_float2(C[2 * tp][0], C[2 * tp][1]);
            *(float2*)(pb + (size_t)r2 * 80 + col)     = make_float2(C[2 * tp][2], C[2 * tp][3]);
            *(float2*)(pb + (size_t)r1 * 80 + col + 8) = make_float2(C[2 * tp + 1][0], C[2 * tp + 1][1]);
            *(float2*)(pb + (size_t)r2 * 80 + col + 8) = make_float2(C[2 * tp + 1][2], C[2 * tp + 1][3]);
        }
    }
}

// ---------------------------------------------------------------------------
// pass2b: ctx = 2^(-stab)*ctxE + EPS*Vsum; reduce splits; emit bf16 hi/lo.
// ---------------------------------------------------------------------------
__global__ __launch_bounds__(256) void pass2b() {
    int gid = blockIdx.x * 256 + threadIdx.x;
    if (gid >= BHN * 288 * 80) return;
    int bh = gid / (288 * 80);
    int rem = gid % (288 * 80);
    int m = rem / 80, d = rem % 80;
    const float scale = ex2f(-g_headmax[bh]);
    const float* base = g_ctx_part + (size_t)bh * NSPL * (320 * 80);
    float s = 0.f, vs = 0.f;
    #pragma unroll
    for (int sp = 0; sp < NSPL; sp++) {
        s  += base[((size_t)sp * 320 + m) * 80 + d];
        vs += base[((size_t)sp * 320 + 288) * 80 + d];
    }
    float f = fmaf(EPSV, vs, scale * s);
    uint32_t ib = __float_as_uint(f);
    g_ctxB0[(size_t)bh * 23040 + d * 288 + m] = (unsigned short)(ib >> 16);
    float lv = f - __uint_as_float(ib & 0xffff0000u);
    g_ctxB1[(size_t)bh * 23040 + d * 288 + m] = __bfloat16_as_ushort(__float2bfloat16(lv));
}

// ---------------------------------------------------------------------------
// pass3: 512 threads. GEMM1 -> rowmax -> exp into A-frags (regs) -> GEMM2
// split-K per col group, partial reduce in smem.
// ---------------------------------------------------------------------------
__global__ __launch_bounds__(512) void pass3(const float* __restrict__ qin,
                                             float* __restrict__ out) {
    extern __shared__ __align__(16) uint8_t sm[];
    uint32_t sb = smem_u32(sm);
    float* diag = (float*)(sm + Q_DIAG);
    float* srm = (float*)(sm + Q_SRM);
    float* part = (float*)(sm + PART);
    const int tid = threadIdx.x, w = tid >> 5, lane = tid & 31;
    const int bh = blockIdx.x >> 8, nt = blockIdx.x & 255;
    const int rs = w >> 2, cg = w & 3;
    const int row0 = rs * 16;
    const int col0 = (cg == 0) ? 0 : (cg == 1) ? 80 : (cg == 2) ? 144 : 208;
    const int ntp = (cg == 0 || cg == 3) ? 5 : 4;
    const int lr = lane >> 2, lc = (lane & 3) * 2;

    for (int i = tid; i < 2592; i += 512) {
        ((uint4*)(sm + PH))[i] = ((const uint4*)g_projB0)[i];
        ((uint4*)(sm + PL))[i] = ((const uint4*)g_projB1)[i];
    }
    if (tid < 256)
        stage_x(qin + (size_t)(bh * NSEQ + nt * 64) * 64, sm, XH, XL, diag, tid);
    __syncthreads();

    float C[10][4] = {};
    if (ntp == 5)
        wgemm<5, 4>(C, sb + XH + row0 * 144, sb + XL + row0 * 144, 144,
                    sb + PH + col0 * 144, sb + PL + col0 * 144, 144, lane);
    else
        wgemm<4, 4>(C, sb + XH + row0 * 144, sb + XL + row0 * 144, 144,
                    sb + PH + col0 * 144, sb + PL + col0 * 144, 144, lane);

    const int r1 = row0 + lr, r2 = r1 + 8;
    const float d1 = diag[r1], d2 = diag[r2];
    float m1 = -CUDART_INF_F, m2 = -CUDART_INF_F;
    #pragma unroll
    for (int t = 0; t < 10; t++) {
        if (t >= 2 * ntp) break;
        int col = col0 + t * 8 + lc;
        if (col < MDIM) {
            m1 = fmaxf(m1, fmaxf(C[t][0], C[t][1]));
            m2 = fmaxf(m2, fmaxf(C[t][2], C[t][3]));
        }
    }
    m1 = fmaxf(m1, __shfl_xor_sync(~0u, m1, 1));
    m1 = fmaxf(m1, __shfl_xor_sync(~0u, m1, 2));
    m2 = fmaxf(m2, __shfl_xor_sync(~0u, m2, 1));
    m2 = fmaxf(m2, __shfl_xor_sync(~0u, m2, 2));
    if ((lane & 3) == 0) {
        srm[cg * 64 + r1] = m1;
        srm[cg * 64 + r2] = m2;
    }
    __syncthreads();   // also: all GEMM1 smem reads done -> CT may overwrite
    const float rmax1 = fmaxf(fmaxf(srm[r1], srm[64 + r1]),
                              fmaxf(srm[128 + r1], srm[192 + r1]));
    const float rmax2 = fmaxf(fmaxf(srm[r2], srm[64 + r2]),
                              fmaxf(srm[128 + r2], srm[192 + r2]));
    const float sA = d1 + rmax1, sB = d2 + rmax2;

    // exp -> A-frags directly in registers (C layout == A layout)
    uint32_t ahf[5][4], alf[5][4];
    #pragma unroll
    for (int j = 0; j < 5; j++) {
        if (j >= ntp) break;
        #pragma unroll
        for (int sub = 0; sub < 2; sub++) {
            int t = 2 * j + sub;
            int col = col0 + t * 8 + lc;
            float q0 = 0.f, q1 = 0.f, q2 = 0.f, q3 = 0.f;
            if (col < MDIM) {
                q0 = ex2f(C[t][0] - sA) + EPSV;
                q1 = ex2f(C[t][1] - sA) + EPSV;
                q2 = ex2f(C[t][2] - sB) + EPSV;
                q3 = ex2f(C[t][3] - sB) + EPSV;
            }
            ahf[j][2 * sub]     = bpack2(q0, q1, alf[j][2 * sub]);
            ahf[j][2 * sub + 1] = bpack2(q2, q3, alf[j][2 * sub + 1]);
        }
    }
    // ct^T [80][288] -> smem [80][296] at offset 0 (X/P dead)
    {
        const uint4* s0 = (const uint4*)(g_ctxB0 + (size_t)bh * 23040);
        const uint4* s1 = (const uint4*)(g_ctxB1 + (size_t)bh * 23040);
        for (int i = tid; i < 2880; i += 512) {
            int rr = i / 36, kk = i % 36;
            *(uint4*)(sm + CTH3 + rr * 592 + kk * 16) = s0[i];
            *(uint4*)(sm + CTL3 + rr * 592 + kk * 16) = s1[i];
        }
    }
    __syncthreads();

    // GEMM2 split-K: this warp's K range = its GEMM1 col range
    const int ks0 = (cg == 0) ? 0 : (cg == 1) ? 5 : (cg == 2) ? 9 : 13;
    const uint32_t bo = (uint32_t)(lane & 15) * 592u + (uint32_t)(lane >> 4) * 16u;
    float C2[10][4] = {};
    #pragma unroll
    for (int tp = 0; tp < 5; tp++) {
        #pragma unroll
        for (int j = 0; j < 5; j++) {
            if (j >= ntp) break;
            uint32_t bh4[4], bl4[4];
            uint32_t off = (uint32_t)(tp * 16) * 592u + bo + (uint32_t)(ks0 + j) * 32u;
            ldm4(bh4, sb + CTH3 + off);
            ldm4(bl4, sb + CTL3 + off);
            mma16816(C2[2 * tp], ahf[j], bh4[0], bh4[2]);
            mma16816(C2[2 * tp], ahf[j], bl4[0], bl4[2]);
            mma16816(C2[2 * tp], alf[j], bh4[0], bh4[2]);
            mma16816(C2[2 * tp + 1], ahf[j], bh4[1], bh4[3]);
            mma16816(C2[2 * tp + 1], ahf[j], bl4[1], bl4[3]);
            mma16816(C2[2 * tp + 1], alf[j], bh4[1], bh4[3]);
        }
    }
    __syncthreads();   // CT reads done; PART overwrites

    #pragma unroll
    for (int tp = 0; tp < 5; tp++) {
        int col = tp * 16 + lc;
        *(float2*)&part[(size_t)(cg * 64 + r1) * 80 + col]     = make_float2(C2[2 * tp][0], C2[2 * tp][1]);
        *(float2*)&part[(size_t)(cg * 64 + r2) * 80 + col]     = make_float2(C2[2 * tp][2], C2[2 * tp][3]);
        *(float2*)&part[(size_t)(cg * 64 + r1) * 80 + col + 8] = make_float2(C2[2 * tp + 1][0], C2[2 * tp + 1][1]);
        *(float2*)&part[(size_t)(cg * 64 + r2) * 80 + col + 8] = make_float2(C2[2 * tp + 1][2], C2[2 * tp + 1][3]);
    }
    __syncthreads();

    {
        const int r = tid >> 3, c0 = (tid & 7) * 8;
        float den = part[(size_t)r * 80 + 64] + part[(size_t)(64 + r) * 80 + 64] +
                    part[(size_t)(128 + r) * 80 + 64] + part[(size_t)(192 + r) * 80 + 64];
        float rcp = 1.f / den;
        float4 s0 = make_float4(0.f, 0.f, 0.f, 0.f), s1 = s0;
        #pragma unroll
        for (int cgk = 0; cgk < 4; cgk++) {
            const float* p = &part[(size_t)(cgk * 64 + r) * 80 + c0];
            float4 a = *(const float4*)p;
            float4 b = *(const float4*)(p + 4);
            s0.x += a.x; s0.y += a.y; s0.z += a.z; s0.w += a.w;
            s1.x += b.x; s1.y += b.y; s1.z += b.z; s1.w += b.w;
        }
        float* ob = out + ((size_t)(bh * NSEQ + nt * 64) + r) * 64 + c0;
        *(float4*)ob       = make_float4(s0.x * rcp, s0.y * rcp, s0.z * rcp, s0.w * rcp);
        *(float4*)(ob + 4) = make_float4(s1.x * rcp, s1.y * rcp, s1.z * rcp, s1.w * rcp);
    }
}

// ---------------------------------------------------------------------------
extern "C" void kernel_launch(void* const* d_in, const int* in_sizes, int n_in,
                              void* d_out, int out_size) {
    const float* q    = (const float*)d_in[0];
    const float* k    = (const float*)d_in[1];
    const float* v    = (const float*)d_in[2];
    const float* proj = (const float*)d_in[3];
    float* out = (float*)d_out;

    cudaFuncSetAttribute(pass2a, cudaFuncAttributeMaxDynamicSharedMemorySize, SMEM2);
    cudaFuncSetAttribute(pass3, cudaFuncAttributeMaxDynamicSharedMemorySize, SMEM3);

    prep<<<80, 256>>>(proj);
    pass2a<<<BHN * NSPL, 640, SMEM2>>>(k, v);
    pass2b<<<(BHN * 288 * 80 + 255) / 256, 256>>>();
    pass3<<<BHN * 256, 512, SMEM3>>>(q, out);
}